// round 2
// baseline (speedup 1.0000x reference)
#include <cuda_runtime.h>

// Problem constants
#define B_   65536
#define N_   2
#define D_   512
#define T_   (B_ * N_)          // 131072 tokens
#define TD_  ((size_t)T_ * D_)  // 67,108,864

// ---------------------------------------------------------------------------
// Scratch (static __device__ arrays: no allocation, allowed by harness rules)
// ---------------------------------------------------------------------------
__device__ float g_q[TD_];
__device__ float g_k[TD_];
__device__ float g_v[TD_];
__device__ float g_a[TD_];       // attn_out, later s1 (ReLU(refined@ws1+bs1))
__device__ float g_p[TD_];       // GEMM scratch (pre-LN)
__device__ float g_h[TD_];       // h = LN(x + attn@wo + bo)
__device__ float g_f[2 * TD_];   // FFN hidden (T x 1024)

// ---------------------------------------------------------------------------
// Warp reduction helper
// ---------------------------------------------------------------------------
__device__ __forceinline__ float warp_sum(float v) {
#pragma unroll
    for (int o = 16; o; o >>= 1) v += __shfl_xor_sync(0xffffffffu, v, o);
    return v;
}

// ---------------------------------------------------------------------------
// Generic fp32 GEMM: C[M,N] = A[M,K] @ W[K,N] + bias[N], optional ReLU.
// BM=BN=128, BK=8, 256 threads, 8x8 per-thread microtile.
// M % 128 == 0, N % 128 == 0, K % 8 == 0 guaranteed by problem shapes.
// ---------------------------------------------------------------------------
#define BM 128
#define BN 128
#define BK 8

__global__ __launch_bounds__(256, 2)
void gemm_bias(const float* __restrict__ A, const float* __restrict__ W,
               const float* __restrict__ bias, float* __restrict__ C,
               int M, int N, int K, int relu)
{
    __shared__ float As[BK][BM];
    __shared__ float Bs[BK][BN];

    const int tid = threadIdx.x;
    const int bm  = blockIdx.y;
    const int bn  = blockIdx.x;

    const float* Ab = A + (size_t)bm * BM * K;
    const float* Wb = W + (size_t)bn * BN;

    // A loader: 128 rows x 8 cols = 256 float4; one float4 per thread
    const int arow = tid >> 1;           // 0..127
    const int acol = (tid & 1) * 4;      // 0 or 4
    // B loader: 8 rows x 128 cols = 256 float4
    const int brow = tid >> 5;           // 0..7
    const int bcol = (tid & 31) * 4;     // 0..124

    const int tx = tid & 15;             // 0..15 -> output cols tx*8
    const int ty = tid >> 4;             // 0..15 -> output rows ty*8

    float acc[8][8];
#pragma unroll
    for (int i = 0; i < 8; i++)
#pragma unroll
        for (int j = 0; j < 8; j++) acc[i][j] = 0.0f;

    for (int k0 = 0; k0 < K; k0 += BK) {
        float4 av = *(const float4*)(Ab + (size_t)arow * K + k0 + acol);
        As[acol + 0][arow] = av.x;
        As[acol + 1][arow] = av.y;
        As[acol + 2][arow] = av.z;
        As[acol + 3][arow] = av.w;
        *(float4*)(&Bs[brow][bcol]) =
            *(const float4*)(Wb + (size_t)(k0 + brow) * N + bcol);
        __syncthreads();

#pragma unroll
        for (int k = 0; k < BK; ++k) {
            float ra[8], rb[8];
            *(float4*)(ra)     = *(const float4*)(&As[k][ty * 8]);
            *(float4*)(ra + 4) = *(const float4*)(&As[k][ty * 8 + 4]);
            *(float4*)(rb)     = *(const float4*)(&Bs[k][tx * 8]);
            *(float4*)(rb + 4) = *(const float4*)(&Bs[k][tx * 8 + 4]);
#pragma unroll
            for (int i = 0; i < 8; i++)
#pragma unroll
                for (int j = 0; j < 8; j++)
                    acc[i][j] += ra[i] * rb[j];
        }
        __syncthreads();
    }

    // Epilogue: bias + optional ReLU
    float bv[8];
    *(float4*)(bv)     = *(const float4*)(bias + (size_t)bn * BN + tx * 8);
    *(float4*)(bv + 4) = *(const float4*)(bias + (size_t)bn * BN + tx * 8 + 4);

#pragma unroll
    for (int i = 0; i < 8; i++) {
        size_t row = (size_t)bm * BM + ty * 8 + i;
        float out[8];
#pragma unroll
        for (int j = 0; j < 8; j++) {
            float vv = acc[i][j] + bv[j];
            out[j] = relu ? fmaxf(vv, 0.0f) : vv;
        }
        *(float4*)(C + row * N + (size_t)bn * BN + tx * 8)     = *(float4*)(out);
        *(float4*)(C + row * N + (size_t)bn * BN + tx * 8 + 4) = *(float4*)(out + 4);
    }
}

// ---------------------------------------------------------------------------
// Attention for N=2: one warp per sample.
// scores = leaky_relu(q@k^T / (sqrt(D)+1e-8), 0.2); softmax rows; out = attn@v
// ---------------------------------------------------------------------------
__global__ __launch_bounds__(256)
void attn_kernel(const float* __restrict__ q, const float* __restrict__ k,
                 const float* __restrict__ v, float* __restrict__ o)
{
    int gw   = (blockIdx.x * 256 + threadIdx.x) >> 5;
    int lane = threadIdx.x & 31;
    if (gw >= B_) return;

    const float4* q0 = (const float4*)(q + (size_t)gw * 2 * D_);
    const float4* q1 = q0 + D_ / 4;
    const float4* k0 = (const float4*)(k + (size_t)gw * 2 * D_);
    const float4* k1 = k0 + D_ / 4;

    float s00 = 0.f, s01 = 0.f, s10 = 0.f, s11 = 0.f;
#pragma unroll
    for (int r = 0; r < 4; r++) {
        int i = lane + 32 * r;
        float4 a0 = q0[i], a1 = q1[i], b0 = k0[i], b1 = k1[i];
        s00 += a0.x * b0.x + a0.y * b0.y + a0.z * b0.z + a0.w * b0.w;
        s01 += a0.x * b1.x + a0.y * b1.y + a0.z * b1.z + a0.w * b1.w;
        s10 += a1.x * b0.x + a1.y * b0.y + a1.z * b0.z + a1.w * b0.w;
        s11 += a1.x * b1.x + a1.y * b1.y + a1.z * b1.z + a1.w * b1.w;
    }
    s00 = warp_sum(s00); s01 = warp_sum(s01);
    s10 = warp_sum(s10); s11 = warp_sum(s11);

    const float inv_scale = 1.0f / 22.627416997969522f;  // 1/(sqrt(512)+1e-8)
    s00 *= inv_scale; s01 *= inv_scale; s10 *= inv_scale; s11 *= inv_scale;
    // leaky_relu(0.2)
    s00 = s00 > 0.f ? s00 : 0.2f * s00;
    s01 = s01 > 0.f ? s01 : 0.2f * s01;
    s10 = s10 > 0.f ? s10 : 0.2f * s10;
    s11 = s11 > 0.f ? s11 : 0.2f * s11;

    float m0 = fmaxf(s00, s01), m1 = fmaxf(s10, s11);
    float e00 = expf(s00 - m0), e01 = expf(s01 - m0);
    float e10 = expf(s10 - m1), e11 = expf(s11 - m1);
    float i0 = 1.0f / (e00 + e01), i1 = 1.0f / (e10 + e11);
    float a00 = e00 * i0, a01 = e01 * i0;
    float a10 = e10 * i1, a11 = e11 * i1;

    const float4* v0 = (const float4*)(v + (size_t)gw * 2 * D_);
    const float4* v1 = v0 + D_ / 4;
    float4* o0 = (float4*)(o + (size_t)gw * 2 * D_);
    float4* o1 = o0 + D_ / 4;
#pragma unroll
    for (int r = 0; r < 4; r++) {
        int i = lane + 32 * r;
        float4 x0 = v0[i], x1 = v1[i];
        float4 r0, r1;
        r0.x = a00 * x0.x + a01 * x1.x;  r0.y = a00 * x0.y + a01 * x1.y;
        r0.z = a00 * x0.z + a01 * x1.z;  r0.w = a00 * x0.w + a01 * x1.w;
        r1.x = a10 * x0.x + a11 * x1.x;  r1.y = a10 * x0.y + a11 * x1.y;
        r1.z = a10 * x0.z + a11 * x1.z;  r1.w = a10 * x0.w + a11 * x1.w;
        o0[i] = r0;
        o1[i] = r1;
    }
}

// ---------------------------------------------------------------------------
// out = LayerNorm(A + P) * g + be   (one 128-thread block per row of 512)
// ---------------------------------------------------------------------------
__global__ __launch_bounds__(128)
void add_ln_kernel(const float* __restrict__ A, const float* __restrict__ P,
                   const float* __restrict__ g, const float* __restrict__ be,
                   float* __restrict__ out)
{
    size_t row = blockIdx.x;
    int t = threadIdx.x;

    float4 av = ((const float4*)(A + row * D_))[t];
    float4 pv = ((const float4*)(P + row * D_))[t];
    float4 s;
    s.x = av.x + pv.x; s.y = av.y + pv.y; s.z = av.z + pv.z; s.w = av.w + pv.w;

    float sum = s.x + s.y + s.z + s.w;
    float sq  = s.x * s.x + s.y * s.y + s.z * s.z + s.w * s.w;
    sum = warp_sum(sum);
    sq  = warp_sum(sq);

    __shared__ float sm[8];
    int w = t >> 5;
    if ((t & 31) == 0) { sm[w] = sum; sm[4 + w] = sq; }
    __syncthreads();
    float ts = sm[0] + sm[1] + sm[2] + sm[3];
    float tq = sm[4] + sm[5] + sm[6] + sm[7];

    float mu  = ts * (1.0f / D_);
    float var = tq * (1.0f / D_) - mu * mu;
    float rs  = rsqrtf(var + 1e-5f);

    float4 G  = ((const float4*)g)[t];
    float4 Be = ((const float4*)be)[t];
    float4 o;
    o.x = (s.x - mu) * rs * G.x + Be.x;
    o.y = (s.y - mu) * rs * G.y + Be.y;
    o.z = (s.z - mu) * rs * G.z + Be.z;
    o.w = (s.w - mu) * rs * G.w + Be.w;
    ((float4*)(out + row * D_))[t] = o;
}

// ---------------------------------------------------------------------------
// Final stage: scores = s1 @ ws2 + bs2; alpha = softmax_N; fused = sum alpha*refined;
// fused = param-free LayerNorm(fused). One warp per sample.
// ---------------------------------------------------------------------------
__global__ __launch_bounds__(256)
void final_kernel(const float* __restrict__ s1, const float* __restrict__ ws2,
                  const float* __restrict__ bs2, const float* __restrict__ refined,
                  float* __restrict__ fused, float* __restrict__ alpha)
{
    int gw   = (blockIdx.x * 256 + threadIdx.x) >> 5;
    int lane = threadIdx.x & 31;
    if (gw >= B_) return;

    const float4* r0 = (const float4*)(s1 + (size_t)gw * 2 * D_);
    const float4* r1 = r0 + D_ / 4;
    const float4* w2 = (const float4*)ws2;

    float d0 = 0.f, d1 = 0.f;
#pragma unroll
    for (int r = 0; r < 4; r++) {
        int i = lane + 32 * r;
        float4 w = w2[i], x0 = r0[i], x1 = r1[i];
        d0 += x0.x * w.x + x0.y * w.y + x0.z * w.z + x0.w * w.w;
        d1 += x1.x * w.x + x1.y * w.y + x1.z * w.z + x1.w * w.w;
    }
    d0 = warp_sum(d0) + bs2[0];
    d1 = warp_sum(d1) + bs2[0];

    float m  = fmaxf(d0, d1);
    float e0 = expf(d0 - m), e1 = expf(d1 - m);
    float inv = 1.0f / (e0 + e1);
    float a0 = e0 * inv, a1 = e1 * inv;
    if (lane == 0) {
        alpha[(size_t)gw * 2 + 0] = a0;
        alpha[(size_t)gw * 2 + 1] = a1;
    }

    const float4* f0 = (const float4*)(refined + (size_t)gw * 2 * D_);
    const float4* f1 = f0 + D_ / 4;

    float4 fr[4];
    float sum = 0.f, sq = 0.f;
#pragma unroll
    for (int r = 0; r < 4; r++) {
        int i = lane + 32 * r;
        float4 x0 = f0[i], x1 = f1[i];
        float4 t;
        t.x = a0 * x0.x + a1 * x1.x;  t.y = a0 * x0.y + a1 * x1.y;
        t.z = a0 * x0.z + a1 * x1.z;  t.w = a0 * x0.w + a1 * x1.w;
        fr[r] = t;
        sum += t.x + t.y + t.z + t.w;
        sq  += t.x * t.x + t.y * t.y + t.z * t.z + t.w * t.w;
    }
    sum = warp_sum(sum);
    sq  = warp_sum(sq);
    float mu  = sum * (1.0f / D_);
    float var = sq * (1.0f / D_) - mu * mu;
    float rs  = rsqrtf(var + 1e-5f);

    float4* fo = (float4*)(fused + (size_t)gw * D_);
#pragma unroll
    for (int r = 0; r < 4; r++) {
        int i = lane + 32 * r;
        float4 t = fr[r];
        float4 o;
        o.x = (t.x - mu) * rs;  o.y = (t.y - mu) * rs;
        o.z = (t.z - mu) * rs;  o.w = (t.w - mu) * rs;
        fo[i] = o;
    }
}

// ---------------------------------------------------------------------------
// Launch
// Input order: x, wq,bq, wk,bk, wv,bv, wo,bo, g1,be1, wf1,bf1, wf2,bf2,
//              g2,be2, ws1,bs1, ws2,bs2
// Output tuple flattened: [fused (B*D) | alpha (B*N) | refined (B*N*D)]
// ---------------------------------------------------------------------------
extern "C" void kernel_launch(void* const* d_in, const int* in_sizes, int n_in,
                              void* d_out, int out_size)
{
    const float* x   = (const float*)d_in[0];
    const float* wq  = (const float*)d_in[1];
    const float* bq  = (const float*)d_in[2];
    const float* wk  = (const float*)d_in[3];
    const float* bk  = (const float*)d_in[4];
    const float* wv  = (const float*)d_in[5];
    const float* bv  = (const float*)d_in[6];
    const float* wo  = (const float*)d_in[7];
    const float* bo  = (const float*)d_in[8];
    const float* g1  = (const float*)d_in[9];
    const float* be1 = (const float*)d_in[10];
    const float* wf1 = (const float*)d_in[11];
    const float* bf1 = (const float*)d_in[12];
    const float* wf2 = (const float*)d_in[13];
    const float* bf2 = (const float*)d_in[14];
    const float* g2  = (const float*)d_in[15];
    const float* be2 = (const float*)d_in[16];
    const float* ws1 = (const float*)d_in[17];
    const float* bs1 = (const float*)d_in[18];
    const float* ws2 = (const float*)d_in[19];
    const float* bs2 = (const float*)d_in[20];

    float *q, *k, *v, *a, *p, *h, *f;
    cudaGetSymbolAddress((void**)&q, g_q);
    cudaGetSymbolAddress((void**)&k, g_k);
    cudaGetSymbolAddress((void**)&v, g_v);
    cudaGetSymbolAddress((void**)&a, g_a);
    cudaGetSymbolAddress((void**)&p, g_p);
    cudaGetSymbolAddress((void**)&h, g_h);
    cudaGetSymbolAddress((void**)&f, g_f);

    float* out     = (float*)d_out;
    float* fused   = out;
    float* alpha   = out + (size_t)B_ * D_;
    float* refined = alpha + (size_t)B_ * N_;

    dim3 gD(D_ / BN, T_ / BM);          // (4, 1024) for N=512
    dim3 gF(2 * D_ / BN, T_ / BM);      // (8, 1024) for N=1024

    // Q/K/V projections
    gemm_bias<<<gD, 256>>>(x, wq, bq, q, T_, D_, D_, 0);
    gemm_bias<<<gD, 256>>>(x, wk, bk, k, T_, D_, D_, 0);
    gemm_bias<<<gD, 256>>>(x, wv, bv, v, T_, D_, D_, 0);
    // attention (N=2)
    attn_kernel<<<B_ / 8, 256>>>(q, k, v, a);
    // output projection + residual LN1
    gemm_bias<<<gD, 256>>>(a, wo, bo, p, T_, D_, D_, 0);
    add_ln_kernel<<<T_, 128>>>(x, p, g1, be1, h);
    // FFN
    gemm_bias<<<gF, 256>>>(h, wf1, bf1, f, T_, 2 * D_, D_, 1);
    gemm_bias<<<gD, 256>>>(f, wf2, bf2, p, T_, D_, 2 * D_, 0);
    add_ln_kernel<<<T_, 128>>>(h, p, g2, be2, refined);
    // score MLP stage 1
    gemm_bias<<<gD, 256>>>(refined, ws1, bs1, a, T_, D_, D_, 1);
    // scores, alpha, pooling, final LN
    final_kernel<<<B_ / 8, 256>>>(a, ws2, bs2, refined, fused, alpha);
}

// round 4
// speedup vs baseline: 1.9979x; 1.9979x over previous
#include <cuda_runtime.h>
#include <cuda_bf16.h>
#include <cstdint>

// ---------------------------------------------------------------------------
// Problem constants
// ---------------------------------------------------------------------------
#define B_   65536
#define N_   2
#define D_   512
#define T_   (B_ * N_)          // 131072 tokens
#define TD_  ((size_t)T_ * D_)  // 67,108,864

// ---------------------------------------------------------------------------
// Scratch (static __device__ arrays: no allocation)
// ---------------------------------------------------------------------------
__device__ float g_q[TD_];
__device__ float g_k[TD_];
__device__ float g_v[TD_];
__device__ float g_p[TD_];
__device__ float g_h[TD_];
__device__ float g_s1[TD_];

__device__ __nv_bfloat16 g_xh[TD_], g_xl[TD_];
__device__ __nv_bfloat16 g_ah[TD_], g_al[TD_];
__device__ __nv_bfloat16 g_hh[TD_], g_hl[TD_];
__device__ __nv_bfloat16 g_rh[TD_], g_rl[TD_];
__device__ __nv_bfloat16 g_fh[2 * TD_], g_fl[2 * TD_];

// transposed+split weights, [N,K] layout
#define WQ_OFF  0
#define WK_OFF  262144
#define WV_OFF  524288
#define WO_OFF  786432
#define WF1_OFF 1048576
#define WF2_OFF 1572864
#define WS1_OFF 2097152
__device__ __nv_bfloat16 g_wth[2359296];
__device__ __nv_bfloat16 g_wtl[2359296];

// ---------------------------------------------------------------------------
// PTX helpers (baseline sm_80+ instructions only: cp.async / ldmatrix / mma)
// ---------------------------------------------------------------------------
__device__ __forceinline__ uint32_t smem_u32(const void* smem_ptr) {
    uint32_t addr;
    asm("{ .reg .u64 tmp; cvta.to.shared.u64 tmp, %1; cvt.u32.u64 %0, tmp; }"
        : "=r"(addr) : "l"(smem_ptr));
    return addr;
}

#define CP16(dst, src) \
    asm volatile("cp.async.cg.shared.global [%0], [%1], 16;" \
        :: "r"(dst), "l"(src))

#define CP_COMMIT() asm volatile("cp.async.commit_group;" ::: "memory")
#define CP_WAIT(n)  asm volatile("cp.async.wait_group %0;" :: "n"(n) : "memory")

#define LDSM4(r0, r1, r2, r3, a) \
    asm volatile("ldmatrix.sync.aligned.m8n8.x4.shared.b16 {%0,%1,%2,%3}, [%4];" \
        : "=r"(r0), "=r"(r1), "=r"(r2), "=r"(r3) : "r"(a))

#define MMA16816(d, a, b) \
    asm volatile("mma.sync.aligned.m16n8k16.row.col.f32.bf16.bf16.f32 " \
        "{%0,%1,%2,%3}, {%4,%5,%6,%7}, {%8,%9}, {%0,%1,%2,%3};" \
        : "+f"((d)[0]), "+f"((d)[1]), "+f"((d)[2]), "+f"((d)[3]) \
        : "r"((a)[0]), "r"((a)[1]), "r"((a)[2]), "r"((a)[3]), \
          "r"((b)[0]), "r"((b)[1]))

// bf16 hi/lo split
__device__ __forceinline__ void split1(float v, __nv_bfloat16& h, __nv_bfloat16& l) {
    h = __float2bfloat16(v);
    l = __float2bfloat16(v - __bfloat162float(h));
}

__device__ __forceinline__ uint32_t pack_bf16x2(float lo_val, float hi_val) {
    __nv_bfloat16 a = __float2bfloat16(lo_val);
    __nv_bfloat16 b = __float2bfloat16(hi_val);
    uint16_t ua = *(uint16_t*)&a, ub = *(uint16_t*)&b;
    return (uint32_t)ua | ((uint32_t)ub << 16);
}

__device__ __forceinline__ float warp_sum(float v) {
#pragma unroll
    for (int o = 16; o; o >>= 1) v += __shfl_xor_sync(0xffffffffu, v, o);
    return v;
}

// ---------------------------------------------------------------------------
// mma.sync GEMM: C[M,N] = (Ah+Al)[M,K] @ (Bh+Bl)^T[N,K] + bias
// hi/lo bf16 split: Ah*Bh + Ah*Bl + Al*Bh, fp32 register accumulation.
// CTA tile 128x128, 8 warps (4m x 2n), warp tile 32x64, K-chunk 32,
// 4-stage cp.async pipeline. SMEM rows stride 80B (conflict-free, no swizzle).
// mode: 0 = fp32 out; 1 = fp32 out + ReLU; 2 = bf16 hi/lo out + ReLU.
// ---------------------------------------------------------------------------
#define STAGES        4
#define MAT_BYTES     10240     // 128 rows * 80B
#define STAGE_BYTES   40960     // 4 matrices (Ah, Al, Bh, Bl)
#define ROW_STRIDE    80
#define GEMM_SMEM     (STAGES * STAGE_BYTES)   // 163840

__global__ __launch_bounds__(256, 1)
void gemm_mma(const __nv_bfloat16* __restrict__ Ah, const __nv_bfloat16* __restrict__ Al,
              const __nv_bfloat16* __restrict__ Bh, const __nv_bfloat16* __restrict__ Bl,
              const float* __restrict__ bias,
              float* __restrict__ Cf,
              __nv_bfloat16* __restrict__ Ch, __nv_bfloat16* __restrict__ Cl,
              int N, int K, int mode)
{
    extern __shared__ char smem[];
    const uint32_t sb = smem_u32(smem);
    const int tid  = threadIdx.x;
    const int lane = tid & 31;
    const int wid  = tid >> 5;
    const int wm   = wid & 3;        // 0..3  (M direction)
    const int wn   = wid >> 2;       // 0..1  (N direction)
    const int bn   = blockIdx.x;
    const int bm   = blockIdx.y;
    const int Kb   = K * 2;          // bytes per row

    const char* gAh = (const char*)(Ah + (size_t)bm * 128 * K);
    const char* gAl = (const char*)(Al + (size_t)bm * 128 * K);
    const char* gBh = (const char*)(Bh + (size_t)bn * 128 * K);
    const char* gBl = (const char*)(Bl + (size_t)bn * 128 * K);

    // loader: each thread copies one 32B segment (two 16B cp.async) per matrix
    const int lr  = tid >> 1;            // row 0..127
    const int lcb = (tid & 1) * 32;      // byte offset within 64B row
    const size_t   goff = (size_t)lr * Kb + lcb;
    const uint32_t soff = (uint32_t)lr * ROW_STRIDE + lcb;

    float acc[2][8][4];
#pragma unroll
    for (int mi = 0; mi < 2; mi++)
#pragma unroll
        for (int ni = 0; ni < 8; ni++)
#pragma unroll
            for (int r = 0; r < 4; r++) acc[mi][ni][r] = 0.0f;

    const int nch = K >> 5;   // K-chunks of 32

#define LOAD_STAGE(stage, kc) do {                                        \
        uint32_t d = sb + (uint32_t)(stage) * STAGE_BYTES + soff;         \
        size_t   g = goff + (size_t)(kc) * 64;                            \
        CP16(d,                   gAh + g);                               \
        CP16(d + 16,              gAh + g + 16);                          \
        CP16(d + MAT_BYTES,       gAl + g);                               \
        CP16(d + MAT_BYTES + 16,  gAl + g + 16);                          \
        CP16(d + 2*MAT_BYTES,     gBh + g);                               \
        CP16(d + 2*MAT_BYTES+16,  gBh + g + 16);                          \
        CP16(d + 3*MAT_BYTES,     gBl + g);                               \
        CP16(d + 3*MAT_BYTES+16,  gBl + g + 16);                          \
    } while (0)

    // prefetch first STAGES-1 chunks (nch >= 16 always)
#pragma unroll
    for (int s = 0; s < STAGES - 1; s++) { LOAD_STAGE(s, s); CP_COMMIT(); }

    // precomputed ldmatrix lane addressing
    const uint32_t a_row  = (uint32_t)(wm * 32 + (lane & 15));
    const uint32_t a_coff = (uint32_t)((lane >> 4) * 16);
    const uint32_t b_row  = (uint32_t)(wn * 64 + ((lane >> 4) * 8) + (lane & 7));
    const uint32_t b_coff = (uint32_t)(((lane >> 3) & 1) * 16);

#pragma unroll 1
    for (int i = 0; i < nch; i++) {
        CP_WAIT(STAGES - 2);
        __syncthreads();

        int nxt = i + STAGES - 1;
        if (nxt < nch) LOAD_STAGE(nxt & (STAGES - 1), nxt);
        CP_COMMIT();

        const uint32_t base = sb + (uint32_t)(i & (STAGES - 1)) * STAGE_BYTES;

#pragma unroll
        for (int kk = 0; kk < 2; kk++) {
            uint32_t ah[2][4], al[2][4], bh[8][2], bl[8][2];
#pragma unroll
            for (int mi = 0; mi < 2; mi++) {
                uint32_t ad = base + (a_row + mi * 16) * ROW_STRIDE + kk * 32 + a_coff;
                LDSM4(ah[mi][0], ah[mi][1], ah[mi][2], ah[mi][3], ad);
                LDSM4(al[mi][0], al[mi][1], al[mi][2], al[mi][3], ad + MAT_BYTES);
            }
#pragma unroll
            for (int p = 0; p < 4; p++) {
                uint32_t bd = base + 2 * MAT_BYTES +
                              (b_row + p * 16) * ROW_STRIDE + kk * 32 + b_coff;
                uint32_t r0, r1, r2, r3;
                LDSM4(r0, r1, r2, r3, bd);
                bh[2*p][0] = r0; bh[2*p][1] = r1;
                bh[2*p+1][0] = r2; bh[2*p+1][1] = r3;
                LDSM4(r0, r1, r2, r3, bd + MAT_BYTES);
                bl[2*p][0] = r0; bl[2*p][1] = r1;
                bl[2*p+1][0] = r2; bl[2*p+1][1] = r3;
            }
#pragma unroll
            for (int mi = 0; mi < 2; mi++)
#pragma unroll
                for (int ni = 0; ni < 8; ni++) {
                    MMA16816(acc[mi][ni], ah[mi], bh[ni]);
                    MMA16816(acc[mi][ni], ah[mi], bl[ni]);
                    MMA16816(acc[mi][ni], al[mi], bh[ni]);
                }
        }
    }
#undef LOAD_STAGE

    // epilogue from register accumulators
    const int row0 = bm * 128 + wm * 32 + (lane >> 2);
    const int col0 = bn * 128 + wn * 64 + (lane & 3) * 2;

#pragma unroll
    for (int mi = 0; mi < 2; mi++) {
#pragma unroll
        for (int ni = 0; ni < 8; ni++) {
            const int r = row0 + mi * 16;
            const int c = col0 + ni * 8;
            const float b0 = __ldg(bias + c);
            const float b1 = __ldg(bias + c + 1);
            float v00 = acc[mi][ni][0] + b0;
            float v01 = acc[mi][ni][1] + b1;
            float v10 = acc[mi][ni][2] + b0;
            float v11 = acc[mi][ni][3] + b1;
            if (mode >= 1) {
                v00 = fmaxf(v00, 0.0f); v01 = fmaxf(v01, 0.0f);
                v10 = fmaxf(v10, 0.0f); v11 = fmaxf(v11, 0.0f);
            }
            if (mode == 2) {
                __nv_bfloat16 h00, l00, h01, l01, h10, l10, h11, l11;
                split1(v00, h00, l00); split1(v01, h01, l01);
                split1(v10, h10, l10); split1(v11, h11, l11);
                uint16_t* ph = (uint16_t*)Ch;
                uint16_t* pl = (uint16_t*)Cl;
                uint32_t uh0 = (uint32_t)*(uint16_t*)&h00 | ((uint32_t)*(uint16_t*)&h01 << 16);
                uint32_t ul0 = (uint32_t)*(uint16_t*)&l00 | ((uint32_t)*(uint16_t*)&l01 << 16);
                uint32_t uh1 = (uint32_t)*(uint16_t*)&h10 | ((uint32_t)*(uint16_t*)&h11 << 16);
                uint32_t ul1 = (uint32_t)*(uint16_t*)&l10 | ((uint32_t)*(uint16_t*)&l11 << 16);
                *(uint32_t*)(ph + (size_t)r * N + c)       = uh0;
                *(uint32_t*)(pl + (size_t)r * N + c)       = ul0;
                *(uint32_t*)(ph + (size_t)(r + 8) * N + c) = uh1;
                *(uint32_t*)(pl + (size_t)(r + 8) * N + c) = ul1;
            } else {
                *(float2*)(Cf + (size_t)r * N + c)       = make_float2(v00, v01);
                *(float2*)(Cf + (size_t)(r + 8) * N + c) = make_float2(v10, v11);
            }
        }
    }
}

// ---------------------------------------------------------------------------
// fp32 -> bf16 hi/lo split (vectorized, for x)
// ---------------------------------------------------------------------------
__global__ __launch_bounds__(256)
void split_kernel(const float* __restrict__ in, __nv_bfloat16* __restrict__ hi,
                  __nv_bfloat16* __restrict__ lo, size_t n4)
{
    size_t i = (size_t)blockIdx.x * 256 + threadIdx.x;
    if (i >= n4) return;
    float4 v = ((const float4*)in)[i];
    __nv_bfloat16 h[4], l[4];
    split1(v.x, h[0], l[0]); split1(v.y, h[1], l[1]);
    split1(v.z, h[2], l[2]); split1(v.w, h[3], l[3]);
    ((uint2*)hi)[i] = *(uint2*)h;
    ((uint2*)lo)[i] = *(uint2*)l;
}

// ---------------------------------------------------------------------------
// weight transpose + split: W[K,N] -> Wt_hi/Wt_lo [N,K]
// ---------------------------------------------------------------------------
__global__ __launch_bounds__(256)
void wsplit_kernel(const float* __restrict__ W, __nv_bfloat16* __restrict__ th,
                   __nv_bfloat16* __restrict__ tl, int K, int N)
{
    int idx = blockIdx.x * 256 + threadIdx.x;
    if (idx >= K * N) return;
    int n = idx / K, k = idx - n * K;
    float v = W[(size_t)k * N + n];
    __nv_bfloat16 h, l;
    split1(v, h, l);
    th[idx] = h;
    tl[idx] = l;
}

// ---------------------------------------------------------------------------
// Attention for N=2 (one warp per sample); outputs bf16 hi/lo
// ---------------------------------------------------------------------------
__global__ __launch_bounds__(256)
void attn_kernel(const float* __restrict__ q, const float* __restrict__ k,
                 const float* __restrict__ v,
                 __nv_bfloat16* __restrict__ oh, __nv_bfloat16* __restrict__ ol)
{
    int gw   = (blockIdx.x * 256 + threadIdx.x) >> 5;
    int lane = threadIdx.x & 31;
    if (gw >= B_) return;

    const float4* q0 = (const float4*)(q + (size_t)gw * 2 * D_);
    const float4* q1 = q0 + D_ / 4;
    const float4* k0 = (const float4*)(k + (size_t)gw * 2 * D_);
    const float4* k1 = k0 + D_ / 4;

    float s00 = 0.f, s01 = 0.f, s10 = 0.f, s11 = 0.f;
#pragma unroll
    for (int r = 0; r < 4; r++) {
        int i = lane + 32 * r;
        float4 a0 = q0[i], a1 = q1[i], b0 = k0[i], b1 = k1[i];
        s00 += a0.x * b0.x + a0.y * b0.y + a0.z * b0.z + a0.w * b0.w;
        s01 += a0.x * b1.x + a0.y * b1.y + a0.z * b1.z + a0.w * b1.w;
        s10 += a1.x * b0.x + a1.y * b0.y + a1.z * b0.z + a1.w * b0.w;
        s11 += a1.x * b1.x + a1.y * b1.y + a1.z * b1.z + a1.w * b1.w;
    }
    s00 = warp_sum(s00); s01 = warp_sum(s01);
    s10 = warp_sum(s10); s11 = warp_sum(s11);

    const float inv_scale = 1.0f / 22.627416997969522f;
    s00 *= inv_scale; s01 *= inv_scale; s10 *= inv_scale; s11 *= inv_scale;
    s00 = s00 > 0.f ? s00 : 0.2f * s00;
    s01 = s01 > 0.f ? s01 : 0.2f * s01;
    s10 = s10 > 0.f ? s10 : 0.2f * s10;
    s11 = s11 > 0.f ? s11 : 0.2f * s11;

    float m0 = fmaxf(s00, s01), m1 = fmaxf(s10, s11);
    float e00 = expf(s00 - m0), e01 = expf(s01 - m0);
    float e10 = expf(s10 - m1), e11 = expf(s11 - m1);
    float i0 = 1.0f / (e00 + e01), i1 = 1.0f / (e10 + e11);
    float a00 = e00 * i0, a01 = e01 * i0;
    float a10 = e10 * i1, a11 = e11 * i1;

    const float4* v0 = (const float4*)(v + (size_t)gw * 2 * D_);
    const float4* v1 = v0 + D_ / 4;
    __nv_bfloat16* oh0 = oh + (size_t)gw * 2 * D_;
    __nv_bfloat16* ol0 = ol + (size_t)gw * 2 * D_;

#pragma unroll
    for (int r = 0; r < 4; r++) {
        int i = lane + 32 * r;
        float4 x0 = v0[i], x1 = v1[i];
        float o0[4], o1[4];
        o0[0] = a00 * x0.x + a01 * x1.x;  o0[1] = a00 * x0.y + a01 * x1.y;
        o0[2] = a00 * x0.z + a01 * x1.z;  o0[3] = a00 * x0.w + a01 * x1.w;
        o1[0] = a10 * x0.x + a11 * x1.x;  o1[1] = a10 * x0.y + a11 * x1.y;
        o1[2] = a10 * x0.z + a11 * x1.z;  o1[3] = a10 * x0.w + a11 * x1.w;

        __nv_bfloat16 h0[4], l0[4], h1[4], l1[4];
#pragma unroll
        for (int c = 0; c < 4; c++) { split1(o0[c], h0[c], l0[c]); split1(o1[c], h1[c], l1[c]); }
        *(uint2*)(oh0 + (size_t)i * 4)      = *(uint2*)h0;
        *(uint2*)(ol0 + (size_t)i * 4)      = *(uint2*)l0;
        *(uint2*)(oh0 + D_ + (size_t)i * 4) = *(uint2*)h1;
        *(uint2*)(ol0 + D_ + (size_t)i * 4) = *(uint2*)l1;
    }
}

// ---------------------------------------------------------------------------
// out = LayerNorm(A + P) * g + be ; also emits bf16 hi/lo of out
// ---------------------------------------------------------------------------
__global__ __launch_bounds__(128)
void add_ln_kernel(const float* __restrict__ A, const float* __restrict__ P,
                   const float* __restrict__ g, const float* __restrict__ be,
                   float* __restrict__ out,
                   __nv_bfloat16* __restrict__ oh, __nv_bfloat16* __restrict__ ol)
{
    size_t row = blockIdx.x;
    int t = threadIdx.x;

    float4 av = ((const float4*)(A + row * D_))[t];
    float4 pv = ((const float4*)(P + row * D_))[t];
    float4 s;
    s.x = av.x + pv.x; s.y = av.y + pv.y; s.z = av.z + pv.z; s.w = av.w + pv.w;

    float sum = s.x + s.y + s.z + s.w;
    float sq  = s.x * s.x + s.y * s.y + s.z * s.z + s.w * s.w;
    sum = warp_sum(sum);
    sq  = warp_sum(sq);

    __shared__ float sm[8];
    int w = t >> 5;
    if ((t & 31) == 0) { sm[w] = sum; sm[4 + w] = sq; }
    __syncthreads();
    float ts = sm[0] + sm[1] + sm[2] + sm[3];
    float tq = sm[4] + sm[5] + sm[6] + sm[7];

    float mu  = ts * (1.0f / D_);
    float var = tq * (1.0f / D_) - mu * mu;
    float rs  = rsqrtf(var + 1e-5f);

    float4 G  = ((const float4*)g)[t];
    float4 Be = ((const float4*)be)[t];
    float4 o;
    o.x = (s.x - mu) * rs * G.x + Be.x;
    o.y = (s.y - mu) * rs * G.y + Be.y;
    o.z = (s.z - mu) * rs * G.z + Be.z;
    o.w = (s.w - mu) * rs * G.w + Be.w;
    ((float4*)(out + row * D_))[t] = o;

    __nv_bfloat16 h[4], l[4];
    split1(o.x, h[0], l[0]); split1(o.y, h[1], l[1]);
    split1(o.z, h[2], l[2]); split1(o.w, h[3], l[3]);
    *(uint2*)(oh + row * D_ + (size_t)t * 4) = *(uint2*)h;
    *(uint2*)(ol + row * D_ + (size_t)t * 4) = *(uint2*)l;
}

// ---------------------------------------------------------------------------
// Final stage: score dot, softmax over N=2, pooling, param-free LN
// ---------------------------------------------------------------------------
__global__ __launch_bounds__(256)
void final_kernel(const float* __restrict__ s1, const float* __restrict__ ws2,
                  const float* __restrict__ bs2, const float* __restrict__ refined,
                  float* __restrict__ fused, float* __restrict__ alpha)
{
    int gw   = (blockIdx.x * 256 + threadIdx.x) >> 5;
    int lane = threadIdx.x & 31;
    if (gw >= B_) return;

    const float4* r0 = (const float4*)(s1 + (size_t)gw * 2 * D_);
    const float4* r1 = r0 + D_ / 4;
    const float4* w2 = (const float4*)ws2;

    float d0 = 0.f, d1 = 0.f;
#pragma unroll
    for (int r = 0; r < 4; r++) {
        int i = lane + 32 * r;
        float4 w = w2[i], x0 = r0[i], x1 = r1[i];
        d0 += x0.x * w.x + x0.y * w.y + x0.z * w.z + x0.w * w.w;
        d1 += x1.x * w.x + x1.y * w.y + x1.z * w.z + x1.w * w.w;
    }
    d0 = warp_sum(d0) + bs2[0];
    d1 = warp_sum(d1) + bs2[0];

    float m  = fmaxf(d0, d1);
    float e0 = expf(d0 - m), e1 = expf(d1 - m);
    float inv = 1.0f / (e0 + e1);
    float a0 = e0 * inv, a1 = e1 * inv;
    if (lane == 0) {
        alpha[(size_t)gw * 2 + 0] = a0;
        alpha[(size_t)gw * 2 + 1] = a1;
    }

    const float4* f0 = (const float4*)(refined + (size_t)gw * 2 * D_);
    const float4* f1 = f0 + D_ / 4;

    float4 fr[4];
    float sum = 0.f, sq = 0.f;
#pragma unroll
    for (int r = 0; r < 4; r++) {
        int i = lane + 32 * r;
        float4 x0 = f0[i], x1 = f1[i];
        float4 t;
        t.x = a0 * x0.x + a1 * x1.x;  t.y = a0 * x0.y + a1 * x1.y;
        t.z = a0 * x0.z + a1 * x1.z;  t.w = a0 * x0.w + a1 * x1.w;
        fr[r] = t;
        sum += t.x + t.y + t.z + t.w;
        sq  += t.x * t.x + t.y * t.y + t.z * t.z + t.w * t.w;
    }
    sum = warp_sum(sum);
    sq  = warp_sum(sq);
    float mu  = sum * (1.0f / D_);
    float var = sq * (1.0f / D_) - mu * mu;
    float rs  = rsqrtf(var + 1e-5f);

    float4* fo = (float4*)(fused + (size_t)gw * D_);
#pragma unroll
    for (int r = 0; r < 4; r++) {
        int i = lane + 32 * r;
        float4 t = fr[r];
        float4 o;
        o.x = (t.x - mu) * rs;  o.y = (t.y - mu) * rs;
        o.z = (t.z - mu) * rs;  o.w = (t.w - mu) * rs;
        fo[i] = o;
    }
}

// ---------------------------------------------------------------------------
// Launch
// ---------------------------------------------------------------------------
extern "C" void kernel_launch(void* const* d_in, const int* in_sizes, int n_in,
                              void* d_out, int out_size)
{
    const float* x   = (const float*)d_in[0];
    const float* wq  = (const float*)d_in[1];
    const float* bq  = (const float*)d_in[2];
    const float* wk  = (const float*)d_in[3];
    const float* bk  = (const float*)d_in[4];
    const float* wv  = (const float*)d_in[5];
    const float* bv  = (const float*)d_in[6];
    const float* wo  = (const float*)d_in[7];
    const float* bo  = (const float*)d_in[8];
    const float* g1  = (const float*)d_in[9];
    const float* be1 = (const float*)d_in[10];
    const float* wf1 = (const float*)d_in[11];
    const float* bf1 = (const float*)d_in[12];
    const float* wf2 = (const float*)d_in[13];
    const float* bf2 = (const float*)d_in[14];
    const float* g2  = (const float*)d_in[15];
    const float* be2 = (const float*)d_in[16];
    const float* ws1 = (const float*)d_in[17];
    const float* bs1 = (const float*)d_in[18];
    const float* ws2 = (const float*)d_in[19];
    const float* bs2 = (const float*)d_in[20];

    float *q, *k, *v, *p, *h, *s1;
    __nv_bfloat16 *xh, *xl, *ah, *al, *hh, *hl, *rh, *rl, *fh, *fl, *wth, *wtl;
    cudaGetSymbolAddress((void**)&q, g_q);
    cudaGetSymbolAddress((void**)&k, g_k);
    cudaGetSymbolAddress((void**)&v, g_v);
    cudaGetSymbolAddress((void**)&p, g_p);
    cudaGetSymbolAddress((void**)&h, g_h);
    cudaGetSymbolAddress((void**)&s1, g_s1);
    cudaGetSymbolAddress((void**)&xh, g_xh);
    cudaGetSymbolAddress((void**)&xl, g_xl);
    cudaGetSymbolAddress((void**)&ah, g_ah);
    cudaGetSymbolAddress((void**)&al, g_al);
    cudaGetSymbolAddress((void**)&hh, g_hh);
    cudaGetSymbolAddress((void**)&hl, g_hl);
    cudaGetSymbolAddress((void**)&rh, g_rh);
    cudaGetSymbolAddress((void**)&rl, g_rl);
    cudaGetSymbolAddress((void**)&fh, g_fh);
    cudaGetSymbolAddress((void**)&fl, g_fl);
    cudaGetSymbolAddress((void**)&wth, g_wth);
    cudaGetSymbolAddress((void**)&wtl, g_wtl);

    cudaFuncSetAttribute(gemm_mma, cudaFuncAttributeMaxDynamicSharedMemorySize,
                         GEMM_SMEM);

    float* out     = (float*)d_out;
    float* fused   = out;
    float* alpha   = out + (size_t)B_ * D_;
    float* refined = alpha + (size_t)B_ * N_;

    // preprocessing: split x, transpose+split weights
    split_kernel<<<(unsigned)(TD_ / 4 / 256), 256>>>(x, xh, xl, TD_ / 4);
    wsplit_kernel<<<(512 * 512 + 255) / 256, 256>>>(wq,  wth + WQ_OFF,  wtl + WQ_OFF,  512, 512);
    wsplit_kernel<<<(512 * 512 + 255) / 256, 256>>>(wk,  wth + WK_OFF,  wtl + WK_OFF,  512, 512);
    wsplit_kernel<<<(512 * 512 + 255) / 256, 256>>>(wv,  wth + WV_OFF,  wtl + WV_OFF,  512, 512);
    wsplit_kernel<<<(512 * 512 + 255) / 256, 256>>>(wo,  wth + WO_OFF,  wtl + WO_OFF,  512, 512);
    wsplit_kernel<<<(512 * 1024 + 255) / 256, 256>>>(wf1, wth + WF1_OFF, wtl + WF1_OFF, 512, 1024);
    wsplit_kernel<<<(1024 * 512 + 255) / 256, 256>>>(wf2, wth + WF2_OFF, wtl + WF2_OFF, 1024, 512);
    wsplit_kernel<<<(512 * 512 + 255) / 256, 256>>>(ws1, wth + WS1_OFF, wtl + WS1_OFF, 512, 512);

    dim3 blk(256);
    dim3 gD(512 / 128, T_ / 128);    // (4, 1024)
    dim3 gF(1024 / 128, T_ / 128);   // (8, 1024)

    // Q/K/V projections
    gemm_mma<<<gD, blk, GEMM_SMEM>>>(xh, xl, wth + WQ_OFF, wtl + WQ_OFF, bq, q, nullptr, nullptr, 512, 512, 0);
    gemm_mma<<<gD, blk, GEMM_SMEM>>>(xh, xl, wth + WK_OFF, wtl + WK_OFF, bk, k, nullptr, nullptr, 512, 512, 0);
    gemm_mma<<<gD, blk, GEMM_SMEM>>>(xh, xl, wth + WV_OFF, wtl + WV_OFF, bv, v, nullptr, nullptr, 512, 512, 0);
    // attention -> bf16 hi/lo
    attn_kernel<<<B_ / 8, 256>>>(q, k, v, ah, al);
    // output projection + residual LN1
    gemm_mma<<<gD, blk, GEMM_SMEM>>>(ah, al, wth + WO_OFF, wtl + WO_OFF, bo, p, nullptr, nullptr, 512, 512, 0);
    add_ln_kernel<<<T_, 128>>>(x, p, g1, be1, h, hh, hl);
    // FFN
    gemm_mma<<<gF, blk, GEMM_SMEM>>>(hh, hl, wth + WF1_OFF, wtl + WF1_OFF, bf1, nullptr, fh, fl, 1024, 512, 2);
    gemm_mma<<<gD, blk, GEMM_SMEM>>>(fh, fl, wth + WF2_OFF, wtl + WF2_OFF, bf2, p, nullptr, nullptr, 512, 1024, 0);
    add_ln_kernel<<<T_, 128>>>(h, p, g2, be2, refined, rh, rl);
    // score MLP stage 1 (ReLU)
    gemm_mma<<<gD, blk, GEMM_SMEM>>>(rh, rl, wth + WS1_OFF, wtl + WS1_OFF, bs1, s1, nullptr, nullptr, 512, 512, 1);
    // scores, alpha, pooling, final LN
    final_kernel<<<B_ / 8, 256>>>(s1, ws2, bs2, refined, fused, alpha);
}

// round 5
// speedup vs baseline: 2.4891x; 1.2459x over previous
#include <cuda_runtime.h>
#include <cuda_fp16.h>
#include <cstdint>

// ---------------------------------------------------------------------------
// Problem constants
// ---------------------------------------------------------------------------
#define B_   65536
#define N_   2
#define D_   512
#define T_   (B_ * N_)          // 131072 tokens
#define TD_  ((size_t)T_ * D_)  // 67,108,864

// ---------------------------------------------------------------------------
// Scratch (static __device__ arrays)
// ---------------------------------------------------------------------------
__device__ float g_qkv[3 * TD_];   // fused QKV output [T, 1536]
__device__ float g_p[TD_];
__device__ float g_h[TD_];
__device__ float g_s1[TD_];
__device__ float g_bqkv[3 * D_];   // concat bias for fused QKV

__device__ __half g_xh[TD_], g_xl[TD_];
__device__ __half g_ah[TD_], g_al[TD_];
__device__ __half g_hh[TD_], g_hl[TD_];
__device__ __half g_rh[TD_], g_rl[TD_];
__device__ __half g_fh[2 * TD_], g_fl[2 * TD_];

// transposed fp16 weights, [N,K] layout. QKV concat at 0.
#define WQ_OFF  0
#define WK_OFF  262144
#define WV_OFF  524288
#define WO_OFF  786432
#define WF1_OFF 1048576
#define WF2_OFF 1572864
#define WS1_OFF 2097152
__device__ __half g_wt[2359296];

// ---------------------------------------------------------------------------
// PTX helpers (baseline sm_80+)
// ---------------------------------------------------------------------------
__device__ __forceinline__ uint32_t smem_u32(const void* smem_ptr) {
    uint32_t addr;
    asm("{ .reg .u64 tmp; cvta.to.shared.u64 tmp, %1; cvt.u32.u64 %0, tmp; }"
        : "=r"(addr) : "l"(smem_ptr));
    return addr;
}

#define CP16(dst, src) \
    asm volatile("cp.async.cg.shared.global [%0], [%1], 16;" \
        :: "r"(dst), "l"(src))

#define CP_COMMIT() asm volatile("cp.async.commit_group;" ::: "memory")
#define CP_WAIT(n)  asm volatile("cp.async.wait_group %0;" :: "n"(n) : "memory")

#define LDSM4(r0, r1, r2, r3, a) \
    asm volatile("ldmatrix.sync.aligned.m8n8.x4.shared.b16 {%0,%1,%2,%3}, [%4];" \
        : "=r"(r0), "=r"(r1), "=r"(r2), "=r"(r3) : "r"(a))

#define MMAH(d, a0, a1, a2, a3, b0, b1) \
    asm volatile("mma.sync.aligned.m16n8k16.row.col.f32.f16.f16.f32 " \
        "{%0,%1,%2,%3}, {%4,%5,%6,%7}, {%8,%9}, {%0,%1,%2,%3};" \
        : "+f"((d)[0]), "+f"((d)[1]), "+f"((d)[2]), "+f"((d)[3]) \
        : "r"(a0), "r"(a1), "r"(a2), "r"(a3), "r"(b0), "r"(b1))

// fp16 hi/lo split
__device__ __forceinline__ void split1(float v, __half& h, __half& l) {
    h = __float2half_rn(v);
    l = __float2half_rn(v - __half2float(h));
}

__device__ __forceinline__ float warp_sum(float v) {
#pragma unroll
    for (int o = 16; o; o >>= 1) v += __shfl_xor_sync(0xffffffffu, v, o);
    return v;
}

// ---------------------------------------------------------------------------
// mma.sync GEMM: C[M,N] = (Ah+Al)[M,K] @ B^T[N,K] + bias
// A in fp16 hi/lo (2 MMA terms), B single fp16. fp32 register accumulation.
// CTA tile 128x128, 8 warps (4m x 2n), warp tile 32x64, K-chunk 64,
// 4-stage cp.async pipeline. SMEM rows stride 144B (conflict-free).
// mode: 0 = fp32 out; 1 = fp32 out + ReLU; 2 = fp16 hi/lo out + ReLU.
// ---------------------------------------------------------------------------
#define STAGES        4
#define ROW_STRIDE    144
#define MAT_BYTES     18432     // 128 rows * 144B
#define STAGE_BYTES   55296     // 3 matrices (Ah, Al, B)
#define GEMM_SMEM     (STAGES * STAGE_BYTES)   // 221184

__global__ __launch_bounds__(256, 1)
void gemm_mma(const __half* __restrict__ Ah, const __half* __restrict__ Al,
              const __half* __restrict__ B,
              const float* __restrict__ bias,
              float* __restrict__ Cf,
              __half* __restrict__ Ch, __half* __restrict__ Cl,
              int N, int K, int mode)
{
    extern __shared__ char smem[];
    const uint32_t sb = smem_u32(smem);
    const int tid  = threadIdx.x;
    const int lane = tid & 31;
    const int wid  = tid >> 5;
    const int wm   = wid & 3;        // 0..3  (M direction)
    const int wn   = wid >> 2;       // 0..1  (N direction)
    const int bn   = blockIdx.x;
    const int bm   = blockIdx.y;
    const int Kb   = K * 2;          // bytes per row

    const char* gAh = (const char*)(Ah + (size_t)bm * 128 * K);
    const char* gAl = (const char*)(Al + (size_t)bm * 128 * K);
    const char* gB  = (const char*)(B  + (size_t)bn * 128 * K);

    // loader: thread -> (row, 64B half-row); 4 CP16 per matrix per stage
    const int lr  = tid >> 1;
    const int lcb = (tid & 1) * 64;
    const size_t   goff = (size_t)lr * Kb + lcb;
    const uint32_t soff = (uint32_t)lr * ROW_STRIDE + lcb;

    float acc[2][8][4];
#pragma unroll
    for (int mi = 0; mi < 2; mi++)
#pragma unroll
        for (int ni = 0; ni < 8; ni++)
#pragma unroll
            for (int r = 0; r < 4; r++) acc[mi][ni][r] = 0.0f;

    const int nch = K >> 6;   // K-chunks of 64

#define LOAD_STAGE(stage, kc) do {                                        \
        uint32_t d = sb + (uint32_t)(stage) * STAGE_BYTES + soff;         \
        size_t   g = goff + (size_t)(kc) * 128;                           \
        CP16(d,                    gAh + g);                              \
        CP16(d + 16,               gAh + g + 16);                         \
        CP16(d + 32,               gAh + g + 32);                         \
        CP16(d + 48,               gAh + g + 48);                         \
        CP16(d + MAT_BYTES,        gAl + g);                              \
        CP16(d + MAT_BYTES + 16,   gAl + g + 16);                         \
        CP16(d + MAT_BYTES + 32,   gAl + g + 32);                         \
        CP16(d + MAT_BYTES + 48,   gAl + g + 48);                         \
        CP16(d + 2*MAT_BYTES,      gB  + g);                              \
        CP16(d + 2*MAT_BYTES + 16, gB  + g + 16);                         \
        CP16(d + 2*MAT_BYTES + 32, gB  + g + 32);                         \
        CP16(d + 2*MAT_BYTES + 48, gB  + g + 48);                         \
    } while (0)

#pragma unroll
    for (int s = 0; s < STAGES - 1; s++) { LOAD_STAGE(s, s); CP_COMMIT(); }

    // ldmatrix lane addressing
    const uint32_t a_row  = (uint32_t)(wm * 32 + (lane & 15));
    const uint32_t a_coff = (uint32_t)((lane >> 4) * 16);
    const uint32_t b_row  = (uint32_t)(wn * 64 + ((lane >> 4) * 8) + (lane & 7));
    const uint32_t b_coff = (uint32_t)(((lane >> 3) & 1) * 16);

#pragma unroll 1
    for (int i = 0; i < nch; i++) {
        CP_WAIT(STAGES - 2);
        __syncthreads();

        int nxt = i + STAGES - 1;
        if (nxt < nch) LOAD_STAGE((nxt & (STAGES - 1)), nxt);
        CP_COMMIT();

        const uint32_t base = sb + (uint32_t)(i & (STAGES - 1)) * STAGE_BYTES;

#pragma unroll
        for (int kk = 0; kk < 4; kk++) {
            const uint32_t kb = kk * 32;
            uint32_t ah[2][4], al[2][4], bh[8][2];
#pragma unroll
            for (int mi = 0; mi < 2; mi++) {
                uint32_t ad = base + (a_row + mi * 16) * ROW_STRIDE + kb + a_coff;
                LDSM4(ah[mi][0], ah[mi][1], ah[mi][2], ah[mi][3], ad);
                LDSM4(al[mi][0], al[mi][1], al[mi][2], al[mi][3], ad + MAT_BYTES);
            }
#pragma unroll
            for (int p = 0; p < 4; p++) {
                uint32_t bd = base + 2 * MAT_BYTES +
                              (b_row + p * 16) * ROW_STRIDE + kb + b_coff;
                uint32_t r0, r1, r2, r3;
                LDSM4(r0, r1, r2, r3, bd);
                bh[2*p][0] = r0;   bh[2*p][1] = r1;
                bh[2*p+1][0] = r2; bh[2*p+1][1] = r3;
            }
            // hi pass: 16 independent MMAs
#pragma unroll
            for (int mi = 0; mi < 2; mi++)
#pragma unroll
                for (int ni = 0; ni < 8; ni++)
                    MMAH(acc[mi][ni], ah[mi][0], ah[mi][1], ah[mi][2], ah[mi][3],
                         bh[ni][0], bh[ni][1]);
            // lo pass: 16 independent MMAs (acc reuse distance = 16)
#pragma unroll
            for (int mi = 0; mi < 2; mi++)
#pragma unroll
                for (int ni = 0; ni < 8; ni++)
                    MMAH(acc[mi][ni], al[mi][0], al[mi][1], al[mi][2], al[mi][3],
                         bh[ni][0], bh[ni][1]);
        }
    }
#undef LOAD_STAGE

    // epilogue
    const int row0 = bm * 128 + wm * 32 + (lane >> 2);
    const int col0 = bn * 128 + wn * 64 + (lane & 3) * 2;

#pragma unroll
    for (int mi = 0; mi < 2; mi++) {
#pragma unroll
        for (int ni = 0; ni < 8; ni++) {
            const int r = row0 + mi * 16;
            const int c = col0 + ni * 8;
            const float b0 = __ldg(bias + c);
            const float b1 = __ldg(bias + c + 1);
            float v00 = acc[mi][ni][0] + b0;
            float v01 = acc[mi][ni][1] + b1;
            float v10 = acc[mi][ni][2] + b0;
            float v11 = acc[mi][ni][3] + b1;
            if (mode >= 1) {
                v00 = fmaxf(v00, 0.0f); v01 = fmaxf(v01, 0.0f);
                v10 = fmaxf(v10, 0.0f); v11 = fmaxf(v11, 0.0f);
            }
            if (mode == 2) {
                __half h00, l00, h01, l01, h10, l10, h11, l11;
                split1(v00, h00, l00); split1(v01, h01, l01);
                split1(v10, h10, l10); split1(v11, h11, l11);
                uint16_t* ph = (uint16_t*)Ch;
                uint16_t* pl = (uint16_t*)Cl;
                uint32_t uh0 = (uint32_t)*(uint16_t*)&h00 | ((uint32_t)*(uint16_t*)&h01 << 16);
                uint32_t ul0 = (uint32_t)*(uint16_t*)&l00 | ((uint32_t)*(uint16_t*)&l01 << 16);
                uint32_t uh1 = (uint32_t)*(uint16_t*)&h10 | ((uint32_t)*(uint16_t*)&h11 << 16);
                uint32_t ul1 = (uint32_t)*(uint16_t*)&l10 | ((uint32_t)*(uint16_t*)&l11 << 16);
                *(uint32_t*)(ph + (size_t)r * N + c)       = uh0;
                *(uint32_t*)(pl + (size_t)r * N + c)       = ul0;
                *(uint32_t*)(ph + (size_t)(r + 8) * N + c) = uh1;
                *(uint32_t*)(pl + (size_t)(r + 8) * N + c) = ul1;
            } else {
                *(float2*)(Cf + (size_t)r * N + c)       = make_float2(v00, v01);
                *(float2*)(Cf + (size_t)(r + 8) * N + c) = make_float2(v10, v11);
            }
        }
    }
}

// ---------------------------------------------------------------------------
// fp32 -> fp16 hi/lo split (for x)
// ---------------------------------------------------------------------------
__global__ __launch_bounds__(256)
void split_kernel(const float* __restrict__ in, __half* __restrict__ hi,
                  __half* __restrict__ lo, size_t n4)
{
    size_t i = (size_t)blockIdx.x * 256 + threadIdx.x;
    if (i >= n4) return;
    float4 v = ((const float4*)in)[i];
    __half h[4], l[4];
    split1(v.x, h[0], l[0]); split1(v.y, h[1], l[1]);
    split1(v.z, h[2], l[2]); split1(v.w, h[3], l[3]);
    ((uint2*)hi)[i] = *(uint2*)h;
    ((uint2*)lo)[i] = *(uint2*)l;
}

// ---------------------------------------------------------------------------
// weight transpose + fp16 convert: W[K,N] -> Wt[N,K]
// ---------------------------------------------------------------------------
__global__ __launch_bounds__(256)
void wcvt_kernel(const float* __restrict__ W, __half* __restrict__ t,
                 int K, int N)
{
    int idx = blockIdx.x * 256 + threadIdx.x;
    if (idx >= K * N) return;
    int n = idx / K, k = idx - n * K;
    t[idx] = __float2half_rn(W[(size_t)k * N + n]);
}

// ---------------------------------------------------------------------------
// Attention for N=2 (one warp per sample). qkv: [T, 1536] (q|k|v).
// Outputs fp16 hi/lo.
// ---------------------------------------------------------------------------
__global__ __launch_bounds__(256)
void attn_kernel(const float* __restrict__ qkv,
                 __half* __restrict__ oh, __half* __restrict__ ol)
{
    int gw   = (blockIdx.x * 256 + threadIdx.x) >> 5;
    int lane = threadIdx.x & 31;
    if (gw >= B_) return;

    const float* base = qkv + (size_t)gw * 2 * 1536;
    const float4* q0 = (const float4*)(base);
    const float4* q1 = (const float4*)(base + 1536);
    const float4* k0 = (const float4*)(base + 512);
    const float4* k1 = (const float4*)(base + 1536 + 512);

    float s00 = 0.f, s01 = 0.f, s10 = 0.f, s11 = 0.f;
#pragma unroll
    for (int r = 0; r < 4; r++) {
        int i = lane + 32 * r;
        float4 a0 = q0[i], a1 = q1[i], b0 = k0[i], b1 = k1[i];
        s00 += a0.x * b0.x + a0.y * b0.y + a0.z * b0.z + a0.w * b0.w;
        s01 += a0.x * b1.x + a0.y * b1.y + a0.z * b1.z + a0.w * b1.w;
        s10 += a1.x * b0.x + a1.y * b0.y + a1.z * b0.z + a1.w * b0.w;
        s11 += a1.x * b1.x + a1.y * b1.y + a1.z * b1.z + a1.w * b1.w;
    }
    s00 = warp_sum(s00); s01 = warp_sum(s01);
    s10 = warp_sum(s10); s11 = warp_sum(s11);

    const float inv_scale = 1.0f / 22.627416997969522f;
    s00 *= inv_scale; s01 *= inv_scale; s10 *= inv_scale; s11 *= inv_scale;
    s00 = s00 > 0.f ? s00 : 0.2f * s00;
    s01 = s01 > 0.f ? s01 : 0.2f * s01;
    s10 = s10 > 0.f ? s10 : 0.2f * s10;
    s11 = s11 > 0.f ? s11 : 0.2f * s11;

    float m0 = fmaxf(s00, s01), m1 = fmaxf(s10, s11);
    float e00 = expf(s00 - m0), e01 = expf(s01 - m0);
    float e10 = expf(s10 - m1), e11 = expf(s11 - m1);
    float i0 = 1.0f / (e00 + e01), i1 = 1.0f / (e10 + e11);
    float a00 = e00 * i0, a01 = e01 * i0;
    float a10 = e10 * i1, a11 = e11 * i1;

    const float4* v0 = (const float4*)(base + 1024);
    const float4* v1 = (const float4*)(base + 1536 + 1024);
    __half* oh0 = oh + (size_t)gw * 2 * D_;
    __half* ol0 = ol + (size_t)gw * 2 * D_;

#pragma unroll
    for (int r = 0; r < 4; r++) {
        int i = lane + 32 * r;
        float4 x0 = v0[i], x1 = v1[i];
        float o0[4], o1[4];
        o0[0] = a00 * x0.x + a01 * x1.x;  o0[1] = a00 * x0.y + a01 * x1.y;
        o0[2] = a00 * x0.z + a01 * x1.z;  o0[3] = a00 * x0.w + a01 * x1.w;
        o1[0] = a10 * x0.x + a11 * x1.x;  o1[1] = a10 * x0.y + a11 * x1.y;
        o1[2] = a10 * x0.z + a11 * x1.z;  o1[3] = a10 * x0.w + a11 * x1.w;

        __half h0[4], l0[4], h1[4], l1[4];
#pragma unroll
        for (int c = 0; c < 4; c++) { split1(o0[c], h0[c], l0[c]); split1(o1[c], h1[c], l1[c]); }
        *(uint2*)(oh0 + (size_t)i * 4)      = *(uint2*)h0;
        *(uint2*)(ol0 + (size_t)i * 4)      = *(uint2*)l0;
        *(uint2*)(oh0 + D_ + (size_t)i * 4) = *(uint2*)h1;
        *(uint2*)(ol0 + D_ + (size_t)i * 4) = *(uint2*)l1;
    }
}

// ---------------------------------------------------------------------------
// out = LayerNorm(A + P) * g + be ; also emits fp16 hi/lo of out
// ---------------------------------------------------------------------------
__global__ __launch_bounds__(128)
void add_ln_kernel(const float* __restrict__ A, const float* __restrict__ P,
                   const float* __restrict__ g, const float* __restrict__ be,
                   float* __restrict__ out,
                   __half* __restrict__ oh, __half* __restrict__ ol)
{
    size_t row = blockIdx.x;
    int t = threadIdx.x;

    float4 av = ((const float4*)(A + row * D_))[t];
    float4 pv = ((const float4*)(P + row * D_))[t];
    float4 s;
    s.x = av.x + pv.x; s.y = av.y + pv.y; s.z = av.z + pv.z; s.w = av.w + pv.w;

    float sum = s.x + s.y + s.z + s.w;
    float sq  = s.x * s.x + s.y * s.y + s.z * s.z + s.w * s.w;
    sum = warp_sum(sum);
    sq  = warp_sum(sq);

    __shared__ float sm[8];
    int w = t >> 5;
    if ((t & 31) == 0) { sm[w] = sum; sm[4 + w] = sq; }
    __syncthreads();
    float ts = sm[0] + sm[1] + sm[2] + sm[3];
    float tq = sm[4] + sm[5] + sm[6] + sm[7];

    float mu  = ts * (1.0f / D_);
    float var = tq * (1.0f / D_) - mu * mu;
    float rs  = rsqrtf(var + 1e-5f);

    float4 G  = ((const float4*)g)[t];
    float4 Be = ((const float4*)be)[t];
    float4 o;
    o.x = (s.x - mu) * rs * G.x + Be.x;
    o.y = (s.y - mu) * rs * G.y + Be.y;
    o.z = (s.z - mu) * rs * G.z + Be.z;
    o.w = (s.w - mu) * rs * G.w + Be.w;
    ((float4*)(out + row * D_))[t] = o;

    __half h[4], l[4];
    split1(o.x, h[0], l[0]); split1(o.y, h[1], l[1]);
    split1(o.z, h[2], l[2]); split1(o.w, h[3], l[3]);
    *(uint2*)(oh + row * D_ + (size_t)t * 4) = *(uint2*)h;
    *(uint2*)(ol + row * D_ + (size_t)t * 4) = *(uint2*)l;
}

// ---------------------------------------------------------------------------
// Final stage: score dot, softmax over N=2, pooling, param-free LN
// ---------------------------------------------------------------------------
__global__ __launch_bounds__(256)
void final_kernel(const float* __restrict__ s1, const float* __restrict__ ws2,
                  const float* __restrict__ bs2, const float* __restrict__ refined,
                  float* __restrict__ fused, float* __restrict__ alpha)
{
    int gw   = (blockIdx.x * 256 + threadIdx.x) >> 5;
    int lane = threadIdx.x & 31;
    if (gw >= B_) return;

    const float4* r0 = (const float4*)(s1 + (size_t)gw * 2 * D_);
    const float4* r1 = r0 + D_ / 4;
    const float4* w2 = (const float4*)ws2;

    float d0 = 0.f, d1 = 0.f;
#pragma unroll
    for (int r = 0; r < 4; r++) {
        int i = lane + 32 * r;
        float4 w = w2[i], x0 = r0[i], x1 = r1[i];
        d0 += x0.x * w.x + x0.y * w.y + x0.z * w.z + x0.w * w.w;
        d1 += x1.x * w.x + x1.y * w.y + x1.z * w.z + x1.w * w.w;
    }
    d0 = warp_sum(d0) + bs2[0];
    d1 = warp_sum(d1) + bs2[0];

    float m  = fmaxf(d0, d1);
    float e0 = expf(d0 - m), e1 = expf(d1 - m);
    float inv = 1.0f / (e0 + e1);
    float a0 = e0 * inv, a1 = e1 * inv;
    if (lane == 0) {
        alpha[(size_t)gw * 2 + 0] = a0;
        alpha[(size_t)gw * 2 + 1] = a1;
    }

    const float4* f0 = (const float4*)(refined + (size_t)gw * 2 * D_);
    const float4* f1 = f0 + D_ / 4;

    float4 fr[4];
    float sum = 0.f, sq = 0.f;
#pragma unroll
    for (int r = 0; r < 4; r++) {
        int i = lane + 32 * r;
        float4 x0 = f0[i], x1 = f1[i];
        float4 t;
        t.x = a0 * x0.x + a1 * x1.x;  t.y = a0 * x0.y + a1 * x1.y;
        t.z = a0 * x0.z + a1 * x1.z;  t.w = a0 * x0.w + a1 * x1.w;
        fr[r] = t;
        sum += t.x + t.y + t.z + t.w;
        sq  += t.x * t.x + t.y * t.y + t.z * t.z + t.w * t.w;
    }
    sum = warp_sum(sum);
    sq  = warp_sum(sq);
    float mu  = sum * (1.0f / D_);
    float var = sq * (1.0f / D_) - mu * mu;
    float rs  = rsqrtf(var + 1e-5f);

    float4* fo = (float4*)(fused + (size_t)gw * D_);
#pragma unroll
    for (int r = 0; r < 4; r++) {
        int i = lane + 32 * r;
        float4 t = fr[r];
        float4 o;
        o.x = (t.x - mu) * rs;  o.y = (t.y - mu) * rs;
        o.z = (t.z - mu) * rs;  o.w = (t.w - mu) * rs;
        fo[i] = o;
    }
}

// ---------------------------------------------------------------------------
// Launch
// ---------------------------------------------------------------------------
extern "C" void kernel_launch(void* const* d_in, const int* in_sizes, int n_in,
                              void* d_out, int out_size)
{
    const float* x   = (const float*)d_in[0];
    const float* wq  = (const float*)d_in[1];
    const float* bq  = (const float*)d_in[2];
    const float* wk  = (const float*)d_in[3];
    const float* bk  = (const float*)d_in[4];
    const float* wv  = (const float*)d_in[5];
    const float* bv  = (const float*)d_in[6];
    const float* wo  = (const float*)d_in[7];
    const float* bo  = (const float*)d_in[8];
    const float* g1  = (const float*)d_in[9];
    const float* be1 = (const float*)d_in[10];
    const float* wf1 = (const float*)d_in[11];
    const float* bf1 = (const float*)d_in[12];
    const float* wf2 = (const float*)d_in[13];
    const float* bf2 = (const float*)d_in[14];
    const float* g2  = (const float*)d_in[15];
    const float* be2 = (const float*)d_in[16];
    const float* ws1 = (const float*)d_in[17];
    const float* bs1 = (const float*)d_in[18];
    const float* ws2 = (const float*)d_in[19];
    const float* bs2 = (const float*)d_in[20];

    float *qkv, *p, *h, *s1, *bqkv;
    __half *xh, *xl, *ah, *al, *hh, *hl, *rh, *rl, *fh, *fl, *wt;
    cudaGetSymbolAddress((void**)&qkv, g_qkv);
    cudaGetSymbolAddress((void**)&p, g_p);
    cudaGetSymbolAddress((void**)&h, g_h);
    cudaGetSymbolAddress((void**)&s1, g_s1);
    cudaGetSymbolAddress((void**)&bqkv, g_bqkv);
    cudaGetSymbolAddress((void**)&xh, g_xh);
    cudaGetSymbolAddress((void**)&xl, g_xl);
    cudaGetSymbolAddress((void**)&ah, g_ah);
    cudaGetSymbolAddress((void**)&al, g_al);
    cudaGetSymbolAddress((void**)&hh, g_hh);
    cudaGetSymbolAddress((void**)&hl, g_hl);
    cudaGetSymbolAddress((void**)&rh, g_rh);
    cudaGetSymbolAddress((void**)&rl, g_rl);
    cudaGetSymbolAddress((void**)&fh, g_fh);
    cudaGetSymbolAddress((void**)&fl, g_fl);
    cudaGetSymbolAddress((void**)&wt, g_wt);

    cudaFuncSetAttribute(gemm_mma, cudaFuncAttributeMaxDynamicSharedMemorySize,
                         GEMM_SMEM);

    float* out     = (float*)d_out;
    float* fused   = out;
    float* alpha   = out + (size_t)B_ * D_;
    float* refined = alpha + (size_t)B_ * N_;

    // preprocessing
    split_kernel<<<(unsigned)(TD_ / 4 / 256), 256>>>(x, xh, xl, TD_ / 4);
    wcvt_kernel<<<1024, 256>>>(wq,  wt + WQ_OFF,  512, 512);
    wcvt_kernel<<<1024, 256>>>(wk,  wt + WK_OFF,  512, 512);
    wcvt_kernel<<<1024, 256>>>(wv,  wt + WV_OFF,  512, 512);
    wcvt_kernel<<<1024, 256>>>(wo,  wt + WO_OFF,  512, 512);
    wcvt_kernel<<<2048, 256>>>(wf1, wt + WF1_OFF, 512, 1024);
    wcvt_kernel<<<2048, 256>>>(wf2, wt + WF2_OFF, 1024, 512);
    wcvt_kernel<<<1024, 256>>>(ws1, wt + WS1_OFF, 512, 512);
    cudaMemcpyAsync(bqkv,        bq, 512 * 4, cudaMemcpyDeviceToDevice);
    cudaMemcpyAsync(bqkv + 512,  bk, 512 * 4, cudaMemcpyDeviceToDevice);
    cudaMemcpyAsync(bqkv + 1024, bv, 512 * 4, cudaMemcpyDeviceToDevice);

    dim3 blk(256);
    dim3 gQKV(12, T_ / 128);
    dim3 gD(4, T_ / 128);
    dim3 gF(8, T_ / 128);

    // fused QKV projection: [T,512] @ [512,1536] -> [T,1536]
    gemm_mma<<<gQKV, blk, GEMM_SMEM>>>(xh, xl, wt + WQ_OFF, bqkv, qkv, nullptr, nullptr, 1536, 512, 0);
    // attention -> fp16 hi/lo
    attn_kernel<<<B_ / 8, 256>>>(qkv, ah, al);
    // output projection + residual LN1
    gemm_mma<<<gD, blk, GEMM_SMEM>>>(ah, al, wt + WO_OFF, bo, p, nullptr, nullptr, 512, 512, 0);
    add_ln_kernel<<<T_, 128>>>(x, p, g1, be1, h, hh, hl);
    // FFN
    gemm_mma<<<gF, blk, GEMM_SMEM>>>(hh, hl, wt + WF1_OFF, bf1, nullptr, fh, fl, 1024, 512, 2);
    gemm_mma<<<gD, blk, GEMM_SMEM>>>(fh, fl, wt + WF2_OFF, bf2, p, nullptr, nullptr, 512, 1024, 0);
    add_ln_kernel<<<T_, 128>>>(h, p, g2, be2, refined, rh, rl);
    // score MLP stage 1 (ReLU)
    gemm_mma<<<gD, blk, GEMM_SMEM>>>(rh, rl, wt + WS1_OFF, bs1, s1, nullptr, nullptr, 512, 512, 1);
    // scores, alpha, pooling, final LN
    final_kernel<<<B_ / 8, 256>>>(s1, ws2, bs2, refined, fused, alpha);
}

// round 6
// speedup vs baseline: 3.9710x; 1.5953x over previous
#include <cuda_runtime.h>
#include <cuda_fp16.h>
#include <cstdint>

// ---------------------------------------------------------------------------
// Problem constants
// ---------------------------------------------------------------------------
#define B_   65536
#define N_   2
#define D_   512
#define T_   (B_ * N_)          // 131072 tokens
#define TD_  ((size_t)T_ * D_)  // 67,108,864

// ---------------------------------------------------------------------------
// Scratch (static __device__ arrays)
// ---------------------------------------------------------------------------
__device__ __half g_qkv[3 * TD_];  // fused QKV output [T, 1536] fp16
__device__ float  g_p[TD_];
__device__ float  g_h[TD_];
__device__ float  g_s1[TD_];
__device__ float  g_bqkv[3 * D_];

__device__ __half g_xh[TD_];
__device__ __half g_ah[TD_];
__device__ __half g_hh[TD_];
__device__ __half g_rh[TD_];
__device__ __half g_fh[2 * TD_];

// transposed fp16 weights, [N,K] layout. QKV concat at 0.
#define WQ_OFF  0
#define WK_OFF  262144
#define WV_OFF  524288
#define WO_OFF  786432
#define WF1_OFF 1048576
#define WF2_OFF 1572864
#define WS1_OFF 2097152
__device__ __half g_wt[2359296];

// ---------------------------------------------------------------------------
// PTX helpers (baseline sm_80+)
// ---------------------------------------------------------------------------
__device__ __forceinline__ uint32_t smem_u32(const void* smem_ptr) {
    uint32_t addr;
    asm("{ .reg .u64 tmp; cvta.to.shared.u64 tmp, %1; cvt.u32.u64 %0, tmp; }"
        : "=r"(addr) : "l"(smem_ptr));
    return addr;
}

#define CP16(dst, src) \
    asm volatile("cp.async.cg.shared.global [%0], [%1], 16;" \
        :: "r"(dst), "l"(src))

#define CP_COMMIT() asm volatile("cp.async.commit_group;" ::: "memory")
#define CP_WAIT(n)  asm volatile("cp.async.wait_group %0;" :: "n"(n) : "memory")

#define LDSM4(r0, r1, r2, r3, a) \
    asm volatile("ldmatrix.sync.aligned.m8n8.x4.shared.b16 {%0,%1,%2,%3}, [%4];" \
        : "=r"(r0), "=r"(r1), "=r"(r2), "=r"(r3) : "r"(a))

#define MMAH(d, a0, a1, a2, a3, b0, b1) \
    asm volatile("mma.sync.aligned.m16n8k16.row.col.f32.f16.f16.f32 " \
        "{%0,%1,%2,%3}, {%4,%5,%6,%7}, {%8,%9}, {%0,%1,%2,%3};" \
        : "+f"((d)[0]), "+f"((d)[1]), "+f"((d)[2]), "+f"((d)[3]) \
        : "r"(a0), "r"(a1), "r"(a2), "r"(a3), "r"(b0), "r"(b1))

__device__ __forceinline__ float warp_sum(float v) {
#pragma unroll
    for (int o = 16; o; o >>= 1) v += __shfl_xor_sync(0xffffffffu, v, o);
    return v;
}

// dot of 8 fp16 pairs packed in uint4, accumulated in fp32
__device__ __forceinline__ float dot8(uint4 a, uint4 b) {
    const __half2* pa = (const __half2*)&a;
    const __half2* pb = (const __half2*)&b;
    float s = 0.f;
#pragma unroll
    for (int j = 0; j < 4; j++) {
        float2 fa = __half22float2(pa[j]);
        float2 fb = __half22float2(pb[j]);
        s += fa.x * fb.x + fa.y * fb.y;
    }
    return s;
}

// ---------------------------------------------------------------------------
// mma.sync GEMM: C[M,N] = A[M,K] @ B^T[N,K] + bias  (both fp16, fp32 accum)
// CTA tile 128x128, 8 warps (4m x 2n), warp tile 32x64, K-chunk 64,
// 4-stage cp.async pipeline. SMEM rows stride 144B (conflict-free).
// mode: 0 = fp32 out; 1 = fp32 out + ReLU; 2 = fp16 out + ReLU; 3 = fp16 out.
// ---------------------------------------------------------------------------
#define STAGES        4
#define ROW_STRIDE    144
#define MAT_BYTES     18432     // 128 rows * 144B
#define STAGE_BYTES   36864     // 2 matrices (A, B)
#define GEMM_SMEM     (STAGES * STAGE_BYTES)   // 147456

__global__ __launch_bounds__(256, 1)
void gemm_mma(const __half* __restrict__ A, const __half* __restrict__ B,
              const float* __restrict__ bias,
              float* __restrict__ Cf, __half* __restrict__ Ch,
              int N, int K, int mode)
{
    extern __shared__ char smem[];
    const uint32_t sb = smem_u32(smem);
    const int tid  = threadIdx.x;
    const int lane = tid & 31;
    const int wid  = tid >> 5;
    const int wm   = wid & 3;
    const int wn   = wid >> 2;
    const int bn   = blockIdx.x;
    const int bm   = blockIdx.y;
    const int Kb   = K * 2;

    const char* gA = (const char*)(A + (size_t)bm * 128 * K);
    const char* gB = (const char*)(B + (size_t)bn * 128 * K);

    const int lr  = tid >> 1;
    const int lcb = (tid & 1) * 64;
    const size_t   goff = (size_t)lr * Kb + lcb;
    const uint32_t soff = (uint32_t)lr * ROW_STRIDE + lcb;

    float acc[2][8][4];
#pragma unroll
    for (int mi = 0; mi < 2; mi++)
#pragma unroll
        for (int ni = 0; ni < 8; ni++)
#pragma unroll
            for (int r = 0; r < 4; r++) acc[mi][ni][r] = 0.0f;

    const int nch = K >> 6;

#define LOAD_STAGE(stage, kc) do {                                        \
        uint32_t d = sb + (uint32_t)(stage) * STAGE_BYTES + soff;         \
        size_t   g = goff + (size_t)(kc) * 128;                           \
        CP16(d,                   gA + g);                                \
        CP16(d + 16,              gA + g + 16);                           \
        CP16(d + 32,              gA + g + 32);                           \
        CP16(d + 48,              gA + g + 48);                           \
        CP16(d + MAT_BYTES,       gB + g);                                \
        CP16(d + MAT_BYTES + 16,  gB + g + 16);                           \
        CP16(d + MAT_BYTES + 32,  gB + g + 32);                           \
        CP16(d + MAT_BYTES + 48,  gB + g + 48);                           \
    } while (0)

#pragma unroll
    for (int s = 0; s < STAGES - 1; s++) { LOAD_STAGE(s, s); CP_COMMIT(); }

    const uint32_t a_row  = (uint32_t)(wm * 32 + (lane & 15));
    const uint32_t a_coff = (uint32_t)((lane >> 4) * 16);
    const uint32_t b_row  = (uint32_t)(wn * 64 + ((lane >> 4) * 8) + (lane & 7));
    const uint32_t b_coff = (uint32_t)(((lane >> 3) & 1) * 16);

#pragma unroll 1
    for (int i = 0; i < nch; i++) {
        CP_WAIT(STAGES - 2);
        __syncthreads();

        int nxt = i + STAGES - 1;
        if (nxt < nch) LOAD_STAGE((nxt & (STAGES - 1)), nxt);
        CP_COMMIT();

        const uint32_t base = sb + (uint32_t)(i & (STAGES - 1)) * STAGE_BYTES;

#pragma unroll
        for (int kk = 0; kk < 4; kk++) {
            const uint32_t kb = kk * 32;
            uint32_t ar[2][4], br[8][2];
#pragma unroll
            for (int mi = 0; mi < 2; mi++) {
                uint32_t ad = base + (a_row + mi * 16) * ROW_STRIDE + kb + a_coff;
                LDSM4(ar[mi][0], ar[mi][1], ar[mi][2], ar[mi][3], ad);
            }
#pragma unroll
            for (int p = 0; p < 4; p++) {
                uint32_t bd = base + MAT_BYTES +
                              (b_row + p * 16) * ROW_STRIDE + kb + b_coff;
                uint32_t r0, r1, r2, r3;
                LDSM4(r0, r1, r2, r3, bd);
                br[2*p][0] = r0;   br[2*p][1] = r1;
                br[2*p+1][0] = r2; br[2*p+1][1] = r3;
            }
#pragma unroll
            for (int mi = 0; mi < 2; mi++)
#pragma unroll
                for (int ni = 0; ni < 8; ni++)
                    MMAH(acc[mi][ni], ar[mi][0], ar[mi][1], ar[mi][2], ar[mi][3],
                         br[ni][0], br[ni][1]);
        }
    }
#undef LOAD_STAGE

    // epilogue
    const int row0 = bm * 128 + wm * 32 + (lane >> 2);
    const int col0 = bn * 128 + wn * 64 + (lane & 3) * 2;

#pragma unroll
    for (int mi = 0; mi < 2; mi++) {
#pragma unroll
        for (int ni = 0; ni < 8; ni++) {
            const int r = row0 + mi * 16;
            const int c = col0 + ni * 8;
            const float b0 = __ldg(bias + c);
            const float b1 = __ldg(bias + c + 1);
            float v00 = acc[mi][ni][0] + b0;
            float v01 = acc[mi][ni][1] + b1;
            float v10 = acc[mi][ni][2] + b0;
            float v11 = acc[mi][ni][3] + b1;
            if (mode == 1 || mode == 2) {
                v00 = fmaxf(v00, 0.0f); v01 = fmaxf(v01, 0.0f);
                v10 = fmaxf(v10, 0.0f); v11 = fmaxf(v11, 0.0f);
            }
            if (mode >= 2) {
                __half2 h0 = __floats2half2_rn(v00, v01);
                __half2 h1 = __floats2half2_rn(v10, v11);
                *(__half2*)(Ch + (size_t)r * N + c)       = h0;
                *(__half2*)(Ch + (size_t)(r + 8) * N + c) = h1;
            } else {
                *(float2*)(Cf + (size_t)r * N + c)       = make_float2(v00, v01);
                *(float2*)(Cf + (size_t)(r + 8) * N + c) = make_float2(v10, v11);
            }
        }
    }
}

// ---------------------------------------------------------------------------
// fp32 -> fp16 convert (for x)
// ---------------------------------------------------------------------------
__global__ __launch_bounds__(256)
void cvt_kernel(const float* __restrict__ in, __half* __restrict__ out, size_t n4)
{
    size_t i = (size_t)blockIdx.x * 256 + threadIdx.x;
    if (i >= n4) return;
    float4 v = ((const float4*)in)[i];
    __half2 h0 = __floats2half2_rn(v.x, v.y);
    __half2 h1 = __floats2half2_rn(v.z, v.w);
    uint2 o;
    o.x = *(uint32_t*)&h0;
    o.y = *(uint32_t*)&h1;
    ((uint2*)out)[i] = o;
}

// ---------------------------------------------------------------------------
// weight transpose + fp16 convert: W[K,N] -> Wt[N,K]
// ---------------------------------------------------------------------------
__global__ __launch_bounds__(256)
void wcvt_kernel(const float* __restrict__ W, __half* __restrict__ t,
                 int K, int N)
{
    int idx = blockIdx.x * 256 + threadIdx.x;
    if (idx >= K * N) return;
    int n = idx / K, k = idx - n * K;
    t[idx] = __float2half_rn(W[(size_t)k * N + n]);
}

// ---------------------------------------------------------------------------
// Attention for N=2 (one warp per sample). qkv fp16 [T, 1536] (q|k|v).
// Output single fp16.
// ---------------------------------------------------------------------------
__global__ __launch_bounds__(256)
void attn_kernel(const __half* __restrict__ qkv, __half* __restrict__ oh)
{
    int gw   = (blockIdx.x * 256 + threadIdx.x) >> 5;
    int lane = threadIdx.x & 31;
    if (gw >= B_) return;

    const __half* base = qkv + (size_t)gw * 2 * 1536;
    // each uint4 = 8 halves; 512 halves = 64 uint4; 2 per lane
    const uint4* q0 = (const uint4*)(base);
    const uint4* q1 = (const uint4*)(base + 1536);
    const uint4* k0 = (const uint4*)(base + 512);
    const uint4* k1 = (const uint4*)(base + 1536 + 512);

    float s00 = 0.f, s01 = 0.f, s10 = 0.f, s11 = 0.f;
#pragma unroll
    for (int r = 0; r < 2; r++) {
        int i = lane + 32 * r;
        uint4 a0 = q0[i], a1 = q1[i], b0 = k0[i], b1 = k1[i];
        s00 += dot8(a0, b0);
        s01 += dot8(a0, b1);
        s10 += dot8(a1, b0);
        s11 += dot8(a1, b1);
    }
    s00 = warp_sum(s00); s01 = warp_sum(s01);
    s10 = warp_sum(s10); s11 = warp_sum(s11);

    const float inv_scale = 1.0f / 22.627416997969522f;
    s00 *= inv_scale; s01 *= inv_scale; s10 *= inv_scale; s11 *= inv_scale;
    s00 = s00 > 0.f ? s00 : 0.2f * s00;
    s01 = s01 > 0.f ? s01 : 0.2f * s01;
    s10 = s10 > 0.f ? s10 : 0.2f * s10;
    s11 = s11 > 0.f ? s11 : 0.2f * s11;

    float m0 = fmaxf(s00, s01), m1 = fmaxf(s10, s11);
    float e00 = expf(s00 - m0), e01 = expf(s01 - m0);
    float e10 = expf(s10 - m1), e11 = expf(s11 - m1);
    float i0 = 1.0f / (e00 + e01), i1 = 1.0f / (e10 + e11);
    float a00 = e00 * i0, a01 = e01 * i0;
    float a10 = e10 * i1, a11 = e11 * i1;

    const uint4* v0 = (const uint4*)(base + 1024);
    const uint4* v1 = (const uint4*)(base + 1536 + 1024);
    uint4* o0 = (uint4*)(oh + (size_t)gw * 2 * D_);
    uint4* o1 = o0 + D_ / 8;

#pragma unroll
    for (int r = 0; r < 2; r++) {
        int i = lane + 32 * r;
        uint4 x0 = v0[i], x1 = v1[i];
        const __half2* p0 = (const __half2*)&x0;
        const __half2* p1 = (const __half2*)&x1;
        uint4 r0, r1;
        __half2* q0o = (__half2*)&r0;
        __half2* q1o = (__half2*)&r1;
#pragma unroll
        for (int j = 0; j < 4; j++) {
            float2 f0 = __half22float2(p0[j]);
            float2 f1 = __half22float2(p1[j]);
            q0o[j] = __floats2half2_rn(a00 * f0.x + a01 * f1.x,
                                       a00 * f0.y + a01 * f1.y);
            q1o[j] = __floats2half2_rn(a10 * f0.x + a11 * f1.x,
                                       a10 * f0.y + a11 * f1.y);
        }
        o0[i] = r0;
        o1[i] = r1;
    }
}

// ---------------------------------------------------------------------------
// out = LayerNorm(A + P) * g + be ; fp32 out + fp16 copy
// ---------------------------------------------------------------------------
__global__ __launch_bounds__(128)
void add_ln_kernel(const float* __restrict__ A, const float* __restrict__ P,
                   const float* __restrict__ g, const float* __restrict__ be,
                   float* __restrict__ out, __half* __restrict__ oh)
{
    size_t row = blockIdx.x;
    int t = threadIdx.x;

    float4 av = ((const float4*)(A + row * D_))[t];
    float4 pv = ((const float4*)(P + row * D_))[t];
    float4 s;
    s.x = av.x + pv.x; s.y = av.y + pv.y; s.z = av.z + pv.z; s.w = av.w + pv.w;

    float sum = s.x + s.y + s.z + s.w;
    float sq  = s.x * s.x + s.y * s.y + s.z * s.z + s.w * s.w;
    sum = warp_sum(sum);
    sq  = warp_sum(sq);

    __shared__ float sm[8];
    int w = t >> 5;
    if ((t & 31) == 0) { sm[w] = sum; sm[4 + w] = sq; }
    __syncthreads();
    float ts = sm[0] + sm[1] + sm[2] + sm[3];
    float tq = sm[4] + sm[5] + sm[6] + sm[7];

    float mu  = ts * (1.0f / D_);
    float var = tq * (1.0f / D_) - mu * mu;
    float rs  = rsqrtf(var + 1e-5f);

    float4 G  = ((const float4*)g)[t];
    float4 Be = ((const float4*)be)[t];
    float4 o;
    o.x = (s.x - mu) * rs * G.x + Be.x;
    o.y = (s.y - mu) * rs * G.y + Be.y;
    o.z = (s.z - mu) * rs * G.z + Be.z;
    o.w = (s.w - mu) * rs * G.w + Be.w;
    ((float4*)(out + row * D_))[t] = o;

    __half2 h0 = __floats2half2_rn(o.x, o.y);
    __half2 h1 = __floats2half2_rn(o.z, o.w);
    uint2 u;
    u.x = *(uint32_t*)&h0;
    u.y = *(uint32_t*)&h1;
    ((uint2*)(oh + row * D_))[t] = u;
}

// ---------------------------------------------------------------------------
// Final stage: score dot, softmax over N=2, pooling, param-free LN
// ---------------------------------------------------------------------------
__global__ __launch_bounds__(256)
void final_kernel(const float* __restrict__ s1, const float* __restrict__ ws2,
                  const float* __restrict__ bs2, const float* __restrict__ refined,
                  float* __restrict__ fused, float* __restrict__ alpha)
{
    int gw   = (blockIdx.x * 256 + threadIdx.x) >> 5;
    int lane = threadIdx.x & 31;
    if (gw >= B_) return;

    const float4* r0 = (const float4*)(s1 + (size_t)gw * 2 * D_);
    const float4* r1 = r0 + D_ / 4;
    const float4* w2 = (const float4*)ws2;

    float d0 = 0.f, d1 = 0.f;
#pragma unroll
    for (int r = 0; r < 4; r++) {
        int i = lane + 32 * r;
        float4 w = w2[i], x0 = r0[i], x1 = r1[i];
        d0 += x0.x * w.x + x0.y * w.y + x0.z * w.z + x0.w * w.w;
        d1 += x1.x * w.x + x1.y * w.y + x1.z * w.z + x1.w * w.w;
    }
    d0 = warp_sum(d0) + bs2[0];
    d1 = warp_sum(d1) + bs2[0];

    float m  = fmaxf(d0, d1);
    float e0 = expf(d0 - m), e1 = expf(d1 - m);
    float inv = 1.0f / (e0 + e1);
    float a0 = e0 * inv, a1 = e1 * inv;
    if (lane == 0) {
        alpha[(size_t)gw * 2 + 0] = a0;
        alpha[(size_t)gw * 2 + 1] = a1;
    }

    const float4* f0 = (const float4*)(refined + (size_t)gw * 2 * D_);
    const float4* f1 = f0 + D_ / 4;

    float4 fr[4];
    float sum = 0.f, sq = 0.f;
#pragma unroll
    for (int r = 0; r < 4; r++) {
        int i = lane + 32 * r;
        float4 x0 = f0[i], x1 = f1[i];
        float4 t;
        t.x = a0 * x0.x + a1 * x1.x;  t.y = a0 * x0.y + a1 * x1.y;
        t.z = a0 * x0.z + a1 * x1.z;  t.w = a0 * x0.w + a1 * x1.w;
        fr[r] = t;
        sum += t.x + t.y + t.z + t.w;
        sq  += t.x * t.x + t.y * t.y + t.z * t.z + t.w * t.w;
    }
    sum = warp_sum(sum);
    sq  = warp_sum(sq);
    float mu  = sum * (1.0f / D_);
    float var = sq * (1.0f / D_) - mu * mu;
    float rs  = rsqrtf(var + 1e-5f);

    float4* fo = (float4*)(fused + (size_t)gw * D_);
#pragma unroll
    for (int r = 0; r < 4; r++) {
        int i = lane + 32 * r;
        float4 t = fr[r];
        float4 o;
        o.x = (t.x - mu) * rs;  o.y = (t.y - mu) * rs;
        o.z = (t.z - mu) * rs;  o.w = (t.w - mu) * rs;
        fo[i] = o;
    }
}

// ---------------------------------------------------------------------------
// Launch
// ---------------------------------------------------------------------------
extern "C" void kernel_launch(void* const* d_in, const int* in_sizes, int n_in,
                              void* d_out, int out_size)
{
    const float* x   = (const float*)d_in[0];
    const float* wq  = (const float*)d_in[1];
    const float* bq  = (const float*)d_in[2];
    const float* wk  = (const float*)d_in[3];
    const float* bk  = (const float*)d_in[4];
    const float* wv  = (const float*)d_in[5];
    const float* bv  = (const float*)d_in[6];
    const float* wo  = (const float*)d_in[7];
    const float* bo  = (const float*)d_in[8];
    const float* g1  = (const float*)d_in[9];
    const float* be1 = (const float*)d_in[10];
    const float* wf1 = (const float*)d_in[11];
    const float* bf1 = (const float*)d_in[12];
    const float* wf2 = (const float*)d_in[13];
    const float* bf2 = (const float*)d_in[14];
    const float* g2  = (const float*)d_in[15];
    const float* be2 = (const float*)d_in[16];
    const float* ws1 = (const float*)d_in[17];
    const float* bs1 = (const float*)d_in[18];
    const float* ws2 = (const float*)d_in[19];
    const float* bs2 = (const float*)d_in[20];

    float *p, *h, *s1, *bqkv;
    __half *qkv, *xh, *ah, *hh, *rh, *fh, *wt;
    cudaGetSymbolAddress((void**)&qkv, g_qkv);
    cudaGetSymbolAddress((void**)&p, g_p);
    cudaGetSymbolAddress((void**)&h, g_h);
    cudaGetSymbolAddress((void**)&s1, g_s1);
    cudaGetSymbolAddress((void**)&bqkv, g_bqkv);
    cudaGetSymbolAddress((void**)&xh, g_xh);
    cudaGetSymbolAddress((void**)&ah, g_ah);
    cudaGetSymbolAddress((void**)&hh, g_hh);
    cudaGetSymbolAddress((void**)&rh, g_rh);
    cudaGetSymbolAddress((void**)&fh, g_fh);
    cudaGetSymbolAddress((void**)&wt, g_wt);

    cudaFuncSetAttribute(gemm_mma, cudaFuncAttributeMaxDynamicSharedMemorySize,
                         GEMM_SMEM);

    float* out     = (float*)d_out;
    float* fused   = out;
    float* alpha   = out + (size_t)B_ * D_;
    float* refined = alpha + (size_t)B_ * N_;

    // preprocessing
    cvt_kernel<<<(unsigned)(TD_ / 4 / 256), 256>>>(x, xh, TD_ / 4);
    wcvt_kernel<<<1024, 256>>>(wq,  wt + WQ_OFF,  512, 512);
    wcvt_kernel<<<1024, 256>>>(wk,  wt + WK_OFF,  512, 512);
    wcvt_kernel<<<1024, 256>>>(wv,  wt + WV_OFF,  512, 512);
    wcvt_kernel<<<1024, 256>>>(wo,  wt + WO_OFF,  512, 512);
    wcvt_kernel<<<2048, 256>>>(wf1, wt + WF1_OFF, 512, 1024);
    wcvt_kernel<<<2048, 256>>>(wf2, wt + WF2_OFF, 1024, 512);
    wcvt_kernel<<<1024, 256>>>(ws1, wt + WS1_OFF, 512, 512);
    cudaMemcpyAsync(bqkv,        bq, 512 * 4, cudaMemcpyDeviceToDevice);
    cudaMemcpyAsync(bqkv + 512,  bk, 512 * 4, cudaMemcpyDeviceToDevice);
    cudaMemcpyAsync(bqkv + 1024, bv, 512 * 4, cudaMemcpyDeviceToDevice);

    dim3 blk(256);
    dim3 gQKV(12, T_ / 128);
    dim3 gD(4, T_ / 128);
    dim3 gF(8, T_ / 128);

    // fused QKV projection -> fp16 [T,1536]
    gemm_mma<<<gQKV, blk, GEMM_SMEM>>>(xh, wt + WQ_OFF, bqkv, nullptr, qkv, 1536, 512, 3);
    // attention -> fp16
    attn_kernel<<<B_ / 8, 256>>>(qkv, ah);
    // output projection + residual LN1
    gemm_mma<<<gD, blk, GEMM_SMEM>>>(ah, wt + WO_OFF, bo, p, nullptr, 512, 512, 0);
    add_ln_kernel<<<T_, 128>>>(x, p, g1, be1, h, hh);
    // FFN
    gemm_mma<<<gF, blk, GEMM_SMEM>>>(hh, wt + WF1_OFF, bf1, nullptr, fh, 1024, 512, 2);
    gemm_mma<<<gD, blk, GEMM_SMEM>>>(fh, wt + WF2_OFF, bf2, p, nullptr, 512, 1024, 0);
    add_ln_kernel<<<T_, 128>>>(h, p, g2, be2, refined, rh);
    // score MLP stage 1 (ReLU)
    gemm_mma<<<gD, blk, GEMM_SMEM>>>(rh, wt + WS1_OFF, bs1, s1, nullptr, 512, 512, 1);
    // scores, alpha, pooling, final LN
    final_kernel<<<B_ / 8, 256>>>(s1, ws2, bs2, refined, fused, alpha);
}

// round 7
// speedup vs baseline: 4.2532x; 1.0711x over previous
#include <cuda_runtime.h>
#include <cuda_fp16.h>
#include <cstdint>

// ---------------------------------------------------------------------------
// Problem constants
// ---------------------------------------------------------------------------
#define B_   65536
#define N_   2
#define D_   512
#define T_   (B_ * N_)          // 131072 tokens
#define TD_  ((size_t)T_ * D_)  // 67,108,864

// ---------------------------------------------------------------------------
// Scratch (static __device__ arrays)
// ---------------------------------------------------------------------------
__device__ __half g_uv[2 * TD_];   // [T, 1024]: u | v
__device__ float  g_h[TD_];
__device__ float  g_sp[(size_t)T_ * 8];  // score partials [T, 8]
__device__ float  g_buv[1024];     // bias for uv GEMM: zeros | bv
__device__ float  g_wa[512], g_wb[512], g_gamma[1];

__device__ __half g_xh[TD_];
__device__ __half g_ah[TD_];
__device__ __half g_hh[TD_];
__device__ __half g_rh[TD_];
__device__ __half g_ph[TD_];       // fp16 GEMM intermediate (pre-LN)
__device__ __half g_fh[2 * TD_];
__device__ __half g_wq16[262144], g_wk16[262144];  // row-major fp16 wq, wk

// transposed fp16 weights, [N,K] layout
#define WK_OFF  262144   // Mt lives here; contiguous with WV for fused uv GEMM
#define WV_OFF  524288
#define WO_OFF  786432
#define WF1_OFF 1048576
#define WF2_OFF 1572864
#define WS1_OFF 2097152
__device__ __half g_wt[2359296];

// ---------------------------------------------------------------------------
// PTX helpers (baseline sm_80+)
// ---------------------------------------------------------------------------
__device__ __forceinline__ uint32_t smem_u32(const void* smem_ptr) {
    uint32_t addr;
    asm("{ .reg .u64 tmp; cvta.to.shared.u64 tmp, %1; cvt.u32.u64 %0, tmp; }"
        : "=r"(addr) : "l"(smem_ptr));
    return addr;
}

#define CP16(dst, src) \
    asm volatile("cp.async.cg.shared.global [%0], [%1], 16;" \
        :: "r"(dst), "l"(src))

#define CP_COMMIT() asm volatile("cp.async.commit_group;" ::: "memory")
#define CP_WAIT(n)  asm volatile("cp.async.wait_group %0;" :: "n"(n) : "memory")

#define LDSM4(r0, r1, r2, r3, a) \
    asm volatile("ldmatrix.sync.aligned.m8n8.x4.shared.b16 {%0,%1,%2,%3}, [%4];" \
        : "=r"(r0), "=r"(r1), "=r"(r2), "=r"(r3) : "r"(a))

#define MMAH(d, a0, a1, a2, a3, b0, b1) \
    asm volatile("mma.sync.aligned.m16n8k16.row.col.f32.f16.f16.f32 " \
        "{%0,%1,%2,%3}, {%4,%5,%6,%7}, {%8,%9}, {%0,%1,%2,%3};" \
        : "+f"((d)[0]), "+f"((d)[1]), "+f"((d)[2]), "+f"((d)[3]) \
        : "r"(a0), "r"(a1), "r"(a2), "r"(a3), "r"(b0), "r"(b1))

__device__ __forceinline__ float warp_sum(float v) {
#pragma unroll
    for (int o = 16; o; o >>= 1) v += __shfl_xor_sync(0xffffffffu, v, o);
    return v;
}

// dot of 8 fp16 pairs packed in uint4, accumulated in fp32
__device__ __forceinline__ float dot8(uint4 a, uint4 b) {
    const __half2* pa = (const __half2*)&a;
    const __half2* pb = (const __half2*)&b;
    float s = 0.f;
#pragma unroll
    for (int j = 0; j < 4; j++) {
        float2 fa = __half22float2(pa[j]);
        float2 fb = __half22float2(pb[j]);
        s += fa.x * fb.x + fa.y * fb.y;
    }
    return s;
}

// dot of 8 fp16 (uint4) with 8 fp32 (two float4)
__device__ __forceinline__ float dot8f(uint4 a, float4 w0, float4 w1) {
    const __half2* pa = (const __half2*)&a;
    float2 f0 = __half22float2(pa[0]);
    float2 f1 = __half22float2(pa[1]);
    float2 f2 = __half22float2(pa[2]);
    float2 f3 = __half22float2(pa[3]);
    return f0.x * w0.x + f0.y * w0.y + f1.x * w0.z + f1.y * w0.w +
           f2.x * w1.x + f2.y * w1.y + f3.x * w1.z + f3.y * w1.w;
}

// ---------------------------------------------------------------------------
// mma.sync GEMM: C[M,N] = A[M,K] @ B^T[N,K] + bias  (both fp16, fp32 accum)
// CTA tile 128x128, 8 warps (4m x 2n), warp tile 32x64, K-chunk 64,
// 4-stage cp.async pipeline. SMEM rows stride 144B (conflict-free).
// mode: 0 fp32; 1 fp32+ReLU; 2 fp16+ReLU; 3 fp16;
//       4 score-fused: relu(v+bias) dot ws2 -> partials Cf[row*8 + bn*2 + wn]
// ---------------------------------------------------------------------------
#define STAGES        4
#define ROW_STRIDE    144
#define MAT_BYTES     18432
#define STAGE_BYTES   36864
#define GEMM_SMEM     (STAGES * STAGE_BYTES)   // 147456

__global__ __launch_bounds__(256, 1)
void gemm_mma(const __half* __restrict__ A, const __half* __restrict__ B,
              const float* __restrict__ bias,
              float* __restrict__ Cf, __half* __restrict__ Ch,
              int N, int K, int mode, const float* __restrict__ ws2)
{
    extern __shared__ char smem[];
    const uint32_t sb = smem_u32(smem);
    const int tid  = threadIdx.x;
    const int lane = tid & 31;
    const int wid  = tid >> 5;
    const int wm   = wid & 3;
    const int wn   = wid >> 2;
    const int bn   = blockIdx.x;
    const int bm   = blockIdx.y;
    const int Kb   = K * 2;

    const char* gA = (const char*)(A + (size_t)bm * 128 * K);
    const char* gB = (const char*)(B + (size_t)bn * 128 * K);

    const int lr  = tid >> 1;
    const int lcb = (tid & 1) * 64;
    const size_t   goff = (size_t)lr * Kb + lcb;
    const uint32_t soff = (uint32_t)lr * ROW_STRIDE + lcb;

    float acc[2][8][4];
#pragma unroll
    for (int mi = 0; mi < 2; mi++)
#pragma unroll
        for (int ni = 0; ni < 8; ni++)
#pragma unroll
            for (int r = 0; r < 4; r++) acc[mi][ni][r] = 0.0f;

    const int nch = K >> 6;

#define LOAD_STAGE(stage, kc) do {                                        \
        uint32_t d = sb + (uint32_t)(stage) * STAGE_BYTES + soff;         \
        size_t   g = goff + (size_t)(kc) * 128;                           \
        CP16(d,                   gA + g);                                \
        CP16(d + 16,              gA + g + 16);                           \
        CP16(d + 32,              gA + g + 32);                           \
        CP16(d + 48,              gA + g + 48);                           \
        CP16(d + MAT_BYTES,       gB + g);                                \
        CP16(d + MAT_BYTES + 16,  gB + g + 16);                           \
        CP16(d + MAT_BYTES + 32,  gB + g + 32);                           \
        CP16(d + MAT_BYTES + 48,  gB + g + 48);                           \
    } while (0)

#pragma unroll
    for (int s = 0; s < STAGES - 1; s++) { LOAD_STAGE(s, s); CP_COMMIT(); }

    const uint32_t a_row  = (uint32_t)(wm * 32 + (lane & 15));
    const uint32_t a_coff = (uint32_t)((lane >> 4) * 16);
    const uint32_t b_row  = (uint32_t)(wn * 64 + ((lane >> 4) * 8) + (lane & 7));
    const uint32_t b_coff = (uint32_t)(((lane >> 3) & 1) * 16);

#pragma unroll 1
    for (int i = 0; i < nch; i++) {
        CP_WAIT(STAGES - 2);
        __syncthreads();

        int nxt = i + STAGES - 1;
        if (nxt < nch) LOAD_STAGE((nxt & (STAGES - 1)), nxt);
        CP_COMMIT();

        const uint32_t base = sb + (uint32_t)(i & (STAGES - 1)) * STAGE_BYTES;

#pragma unroll
        for (int kk = 0; kk < 4; kk++) {
            const uint32_t kb = kk * 32;
            uint32_t ar[2][4], br[8][2];
#pragma unroll
            for (int mi = 0; mi < 2; mi++) {
                uint32_t ad = base + (a_row + mi * 16) * ROW_STRIDE + kb + a_coff;
                LDSM4(ar[mi][0], ar[mi][1], ar[mi][2], ar[mi][3], ad);
            }
#pragma unroll
            for (int p = 0; p < 4; p++) {
                uint32_t bd = base + MAT_BYTES +
                              (b_row + p * 16) * ROW_STRIDE + kb + b_coff;
                uint32_t r0, r1, r2, r3;
                LDSM4(r0, r1, r2, r3, bd);
                br[2*p][0] = r0;   br[2*p][1] = r1;
                br[2*p+1][0] = r2; br[2*p+1][1] = r3;
            }
#pragma unroll
            for (int mi = 0; mi < 2; mi++)
#pragma unroll
                for (int ni = 0; ni < 8; ni++)
                    MMAH(acc[mi][ni], ar[mi][0], ar[mi][1], ar[mi][2], ar[mi][3],
                         br[ni][0], br[ni][1]);
        }
    }
#undef LOAD_STAGE

    // epilogue
    const int row0 = bm * 128 + wm * 32 + (lane >> 2);
    const int col0 = bn * 128 + wn * 64 + (lane & 3) * 2;

#pragma unroll
    for (int mi = 0; mi < 2; mi++) {
        float s0 = 0.f, s1 = 0.f;   // mode-4 row partial sums
#pragma unroll
        for (int ni = 0; ni < 8; ni++) {
            const int r = row0 + mi * 16;
            const int c = col0 + ni * 8;
            const float b0 = __ldg(bias + c);
            const float b1 = __ldg(bias + c + 1);
            float v00 = acc[mi][ni][0] + b0;
            float v01 = acc[mi][ni][1] + b1;
            float v10 = acc[mi][ni][2] + b0;
            float v11 = acc[mi][ni][3] + b1;
            if (mode == 1 || mode == 2 || mode == 4) {
                v00 = fmaxf(v00, 0.0f); v01 = fmaxf(v01, 0.0f);
                v10 = fmaxf(v10, 0.0f); v11 = fmaxf(v11, 0.0f);
            }
            if (mode == 4) {
                const float w0 = __ldg(ws2 + c);
                const float w1 = __ldg(ws2 + c + 1);
                s0 += v00 * w0 + v01 * w1;
                s1 += v10 * w0 + v11 * w1;
            } else if (mode >= 2) {
                __half2 h0 = __floats2half2_rn(v00, v01);
                __half2 h1 = __floats2half2_rn(v10, v11);
                *(__half2*)(Ch + (size_t)r * N + c)       = h0;
                *(__half2*)(Ch + (size_t)(r + 8) * N + c) = h1;
            } else {
                *(float2*)(Cf + (size_t)r * N + c)       = make_float2(v00, v01);
                *(float2*)(Cf + (size_t)(r + 8) * N + c) = make_float2(v10, v11);
            }
        }
        if (mode == 4) {
            // reduce over the 4 lanes sharing this row (lane&3 varies cols)
            s0 += __shfl_xor_sync(0xffffffffu, s0, 1);
            s0 += __shfl_xor_sync(0xffffffffu, s0, 2);
            s1 += __shfl_xor_sync(0xffffffffu, s1, 1);
            s1 += __shfl_xor_sync(0xffffffffu, s1, 2);
            if ((lane & 3) == 0) {
                const int r = row0 + mi * 16;
                Cf[(size_t)r * 8 + bn * 2 + wn]       = s0;
                Cf[(size_t)(r + 8) * 8 + bn * 2 + wn] = s1;
            }
        }
    }
}

// ---------------------------------------------------------------------------
// fp32 -> fp16 convert (elementwise)
// ---------------------------------------------------------------------------
__global__ __launch_bounds__(256)
void cvt_kernel(const float* __restrict__ in, __half* __restrict__ out, size_t n4)
{
    size_t i = (size_t)blockIdx.x * 256 + threadIdx.x;
    if (i >= n4) return;
    float4 v = ((const float4*)in)[i];
    __half2 h0 = __floats2half2_rn(v.x, v.y);
    __half2 h1 = __floats2half2_rn(v.z, v.w);
    uint2 o;
    o.x = *(uint32_t*)&h0;
    o.y = *(uint32_t*)&h1;
    ((uint2*)out)[i] = o;
}

// ---------------------------------------------------------------------------
// weight transpose + fp16 convert: W[K,N] -> Wt[N,K]
// ---------------------------------------------------------------------------
__global__ __launch_bounds__(256)
void wcvt_kernel(const float* __restrict__ W, __half* __restrict__ t,
                 int K, int N)
{
    int idx = blockIdx.x * 256 + threadIdx.x;
    if (idx >= K * N) return;
    int n = idx / K, k = idx - n * K;
    t[idx] = __float2half_rn(W[(size_t)k * N + n]);
}

// ---------------------------------------------------------------------------
// Build uv bias (zeros | bv); also prep for attention bias correction:
// w_a[i] = sum_o wq[i,o]*bk[o]; w_b[j] = sum_o wk[j,o]*bq[o]; gamma = bq.bk
// ---------------------------------------------------------------------------
__global__ __launch_bounds__(128)
void prep_kernel(const float* __restrict__ wq, const float* __restrict__ wk,
                 const float* __restrict__ bq, const float* __restrict__ bk,
                 const float* __restrict__ bv,
                 float* __restrict__ w_a, float* __restrict__ w_b,
                 float* __restrict__ gamma, float* __restrict__ buv)
{
    int i = blockIdx.x * 128 + threadIdx.x;   // 0..511 over grid 4
    float sa = 0.f, sb = 0.f;
    for (int o = 0; o < 512; o++) {
        sa += wq[(size_t)i * 512 + o] * bk[o];
        sb += wk[(size_t)i * 512 + o] * bq[o];
    }
    w_a[i] = sa;
    w_b[i] = sb;
    buv[i] = 0.f;
    buv[512 + i] = bv[i];
    if (blockIdx.x == 0) {
        float gsum = 0.f;
        for (int o = threadIdx.x; o < 512; o += 128) gsum += bq[o] * bk[o];
        gsum = warp_sum(gsum);
        __shared__ float sm[4];
        if ((threadIdx.x & 31) == 0) sm[threadIdx.x >> 5] = gsum;
        __syncthreads();
        if (threadIdx.x == 0) gamma[0] = sm[0] + sm[1] + sm[2] + sm[3];
    }
}

// ---------------------------------------------------------------------------
// Attention for N=2 (one warp per sample).
// uv fp16 [T,1024] (u|v); s_nm = u_n.x_m + a_n + b_m + gamma
// ---------------------------------------------------------------------------
__global__ __launch_bounds__(256)
void attn_kernel(const __half* __restrict__ uv, const __half* __restrict__ xh,
                 const float* __restrict__ w_a, const float* __restrict__ w_b,
                 const float* __restrict__ gamma_p, __half* __restrict__ oh)
{
    int gw   = (blockIdx.x * 256 + threadIdx.x) >> 5;
    int lane = threadIdx.x & 31;
    if (gw >= B_) return;

    const __half* ub = uv + (size_t)gw * 2048;
    const uint4* u0 = (const uint4*)(ub);
    const uint4* u1 = (const uint4*)(ub + 1024);
    const uint4* v0 = (const uint4*)(ub + 512);
    const uint4* v1 = (const uint4*)(ub + 1536);
    const __half* xb = xh + (size_t)gw * 1024;
    const uint4* x0 = (const uint4*)(xb);
    const uint4* x1 = (const uint4*)(xb + 512);
    const float4* wa4 = (const float4*)w_a;
    const float4* wb4 = (const float4*)w_b;

    float s00 = 0.f, s01 = 0.f, s10 = 0.f, s11 = 0.f;
    float a0s = 0.f, a1s = 0.f, b0s = 0.f, b1s = 0.f;
#pragma unroll
    for (int r = 0; r < 2; r++) {
        int i = lane + 32 * r;
        uint4 uu0 = u0[i], uu1 = u1[i], xx0 = x0[i], xx1 = x1[i];
        s00 += dot8(uu0, xx0);
        s01 += dot8(uu0, xx1);
        s10 += dot8(uu1, xx0);
        s11 += dot8(uu1, xx1);
        float4 wa0 = wa4[2 * i], wa1 = wa4[2 * i + 1];
        float4 wb0 = wb4[2 * i], wb1 = wb4[2 * i + 1];
        a0s += dot8f(xx0, wa0, wa1);
        a1s += dot8f(xx1, wa0, wa1);
        b0s += dot8f(xx0, wb0, wb1);
        b1s += dot8f(xx1, wb0, wb1);
    }
    s00 = warp_sum(s00); s01 = warp_sum(s01);
    s10 = warp_sum(s10); s11 = warp_sum(s11);
    a0s = warp_sum(a0s); a1s = warp_sum(a1s);
    b0s = warp_sum(b0s); b1s = warp_sum(b1s);

    const float gmm = gamma_p[0];
    s00 += a0s + b0s + gmm;
    s01 += a0s + b1s + gmm;
    s10 += a1s + b0s + gmm;
    s11 += a1s + b1s + gmm;

    const float inv_scale = 1.0f / 22.627416997969522f;
    s00 *= inv_scale; s01 *= inv_scale; s10 *= inv_scale; s11 *= inv_scale;
    s00 = s00 > 0.f ? s00 : 0.2f * s00;
    s01 = s01 > 0.f ? s01 : 0.2f * s01;
    s10 = s10 > 0.f ? s10 : 0.2f * s10;
    s11 = s11 > 0.f ? s11 : 0.2f * s11;

    float m0 = fmaxf(s00, s01), m1 = fmaxf(s10, s11);
    float e00 = expf(s00 - m0), e01 = expf(s01 - m0);
    float e10 = expf(s10 - m1), e11 = expf(s11 - m1);
    float i0 = 1.0f / (e00 + e01), i1 = 1.0f / (e10 + e11);
    float a00 = e00 * i0, a01 = e01 * i0;
    float a10 = e10 * i1, a11 = e11 * i1;

    uint4* o0 = (uint4*)(oh + (size_t)gw * 2 * D_);
    uint4* o1 = o0 + D_ / 8;

#pragma unroll
    for (int r = 0; r < 2; r++) {
        int i = lane + 32 * r;
        uint4 xv0 = v0[i], xv1 = v1[i];
        const __half2* p0 = (const __half2*)&xv0;
        const __half2* p1 = (const __half2*)&xv1;
        uint4 r0, r1;
        __half2* q0o = (__half2*)&r0;
        __half2* q1o = (__half2*)&r1;
#pragma unroll
        for (int j = 0; j < 4; j++) {
            float2 f0 = __half22float2(p0[j]);
            float2 f1 = __half22float2(p1[j]);
            q0o[j] = __floats2half2_rn(a00 * f0.x + a01 * f1.x,
                                       a00 * f0.y + a01 * f1.y);
            q1o[j] = __floats2half2_rn(a10 * f0.x + a11 * f1.x,
                                       a10 * f0.y + a11 * f1.y);
        }
        o0[i] = r0;
        o1[i] = r1;
    }
}

// ---------------------------------------------------------------------------
// out = LayerNorm(A + P) * g + be ; A fp32, P fp16; fp32 out + fp16 copy
// ---------------------------------------------------------------------------
__global__ __launch_bounds__(128)
void add_ln_kernel(const float* __restrict__ A, const __half* __restrict__ P,
                   const float* __restrict__ g, const float* __restrict__ be,
                   float* __restrict__ out, __half* __restrict__ oh)
{
    size_t row = blockIdx.x;
    int t = threadIdx.x;

    float4 av = ((const float4*)(A + row * D_))[t];
    uint2  pu = ((const uint2*)(P + row * D_))[t];
    __half2 ph0 = *(__half2*)&pu.x;
    __half2 ph1 = *(__half2*)&pu.y;
    float2 p0 = __half22float2(ph0);
    float2 p1 = __half22float2(ph1);
    float4 s;
    s.x = av.x + p0.x; s.y = av.y + p0.y; s.z = av.z + p1.x; s.w = av.w + p1.y;

    float sum = s.x + s.y + s.z + s.w;
    float sq  = s.x * s.x + s.y * s.y + s.z * s.z + s.w * s.w;
    sum = warp_sum(sum);
    sq  = warp_sum(sq);

    __shared__ float sm[8];
    int w = t >> 5;
    if ((t & 31) == 0) { sm[w] = sum; sm[4 + w] = sq; }
    __syncthreads();
    float ts = sm[0] + sm[1] + sm[2] + sm[3];
    float tq = sm[4] + sm[5] + sm[6] + sm[7];

    float mu  = ts * (1.0f / D_);
    float var = tq * (1.0f / D_) - mu * mu;
    float rs  = rsqrtf(var + 1e-5f);

    float4 G  = ((const float4*)g)[t];
    float4 Be = ((const float4*)be)[t];
    float4 o;
    o.x = (s.x - mu) * rs * G.x + Be.x;
    o.y = (s.y - mu) * rs * G.y + Be.y;
    o.z = (s.z - mu) * rs * G.z + Be.z;
    o.w = (s.w - mu) * rs * G.w + Be.w;
    ((float4*)(out + row * D_))[t] = o;

    __half2 h0 = __floats2half2_rn(o.x, o.y);
    __half2 h1 = __floats2half2_rn(o.z, o.w);
    uint2 u;
    u.x = *(uint32_t*)&h0;
    u.y = *(uint32_t*)&h1;
    ((uint2*)(oh + row * D_))[t] = u;
}

// ---------------------------------------------------------------------------
// Final stage: sum score partials, softmax over N=2, pooling, param-free LN.
// (bs2 shifts both scores equally -> cancels in softmax.)
// ---------------------------------------------------------------------------
__global__ __launch_bounds__(256)
void final_kernel(const float* __restrict__ sp, const float* __restrict__ refined,
                  float* __restrict__ fused, float* __restrict__ alpha)
{
    int gw   = (blockIdx.x * 256 + threadIdx.x) >> 5;
    int lane = threadIdx.x & 31;
    if (gw >= B_) return;

    // 16 partials: rows gw*2, gw*2+1, 8 each
    float v = (lane < 16) ? sp[(size_t)gw * 16 + lane] : 0.f;
    v += __shfl_xor_sync(0xffffffffu, v, 1);
    v += __shfl_xor_sync(0xffffffffu, v, 2);
    v += __shfl_xor_sync(0xffffffffu, v, 4);
    float d0 = __shfl_sync(0xffffffffu, v, 0);
    float d1 = __shfl_sync(0xffffffffu, v, 8);

    float m  = fmaxf(d0, d1);
    float e0 = expf(d0 - m), e1 = expf(d1 - m);
    float inv = 1.0f / (e0 + e1);
    float a0 = e0 * inv, a1 = e1 * inv;
    if (lane == 0) {
        alpha[(size_t)gw * 2 + 0] = a0;
        alpha[(size_t)gw * 2 + 1] = a1;
    }

    const float4* f0 = (const float4*)(refined + (size_t)gw * 2 * D_);
    const float4* f1 = f0 + D_ / 4;

    float4 fr[4];
    float sum = 0.f, sq = 0.f;
#pragma unroll
    for (int r = 0; r < 4; r++) {
        int i = lane + 32 * r;
        float4 x0 = f0[i], x1 = f1[i];
        float4 t;
        t.x = a0 * x0.x + a1 * x1.x;  t.y = a0 * x0.y + a1 * x1.y;
        t.z = a0 * x0.z + a1 * x1.z;  t.w = a0 * x0.w + a1 * x1.w;
        fr[r] = t;
        sum += t.x + t.y + t.z + t.w;
        sq  += t.x * t.x + t.y * t.y + t.z * t.z + t.w * t.w;
    }
    sum = warp_sum(sum);
    sq  = warp_sum(sq);
    float mu  = sum * (1.0f / D_);
    float var = sq * (1.0f / D_) - mu * mu;
    float rs  = rsqrtf(var + 1e-5f);

    float4* fo = (float4*)(fused + (size_t)gw * D_);
#pragma unroll
    for (int r = 0; r < 4; r++) {
        int i = lane + 32 * r;
        float4 t = fr[r];
        float4 o;
        o.x = (t.x - mu) * rs;  o.y = (t.y - mu) * rs;
        o.z = (t.z - mu) * rs;  o.w = (t.w - mu) * rs;
        fo[i] = o;
    }
}

// ---------------------------------------------------------------------------
// Launch
// ---------------------------------------------------------------------------
extern "C" void kernel_launch(void* const* d_in, const int* in_sizes, int n_in,
                              void* d_out, int out_size)
{
    const float* x   = (const float*)d_in[0];
    const float* wq  = (const float*)d_in[1];
    const float* bq  = (const float*)d_in[2];
    const float* wk  = (const float*)d_in[3];
    const float* bk  = (const float*)d_in[4];
    const float* wv  = (const float*)d_in[5];
    const float* bv  = (const float*)d_in[6];
    const float* wo  = (const float*)d_in[7];
    const float* bo  = (const float*)d_in[8];
    const float* g1  = (const float*)d_in[9];
    const float* be1 = (const float*)d_in[10];
    const float* wf1 = (const float*)d_in[11];
    const float* bf1 = (const float*)d_in[12];
    const float* wf2 = (const float*)d_in[13];
    const float* bf2 = (const float*)d_in[14];
    const float* g2  = (const float*)d_in[15];
    const float* be2 = (const float*)d_in[16];
    const float* ws1 = (const float*)d_in[17];
    const float* bs1 = (const float*)d_in[18];
    const float* ws2 = (const float*)d_in[19];

    float *h, *sp, *buv, *wa, *wb, *gma;
    __half *uv, *xh, *ah, *hh, *rh, *ph, *fh, *wt, *wq16, *wk16;
    cudaGetSymbolAddress((void**)&uv, g_uv);
    cudaGetSymbolAddress((void**)&h, g_h);
    cudaGetSymbolAddress((void**)&sp, g_sp);
    cudaGetSymbolAddress((void**)&buv, g_buv);
    cudaGetSymbolAddress((void**)&wa, g_wa);
    cudaGetSymbolAddress((void**)&wb, g_wb);
    cudaGetSymbolAddress((void**)&gma, g_gamma);
    cudaGetSymbolAddress((void**)&xh, g_xh);
    cudaGetSymbolAddress((void**)&ah, g_ah);
    cudaGetSymbolAddress((void**)&hh, g_hh);
    cudaGetSymbolAddress((void**)&rh, g_rh);
    cudaGetSymbolAddress((void**)&ph, g_ph);
    cudaGetSymbolAddress((void**)&fh, g_fh);
    cudaGetSymbolAddress((void**)&wt, g_wt);
    cudaGetSymbolAddress((void**)&wq16, g_wq16);
    cudaGetSymbolAddress((void**)&wk16, g_wk16);

    cudaFuncSetAttribute(gemm_mma, cudaFuncAttributeMaxDynamicSharedMemorySize,
                         GEMM_SMEM);

    float* out     = (float*)d_out;
    float* fused   = out;
    float* alpha   = out + (size_t)B_ * D_;
    float* refined = alpha + (size_t)B_ * N_;

    dim3 blk(256);

    // preprocessing
    cvt_kernel<<<(unsigned)(TD_ / 4 / 256), 256>>>(x, xh, TD_ / 4);
    cvt_kernel<<<256, 256>>>(wq, wq16, 262144 / 4);      // row-major fp16 wq
    cvt_kernel<<<256, 256>>>(wk, wk16, 262144 / 4);      // row-major fp16 wk
    wcvt_kernel<<<1024, 256>>>(wv,  wt + WV_OFF,  512, 512);
    wcvt_kernel<<<1024, 256>>>(wo,  wt + WO_OFF,  512, 512);
    wcvt_kernel<<<2048, 256>>>(wf1, wt + WF1_OFF, 512, 1024);
    wcvt_kernel<<<2048, 256>>>(wf2, wt + WF2_OFF, 1024, 512);
    wcvt_kernel<<<1024, 256>>>(ws1, wt + WS1_OFF, 512, 512);
    prep_kernel<<<4, 128>>>(wq, wk, bq, bk, bv, wa, wb, gma, buv);

    // Mt[j,i] = sum_o wk[j,o] * wq[i,o]  (fp16 out at wt+WK_OFF, bias=zeros)
    gemm_mma<<<dim3(4, 4), blk, GEMM_SMEM>>>(wk16, wq16, buv, nullptr,
                                             wt + WK_OFF, 512, 512, 3, nullptr);

    // uv = xh @ [Mt | WvT]^T + (0|bv)  -> fp16 [T, 1024]
    gemm_mma<<<dim3(8, T_ / 128), blk, GEMM_SMEM>>>(xh, wt + WK_OFF, buv,
                                                    nullptr, uv, 1024, 512, 3, nullptr);
    // attention -> fp16
    attn_kernel<<<B_ / 8, 256>>>(uv, xh, wa, wb, gma, ah);
    // output projection (fp16 out) + residual LN1
    gemm_mma<<<dim3(4, T_ / 128), blk, GEMM_SMEM>>>(ah, wt + WO_OFF, bo,
                                                    nullptr, ph, 512, 512, 3, nullptr);
    add_ln_kernel<<<T_, 128>>>(x, ph, g1, be1, h, hh);
    // FFN
    gemm_mma<<<dim3(8, T_ / 128), blk, GEMM_SMEM>>>(hh, wt + WF1_OFF, bf1,
                                                    nullptr, fh, 1024, 512, 2, nullptr);
    gemm_mma<<<dim3(4, T_ / 128), blk, GEMM_SMEM>>>(fh, wt + WF2_OFF, bf2,
                                                    nullptr, ph, 512, 1024, 3, nullptr);
    add_ln_kernel<<<T_, 128>>>(h, ph, g2, be2, refined, rh);
    // score MLP fused: partials = relu(refined@ws1 + bs1) . ws2
    gemm_mma<<<dim3(4, T_ / 128), blk, GEMM_SMEM>>>(rh, wt + WS1_OFF, bs1,
                                                    sp, nullptr, 512, 512, 4, ws2);
    // softmax + pooling + final LN
    final_kernel<<<B_ / 8, 256>>>(sp, refined, fused, alpha);
}

// round 8
// speedup vs baseline: 4.7540x; 1.1178x over previous
#include <cuda_runtime.h>
#include <cuda_fp16.h>
#include <cstdint>

// ---------------------------------------------------------------------------
// Problem constants
// ---------------------------------------------------------------------------
#define B_   65536
#define N_   2
#define D_   512
#define T_   (B_ * N_)          // 131072 tokens
#define TD_  ((size_t)T_ * D_)  // 67,108,864

// ---------------------------------------------------------------------------
// Scratch (static __device__ arrays)
// ---------------------------------------------------------------------------
__device__ __half g_uv[2 * TD_];   // [T, 1024]: u | v'  (v' = x@Wvo + bvo)
__device__ float  g_h[TD_];
__device__ float  g_sp[(size_t)T_ * 8];  // score partials [T, 8]
__device__ float  g_buv[1024];     // bias for uv GEMM: zeros | bvo
__device__ float  g_wa[512], g_wb[512], g_gamma[1];

__device__ __half g_xh[TD_];
__device__ __half g_hh[TD_];
__device__ __half g_rh[TD_];
__device__ __half g_ph[TD_];       // fp16 GEMM intermediate (pre-LN2)
__device__ __half g_fh[2 * TD_];
__device__ __half g_wq16[262144], g_wk16[262144], g_wv16[262144]; // row-major fp16

// transposed fp16 weights, [N,K] layout
#define WK_OFF  262144   // Mt lives here; contiguous with WVO for fused uv GEMM
#define WVO_OFF 524288   // Wvo_t lives here
#define WO_OFF  786432   // wo_t (used only to build Wvo_t)
#define WF1_OFF 1048576
#define WF2_OFF 1572864
#define WS1_OFF 2097152
__device__ __half g_wt[2359296];

// ---------------------------------------------------------------------------
// PTX helpers (baseline sm_80+)
// ---------------------------------------------------------------------------
__device__ __forceinline__ uint32_t smem_u32(const void* smem_ptr) {
    uint32_t addr;
    asm("{ .reg .u64 tmp; cvta.to.shared.u64 tmp, %1; cvt.u32.u64 %0, tmp; }"
        : "=r"(addr) : "l"(smem_ptr));
    return addr;
}

#define CP16(dst, src) \
    asm volatile("cp.async.cg.shared.global [%0], [%1], 16;" \
        :: "r"(dst), "l"(src))

#define CP_COMMIT() asm volatile("cp.async.commit_group;" ::: "memory")
#define CP_WAIT(n)  asm volatile("cp.async.wait_group %0;" :: "n"(n) : "memory")

#define LDSM4(r0, r1, r2, r3, a) \
    asm volatile("ldmatrix.sync.aligned.m8n8.x4.shared.b16 {%0,%1,%2,%3}, [%4];" \
        : "=r"(r0), "=r"(r1), "=r"(r2), "=r"(r3) : "r"(a))

#define MMAH(d, a0, a1, a2, a3, b0, b1) \
    asm volatile("mma.sync.aligned.m16n8k16.row.col.f32.f16.f16.f32 " \
        "{%0,%1,%2,%3}, {%4,%5,%6,%7}, {%8,%9}, {%0,%1,%2,%3};" \
        : "+f"((d)[0]), "+f"((d)[1]), "+f"((d)[2]), "+f"((d)[3]) \
        : "r"(a0), "r"(a1), "r"(a2), "r"(a3), "r"(b0), "r"(b1))

__device__ __forceinline__ float warp_sum(float v) {
#pragma unroll
    for (int o = 16; o; o >>= 1) v += __shfl_xor_sync(0xffffffffu, v, o);
    return v;
}

// dot of 8 fp16 (uint4) with 8 fp32 (two float4)
__device__ __forceinline__ float dot8f(uint4 a, float4 w0, float4 w1) {
    const __half2* pa = (const __half2*)&a;
    float2 f0 = __half22float2(pa[0]);
    float2 f1 = __half22float2(pa[1]);
    float2 f2 = __half22float2(pa[2]);
    float2 f3 = __half22float2(pa[3]);
    return f0.x * w0.x + f0.y * w0.y + f1.x * w0.z + f1.y * w0.w +
           f2.x * w1.x + f2.y * w1.y + f3.x * w1.z + f3.y * w1.w;
}

// dot of two float4 pairs
__device__ __forceinline__ float dot8ff(float4 a0, float4 a1, float4 b0, float4 b1) {
    return a0.x * b0.x + a0.y * b0.y + a0.z * b0.z + a0.w * b0.w +
           a1.x * b1.x + a1.y * b1.y + a1.z * b1.z + a1.w * b1.w;
}

// ---------------------------------------------------------------------------
// mma.sync GEMM: C[M,N] = A[M,K] @ B^T[N,K] + bias  (both fp16, fp32 accum)
// CTA tile 128x128, 8 warps (4m x 2n), warp tile 32x64, K-chunk 64,
// 4-stage cp.async pipeline. SMEM rows stride 144B (conflict-free).
// mode: 0 fp32; 1 fp32+ReLU; 2 fp16+ReLU; 3 fp16;
//       4 score-fused: relu(v+bias) dot ws2 -> partials Cf[row*8 + bn*2 + wn]
// ---------------------------------------------------------------------------
#define STAGES        4
#define ROW_STRIDE    144
#define MAT_BYTES     18432
#define STAGE_BYTES   36864
#define GEMM_SMEM     (STAGES * STAGE_BYTES)   // 147456

__global__ __launch_bounds__(256, 1)
void gemm_mma(const __half* __restrict__ A, const __half* __restrict__ B,
              const float* __restrict__ bias,
              float* __restrict__ Cf, __half* __restrict__ Ch,
              int N, int K, int mode, const float* __restrict__ ws2)
{
    extern __shared__ char smem[];
    const uint32_t sb = smem_u32(smem);
    const int tid  = threadIdx.x;
    const int lane = tid & 31;
    const int wid  = tid >> 5;
    const int wm   = wid & 3;
    const int wn   = wid >> 2;
    const int bn   = blockIdx.x;
    const int bm   = blockIdx.y;
    const int Kb   = K * 2;

    const char* gA = (const char*)(A + (size_t)bm * 128 * K);
    const char* gB = (const char*)(B + (size_t)bn * 128 * K);

    const int lr  = tid >> 1;
    const int lcb = (tid & 1) * 64;
    const size_t   goff = (size_t)lr * Kb + lcb;
    const uint32_t soff = (uint32_t)lr * ROW_STRIDE + lcb;

    float acc[2][8][4];
#pragma unroll
    for (int mi = 0; mi < 2; mi++)
#pragma unroll
        for (int ni = 0; ni < 8; ni++)
#pragma unroll
            for (int r = 0; r < 4; r++) acc[mi][ni][r] = 0.0f;

    const int nch = K >> 6;

#define LOAD_STAGE(stage, kc) do {                                        \
        uint32_t d = sb + (uint32_t)(stage) * STAGE_BYTES + soff;         \
        size_t   g = goff + (size_t)(kc) * 128;                           \
        CP16(d,                   gA + g);                                \
        CP16(d + 16,              gA + g + 16);                           \
        CP16(d + 32,              gA + g + 32);                           \
        CP16(d + 48,              gA + g + 48);                           \
        CP16(d + MAT_BYTES,       gB + g);                                \
        CP16(d + MAT_BYTES + 16,  gB + g + 16);                           \
        CP16(d + MAT_BYTES + 32,  gB + g + 32);                           \
        CP16(d + MAT_BYTES + 48,  gB + g + 48);                           \
    } while (0)

#pragma unroll
    for (int s = 0; s < STAGES - 1; s++) { LOAD_STAGE(s, s); CP_COMMIT(); }

    const uint32_t a_row  = (uint32_t)(wm * 32 + (lane & 15));
    const uint32_t a_coff = (uint32_t)((lane >> 4) * 16);
    const uint32_t b_row  = (uint32_t)(wn * 64 + ((lane >> 4) * 8) + (lane & 7));
    const uint32_t b_coff = (uint32_t)(((lane >> 3) & 1) * 16);

#pragma unroll 1
    for (int i = 0; i < nch; i++) {
        CP_WAIT(STAGES - 2);
        __syncthreads();

        int nxt = i + STAGES - 1;
        if (nxt < nch) LOAD_STAGE((nxt & (STAGES - 1)), nxt);
        CP_COMMIT();

        const uint32_t base = sb + (uint32_t)(i & (STAGES - 1)) * STAGE_BYTES;

#pragma unroll
        for (int kk = 0; kk < 4; kk++) {
            const uint32_t kb = kk * 32;
            uint32_t ar[2][4], br[8][2];
#pragma unroll
            for (int mi = 0; mi < 2; mi++) {
                uint32_t ad = base + (a_row + mi * 16) * ROW_STRIDE + kb + a_coff;
                LDSM4(ar[mi][0], ar[mi][1], ar[mi][2], ar[mi][3], ad);
            }
#pragma unroll
            for (int p = 0; p < 4; p++) {
                uint32_t bd = base + MAT_BYTES +
                              (b_row + p * 16) * ROW_STRIDE + kb + b_coff;
                uint32_t r0, r1, r2, r3;
                LDSM4(r0, r1, r2, r3, bd);
                br[2*p][0] = r0;   br[2*p][1] = r1;
                br[2*p+1][0] = r2; br[2*p+1][1] = r3;
            }
#pragma unroll
            for (int mi = 0; mi < 2; mi++)
#pragma unroll
                for (int ni = 0; ni < 8; ni++)
                    MMAH(acc[mi][ni], ar[mi][0], ar[mi][1], ar[mi][2], ar[mi][3],
                         br[ni][0], br[ni][1]);
        }
    }
#undef LOAD_STAGE

    // epilogue
    const int row0 = bm * 128 + wm * 32 + (lane >> 2);
    const int col0 = bn * 128 + wn * 64 + (lane & 3) * 2;

#pragma unroll
    for (int mi = 0; mi < 2; mi++) {
        float s0 = 0.f, s1 = 0.f;
#pragma unroll
        for (int ni = 0; ni < 8; ni++) {
            const int r = row0 + mi * 16;
            const int c = col0 + ni * 8;
            const float b0 = __ldg(bias + c);
            const float b1 = __ldg(bias + c + 1);
            float v00 = acc[mi][ni][0] + b0;
            float v01 = acc[mi][ni][1] + b1;
            float v10 = acc[mi][ni][2] + b0;
            float v11 = acc[mi][ni][3] + b1;
            if (mode == 1 || mode == 2 || mode == 4) {
                v00 = fmaxf(v00, 0.0f); v01 = fmaxf(v01, 0.0f);
                v10 = fmaxf(v10, 0.0f); v11 = fmaxf(v11, 0.0f);
            }
            if (mode == 4) {
                const float w0 = __ldg(ws2 + c);
                const float w1 = __ldg(ws2 + c + 1);
                s0 += v00 * w0 + v01 * w1;
                s1 += v10 * w0 + v11 * w1;
            } else if (mode >= 2) {
                __half2 h0 = __floats2half2_rn(v00, v01);
                __half2 h1 = __floats2half2_rn(v10, v11);
                *(__half2*)(Ch + (size_t)r * N + c)       = h0;
                *(__half2*)(Ch + (size_t)(r + 8) * N + c) = h1;
            } else {
                *(float2*)(Cf + (size_t)r * N + c)       = make_float2(v00, v01);
                *(float2*)(Cf + (size_t)(r + 8) * N + c) = make_float2(v10, v11);
            }
        }
        if (mode == 4) {
            s0 += __shfl_xor_sync(0xffffffffu, s0, 1);
            s0 += __shfl_xor_sync(0xffffffffu, s0, 2);
            s1 += __shfl_xor_sync(0xffffffffu, s1, 1);
            s1 += __shfl_xor_sync(0xffffffffu, s1, 2);
            if ((lane & 3) == 0) {
                const int r = row0 + mi * 16;
                Cf[(size_t)r * 8 + bn * 2 + wn]       = s0;
                Cf[(size_t)(r + 8) * 8 + bn * 2 + wn] = s1;
            }
        }
    }
}

// ---------------------------------------------------------------------------
// fp32 -> fp16 convert (elementwise)
// ---------------------------------------------------------------------------
__global__ __launch_bounds__(256)
void cvt_kernel(const float* __restrict__ in, __half* __restrict__ out, size_t n4)
{
    size_t i = (size_t)blockIdx.x * 256 + threadIdx.x;
    if (i >= n4) return;
    float4 v = ((const float4*)in)[i];
    __half2 h0 = __floats2half2_rn(v.x, v.y);
    __half2 h1 = __floats2half2_rn(v.z, v.w);
    uint2 o;
    o.x = *(uint32_t*)&h0;
    o.y = *(uint32_t*)&h1;
    ((uint2*)out)[i] = o;
}

// ---------------------------------------------------------------------------
// weight transpose + fp16 convert: W[K,N] -> Wt[N,K]
// ---------------------------------------------------------------------------
__global__ __launch_bounds__(256)
void wcvt_kernel(const float* __restrict__ W, __half* __restrict__ t,
                 int K, int N)
{
    int idx = blockIdx.x * 256 + threadIdx.x;
    if (idx >= K * N) return;
    int n = idx / K, k = idx - n * K;
    t[idx] = __float2half_rn(W[(size_t)k * N + n]);
}

// ---------------------------------------------------------------------------
// prep: attention bias terms + uv GEMM bias (zeros | bvo)
// w_a[i] = wq[i,:].bk; w_b[j] = wk[j,:].bq; gamma = bq.bk
// bvo[n] = bv . wo[:,n] + bo[n]
// ---------------------------------------------------------------------------
__global__ __launch_bounds__(128)
void prep_kernel(const float* __restrict__ wq, const float* __restrict__ wk,
                 const float* __restrict__ bq, const float* __restrict__ bk,
                 const float* __restrict__ bv, const float* __restrict__ wo,
                 const float* __restrict__ bo,
                 float* __restrict__ w_a, float* __restrict__ w_b,
                 float* __restrict__ gamma, float* __restrict__ buv)
{
    int i = blockIdx.x * 128 + threadIdx.x;   // 0..511 over grid 4
    float sa = 0.f, sb = 0.f, so = 0.f;
    for (int o = 0; o < 512; o++) {
        sa += wq[(size_t)i * 512 + o] * bk[o];
        sb += wk[(size_t)i * 512 + o] * bq[o];
        so += bv[o] * wo[(size_t)o * 512 + i];
    }
    w_a[i] = sa;
    w_b[i] = sb;
    buv[i] = 0.f;
    buv[512 + i] = so + bo[i];
    if (blockIdx.x == 0) {
        float gsum = 0.f;
        for (int o = threadIdx.x; o < 512; o += 128) gsum += bq[o] * bk[o];
        gsum = warp_sum(gsum);
        __shared__ float sm[4];
        if ((threadIdx.x & 31) == 0) sm[threadIdx.x >> 5] = gsum;
        __syncthreads();
        if (threadIdx.x == 0) gamma[0] = sm[0] + sm[1] + sm[2] + sm[3];
    }
}

// ---------------------------------------------------------------------------
// Fused attention + residual + LN1 (one warp per sample).
// uv fp16 [T,1024] (u|v'); s_nm = u_n.x_m + a_n + b_m + gamma.
// h = LN(x + attn@v') * g1 + be1 ; writes h fp32 and hh fp16.
// ---------------------------------------------------------------------------
__global__ __launch_bounds__(256)
void attn_ln_kernel(const __half* __restrict__ uv, const float* __restrict__ x,
                    const float* __restrict__ w_a, const float* __restrict__ w_b,
                    const float* __restrict__ gamma_p,
                    const float* __restrict__ g1, const float* __restrict__ be1,
                    float* __restrict__ hout, __half* __restrict__ hh)
{
    int gw   = (blockIdx.x * 256 + threadIdx.x) >> 5;
    int lane = threadIdx.x & 31;
    if (gw >= B_) return;

    const __half* ub = uv + (size_t)gw * 2048;
    const uint4* u0 = (const uint4*)(ub);
    const uint4* u1 = (const uint4*)(ub + 1024);
    const uint4* v0 = (const uint4*)(ub + 512);
    const uint4* v1 = (const uint4*)(ub + 1536);
    const float4* xb = (const float4*)(x + (size_t)gw * 1024);
    const float4* wa4 = (const float4*)w_a;
    const float4* wb4 = (const float4*)w_b;

    // load x rows: per lane, 2 uint4-equivalents per row (8 floats each)
    float4 xr0[2][2], xr1[2][2];
#pragma unroll
    for (int r = 0; r < 2; r++) {
        int i = lane + 32 * r;
        xr0[r][0] = xb[2 * i];
        xr0[r][1] = xb[2 * i + 1];
        xr1[r][0] = xb[128 + 2 * i];
        xr1[r][1] = xb[128 + 2 * i + 1];
    }

    float s00 = 0.f, s01 = 0.f, s10 = 0.f, s11 = 0.f;
    float a0s = 0.f, a1s = 0.f, b0s = 0.f, b1s = 0.f;
#pragma unroll
    for (int r = 0; r < 2; r++) {
        int i = lane + 32 * r;
        uint4 uu0 = u0[i], uu1 = u1[i];
        s00 += dot8f(uu0, xr0[r][0], xr0[r][1]);
        s01 += dot8f(uu0, xr1[r][0], xr1[r][1]);
        s10 += dot8f(uu1, xr0[r][0], xr0[r][1]);
        s11 += dot8f(uu1, xr1[r][0], xr1[r][1]);
        float4 wa0 = wa4[2 * i], wa1 = wa4[2 * i + 1];
        float4 wb0 = wb4[2 * i], wb1 = wb4[2 * i + 1];
        a0s += dot8ff(xr0[r][0], xr0[r][1], wa0, wa1);
        a1s += dot8ff(xr1[r][0], xr1[r][1], wa0, wa1);
        b0s += dot8ff(xr0[r][0], xr0[r][1], wb0, wb1);
        b1s += dot8ff(xr1[r][0], xr1[r][1], wb0, wb1);
    }
    s00 = warp_sum(s00); s01 = warp_sum(s01);
    s10 = warp_sum(s10); s11 = warp_sum(s11);
    a0s = warp_sum(a0s); a1s = warp_sum(a1s);
    b0s = warp_sum(b0s); b1s = warp_sum(b1s);

    const float gmm = gamma_p[0];
    s00 += a0s + b0s + gmm;
    s01 += a0s + b1s + gmm;
    s10 += a1s + b0s + gmm;
    s11 += a1s + b1s + gmm;

    const float inv_scale = 1.0f / 22.627416997969522f;
    s00 *= inv_scale; s01 *= inv_scale; s10 *= inv_scale; s11 *= inv_scale;
    s00 = s00 > 0.f ? s00 : 0.2f * s00;
    s01 = s01 > 0.f ? s01 : 0.2f * s01;
    s10 = s10 > 0.f ? s10 : 0.2f * s10;
    s11 = s11 > 0.f ? s11 : 0.2f * s11;

    float m0 = fmaxf(s00, s01), m1 = fmaxf(s10, s11);
    float e00 = expf(s00 - m0), e01 = expf(s01 - m0);
    float e10 = expf(s10 - m1), e11 = expf(s11 - m1);
    float i0 = 1.0f / (e00 + e01), i1 = 1.0f / (e10 + e11);
    float a00 = e00 * i0, a01 = e01 * i0;
    float a10 = e10 * i1, a11 = e11 * i1;

    // s_n = x_n + attn@v'  (16 elems per lane per row)
    float sr0[16], sr1[16];
    float sum0 = 0.f, sq0 = 0.f, sum1 = 0.f, sq1 = 0.f;
#pragma unroll
    for (int r = 0; r < 2; r++) {
        int i = lane + 32 * r;
        uint4 xv0 = v0[i], xv1 = v1[i];
        const __half2* p0 = (const __half2*)&xv0;
        const __half2* p1 = (const __half2*)&xv1;
        const float* x0f = (const float*)&xr0[r][0];
        const float* x1f = (const float*)&xr1[r][0];
#pragma unroll
        for (int j = 0; j < 4; j++) {
            float2 f0 = __half22float2(p0[j]);
            float2 f1 = __half22float2(p1[j]);
            float v0a = x0f[2*j]   + a00 * f0.x + a01 * f1.x;
            float v0b = x0f[2*j+1] + a00 * f0.y + a01 * f1.y;
            float v1a = x1f[2*j]   + a10 * f0.x + a11 * f1.x;
            float v1b = x1f[2*j+1] + a10 * f0.y + a11 * f1.y;
            sr0[r*8 + 2*j]   = v0a;  sr0[r*8 + 2*j+1] = v0b;
            sr1[r*8 + 2*j]   = v1a;  sr1[r*8 + 2*j+1] = v1b;
            sum0 += v0a + v0b;  sq0 += v0a * v0a + v0b * v0b;
            sum1 += v1a + v1b;  sq1 += v1a * v1a + v1b * v1b;
        }
    }
    sum0 = warp_sum(sum0); sq0 = warp_sum(sq0);
    sum1 = warp_sum(sum1); sq1 = warp_sum(sq1);
    float mu0 = sum0 * (1.0f / D_);
    float mu1 = sum1 * (1.0f / D_);
    float rs0 = rsqrtf(sq0 * (1.0f / D_) - mu0 * mu0 + 1e-5f);
    float rs1 = rsqrtf(sq1 * (1.0f / D_) - mu1 * mu1 + 1e-5f);

    float4* h4 = (float4*)(hout + (size_t)gw * 1024);
    const float4* g4 = (const float4*)g1;
    const float4* b4 = (const float4*)be1;
    __half* hh0 = hh + (size_t)gw * 1024;

#pragma unroll
    for (int r = 0; r < 2; r++) {
        int i = lane + 32 * r;
        uint4 o0u, o1u;
        __half2* q0o = (__half2*)&o0u;
        __half2* q1o = (__half2*)&o1u;
#pragma unroll
        for (int q = 0; q < 2; q++) {
            float4 G = g4[2 * i + q], Bv = b4[2 * i + q];
            float4 o0, o1;
            o0.x = (sr0[r*8 + 4*q]     - mu0) * rs0 * G.x + Bv.x;
            o0.y = (sr0[r*8 + 4*q + 1] - mu0) * rs0 * G.y + Bv.y;
            o0.z = (sr0[r*8 + 4*q + 2] - mu0) * rs0 * G.z + Bv.z;
            o0.w = (sr0[r*8 + 4*q + 3] - mu0) * rs0 * G.w + Bv.w;
            o1.x = (sr1[r*8 + 4*q]     - mu1) * rs1 * G.x + Bv.x;
            o1.y = (sr1[r*8 + 4*q + 1] - mu1) * rs1 * G.y + Bv.y;
            o1.z = (sr1[r*8 + 4*q + 2] - mu1) * rs1 * G.z + Bv.z;
            o1.w = (sr1[r*8 + 4*q + 3] - mu1) * rs1 * G.w + Bv.w;
            h4[2 * i + q]       = o0;
            h4[128 + 2 * i + q] = o1;
            q0o[2*q]   = __floats2half2_rn(o0.x, o0.y);
            q0o[2*q+1] = __floats2half2_rn(o0.z, o0.w);
            q1o[2*q]   = __floats2half2_rn(o1.x, o1.y);
            q1o[2*q+1] = __floats2half2_rn(o1.z, o1.w);
        }
        ((uint4*)(hh0))[i]       = o0u;
        ((uint4*)(hh0 + 512))[i] = o1u;
    }
}

// ---------------------------------------------------------------------------
// out = LayerNorm(A + P) * g + be ; A fp32, P fp16; fp32 out + fp16 copy
// ---------------------------------------------------------------------------
__global__ __launch_bounds__(128)
void add_ln_kernel(const float* __restrict__ A, const __half* __restrict__ P,
                   const float* __restrict__ g, const float* __restrict__ be,
                   float* __restrict__ out, __half* __restrict__ oh)
{
    size_t row = blockIdx.x;
    int t = threadIdx.x;

    float4 av = ((const float4*)(A + row * D_))[t];
    uint2  pu = ((const uint2*)(P + row * D_))[t];
    __half2 ph0 = *(__half2*)&pu.x;
    __half2 ph1 = *(__half2*)&pu.y;
    float2 p0 = __half22float2(ph0);
    float2 p1 = __half22float2(ph1);
    float4 s;
    s.x = av.x + p0.x; s.y = av.y + p0.y; s.z = av.z + p1.x; s.w = av.w + p1.y;

    float sum = s.x + s.y + s.z + s.w;
    float sq  = s.x * s.x + s.y * s.y + s.z * s.z + s.w * s.w;
    sum = warp_sum(sum);
    sq  = warp_sum(sq);

    __shared__ float sm[8];
    int w = t >> 5;
    if ((t & 31) == 0) { sm[w] = sum; sm[4 + w] = sq; }
    __syncthreads();
    float ts = sm[0] + sm[1] + sm[2] + sm[3];
    float tq = sm[4] + sm[5] + sm[6] + sm[7];

    float mu  = ts * (1.0f / D_);
    float var = tq * (1.0f / D_) - mu * mu;
    float rs  = rsqrtf(var + 1e-5f);

    float4 G  = ((const float4*)g)[t];
    float4 Be = ((const float4*)be)[t];
    float4 o;
    o.x = (s.x - mu) * rs * G.x + Be.x;
    o.y = (s.y - mu) * rs * G.y + Be.y;
    o.z = (s.z - mu) * rs * G.z + Be.z;
    o.w = (s.w - mu) * rs * G.w + Be.w;
    ((float4*)(out + row * D_))[t] = o;

    __half2 h0 = __floats2half2_rn(o.x, o.y);
    __half2 h1 = __floats2half2_rn(o.z, o.w);
    uint2 u;
    u.x = *(uint32_t*)&h0;
    u.y = *(uint32_t*)&h1;
    ((uint2*)(oh + row * D_))[t] = u;
}

// ---------------------------------------------------------------------------
// Final stage: sum score partials, softmax over N=2, pooling, param-free LN
// ---------------------------------------------------------------------------
__global__ __launch_bounds__(256)
void final_kernel(const float* __restrict__ sp, const float* __restrict__ refined,
                  float* __restrict__ fused, float* __restrict__ alpha)
{
    int gw   = (blockIdx.x * 256 + threadIdx.x) >> 5;
    int lane = threadIdx.x & 31;
    if (gw >= B_) return;

    float v = (lane < 16) ? sp[(size_t)gw * 16 + lane] : 0.f;
    v += __shfl_xor_sync(0xffffffffu, v, 1);
    v += __shfl_xor_sync(0xffffffffu, v, 2);
    v += __shfl_xor_sync(0xffffffffu, v, 4);
    float d0 = __shfl_sync(0xffffffffu, v, 0);
    float d1 = __shfl_sync(0xffffffffu, v, 8);

    float m  = fmaxf(d0, d1);
    float e0 = expf(d0 - m), e1 = expf(d1 - m);
    float inv = 1.0f / (e0 + e1);
    float a0 = e0 * inv, a1 = e1 * inv;
    if (lane == 0) {
        alpha[(size_t)gw * 2 + 0] = a0;
        alpha[(size_t)gw * 2 + 1] = a1;
    }

    const float4* f0 = (const float4*)(refined + (size_t)gw * 2 * D_);
    const float4* f1 = f0 + D_ / 4;

    float4 fr[4];
    float sum = 0.f, sq = 0.f;
#pragma unroll
    for (int r = 0; r < 4; r++) {
        int i = lane + 32 * r;
        float4 x0 = f0[i], x1 = f1[i];
        float4 t;
        t.x = a0 * x0.x + a1 * x1.x;  t.y = a0 * x0.y + a1 * x1.y;
        t.z = a0 * x0.z + a1 * x1.z;  t.w = a0 * x0.w + a1 * x1.w;
        fr[r] = t;
        sum += t.x + t.y + t.z + t.w;
        sq  += t.x * t.x + t.y * t.y + t.z * t.z + t.w * t.w;
    }
    sum = warp_sum(sum);
    sq  = warp_sum(sq);
    float mu  = sum * (1.0f / D_);
    float var = sq * (1.0f / D_) - mu * mu;
    float rs  = rsqrtf(var + 1e-5f);

    float4* fo = (float4*)(fused + (size_t)gw * D_);
#pragma unroll
    for (int r = 0; r < 4; r++) {
        int i = lane + 32 * r;
        float4 t = fr[r];
        float4 o;
        o.x = (t.x - mu) * rs;  o.y = (t.y - mu) * rs;
        o.z = (t.z - mu) * rs;  o.w = (t.w - mu) * rs;
        fo[i] = o;
    }
}

// ---------------------------------------------------------------------------
// Launch
// ---------------------------------------------------------------------------
extern "C" void kernel_launch(void* const* d_in, const int* in_sizes, int n_in,
                              void* d_out, int out_size)
{
    const float* x   = (const float*)d_in[0];
    const float* wq  = (const float*)d_in[1];
    const float* bq  = (const float*)d_in[2];
    const float* wk  = (const float*)d_in[3];
    const float* bk  = (const float*)d_in[4];
    const float* wv  = (const float*)d_in[5];
    const float* bv  = (const float*)d_in[6];
    const float* wo  = (const float*)d_in[7];
    const float* bo  = (const float*)d_in[8];
    const float* g1  = (const float*)d_in[9];
    const float* be1 = (const float*)d_in[10];
    const float* wf1 = (const float*)d_in[11];
    const float* bf1 = (const float*)d_in[12];
    const float* wf2 = (const float*)d_in[13];
    const float* bf2 = (const float*)d_in[14];
    const float* g2  = (const float*)d_in[15];
    const float* be2 = (const float*)d_in[16];
    const float* ws1 = (const float*)d_in[17];
    const float* bs1 = (const float*)d_in[18];
    const float* ws2 = (const float*)d_in[19];

    float *h, *sp, *buv, *wa, *wb, *gma;
    __half *uv, *xh, *hh, *rh, *ph, *fh, *wt, *wq16, *wk16, *wv16;
    cudaGetSymbolAddress((void**)&uv, g_uv);
    cudaGetSymbolAddress((void**)&h, g_h);
    cudaGetSymbolAddress((void**)&sp, g_sp);
    cudaGetSymbolAddress((void**)&buv, g_buv);
    cudaGetSymbolAddress((void**)&wa, g_wa);
    cudaGetSymbolAddress((void**)&wb, g_wb);
    cudaGetSymbolAddress((void**)&gma, g_gamma);
    cudaGetSymbolAddress((void**)&xh, g_xh);
    cudaGetSymbolAddress((void**)&hh, g_hh);
    cudaGetSymbolAddress((void**)&rh, g_rh);
    cudaGetSymbolAddress((void**)&ph, g_ph);
    cudaGetSymbolAddress((void**)&fh, g_fh);
    cudaGetSymbolAddress((void**)&wt, g_wt);
    cudaGetSymbolAddress((void**)&wq16, g_wq16);
    cudaGetSymbolAddress((void**)&wk16, g_wk16);
    cudaGetSymbolAddress((void**)&wv16, g_wv16);

    cudaFuncSetAttribute(gemm_mma, cudaFuncAttributeMaxDynamicSharedMemorySize,
                         GEMM_SMEM);

    float* out     = (float*)d_out;
    float* fused   = out;
    float* alpha   = out + (size_t)B_ * D_;
    float* refined = alpha + (size_t)B_ * N_;

    dim3 blk(256);

    // preprocessing
    cvt_kernel<<<(unsigned)(TD_ / 4 / 256), 256>>>(x, xh, TD_ / 4);
    cvt_kernel<<<256, 256>>>(wq, wq16, 262144 / 4);
    cvt_kernel<<<256, 256>>>(wk, wk16, 262144 / 4);
    cvt_kernel<<<256, 256>>>(wv, wv16, 262144 / 4);
    wcvt_kernel<<<1024, 256>>>(wo,  wt + WO_OFF,  512, 512);
    wcvt_kernel<<<2048, 256>>>(wf1, wt + WF1_OFF, 512, 1024);
    wcvt_kernel<<<2048, 256>>>(wf2, wt + WF2_OFF, 1024, 512);
    wcvt_kernel<<<1024, 256>>>(ws1, wt + WS1_OFF, 512, 512);
    prep_kernel<<<4, 128>>>(wq, wk, bq, bk, bv, wo, bo, wa, wb, gma, buv);

    // Mt[j,i] = wk[j,:].wq[i,:]   (fp16 out at wt+WK_OFF; zero bias)
    gemm_mma<<<dim3(4, 4), blk, GEMM_SMEM>>>(wk16, wq16, buv, nullptr,
                                             wt + WK_OFF, 512, 512, 3, nullptr);
    // Wvo_t[n,k] = wo_t[n,:].wv[k,:]  (fp16 out at wt+WVO_OFF; zero bias)
    gemm_mma<<<dim3(4, 4), blk, GEMM_SMEM>>>(wt + WO_OFF, wv16, buv, nullptr,
                                             wt + WVO_OFF, 512, 512, 3, nullptr);

    // uv = xh @ [Mt | Wvo_t]^T + (0|bvo)  -> fp16 [T, 1024]
    gemm_mma<<<dim3(8, T_ / 128), blk, GEMM_SMEM>>>(xh, wt + WK_OFF, buv,
                                                    nullptr, uv, 1024, 512, 3, nullptr);
    // fused attention + residual + LN1 -> h fp32, hh fp16
    attn_ln_kernel<<<B_ / 8, 256>>>(uv, x, wa, wb, gma, g1, be1, h, hh);
    // FFN
    gemm_mma<<<dim3(8, T_ / 128), blk, GEMM_SMEM>>>(hh, wt + WF1_OFF, bf1,
                                                    nullptr, fh, 1024, 512, 2, nullptr);
    gemm_mma<<<dim3(4, T_ / 128), blk, GEMM_SMEM>>>(fh, wt + WF2_OFF, bf2,
                                                    nullptr, ph, 512, 1024, 3, nullptr);
    add_ln_kernel<<<T_, 128>>>(h, ph, g2, be2, refined, rh);
    // score MLP fused: partials = relu(refined@ws1 + bs1) . ws2
    gemm_mma<<<dim3(4, T_ / 128), blk, GEMM_SMEM>>>(rh, wt + WS1_OFF, bs1,
                                                    sp, nullptr, 512, 512, 4, ws2);
    // softmax + pooling + final LN
    final_kernel<<<B_ / 8, 256>>>(sp, refined, fused, alpha);
}

// round 9
// speedup vs baseline: 5.6778x; 1.1943x over previous
#include <cuda_runtime.h>
#include <cuda_fp16.h>
#include <cstdint>

// ---------------------------------------------------------------------------
// Problem constants
// ---------------------------------------------------------------------------
#define B_   65536
#define N_   2
#define D_   512
#define T_   (B_ * N_)          // 131072 tokens
#define TD_  ((size_t)T_ * D_)  // 67,108,864

// ---------------------------------------------------------------------------
// Scratch (static __device__ arrays)
// ---------------------------------------------------------------------------
__device__ __half g_uv[2 * TD_];   // [T, 1024]: u | v'  (v' = x@Wvo + bvo)
__device__ float  g_h[TD_];
__device__ float  g_sp[(size_t)T_ * 8];  // score partials [T, 8]
__device__ float  g_buv[1024];     // bias for uv GEMM: zeros | bvo
__device__ float  g_wa[512], g_wb[512], g_gamma[1];

__device__ __half g_xh[TD_];
__device__ __half g_hh[TD_];
__device__ __half g_rh[TD_];
__device__ __half g_ph[TD_];       // fp16 GEMM intermediate (pre-LN2)
__device__ __half g_fh[2 * TD_];
__device__ __half g_wq16[262144], g_wk16[262144], g_wv16[262144]; // row-major fp16

// transposed fp16 weights, [N,K] layout
#define WK_OFF  262144   // Mt lives here; contiguous with WVO for fused uv GEMM
#define WVO_OFF 524288   // Wvo_t lives here
#define WO_OFF  786432   // wo_t (used only to build Wvo_t)
#define WF1_OFF 1048576
#define WF2_OFF 1572864
#define WS1_OFF 2097152
__device__ __half g_wt[2359296];

// ---------------------------------------------------------------------------
// PTX helpers (baseline sm_80+)
// ---------------------------------------------------------------------------
__device__ __forceinline__ uint32_t smem_u32(const void* smem_ptr) {
    uint32_t addr;
    asm("{ .reg .u64 tmp; cvta.to.shared.u64 tmp, %1; cvt.u32.u64 %0, tmp; }"
        : "=r"(addr) : "l"(smem_ptr));
    return addr;
}

#define CP16(dst, src) \
    asm volatile("cp.async.cg.shared.global [%0], [%1], 16;" \
        :: "r"(dst), "l"(src))

#define CP_COMMIT() asm volatile("cp.async.commit_group;" ::: "memory")
#define CP_WAIT(n)  asm volatile("cp.async.wait_group %0;" :: "n"(n) : "memory")

#define LDSM4(r0, r1, r2, r3, a) \
    asm volatile("ldmatrix.sync.aligned.m8n8.x4.shared.b16 {%0,%1,%2,%3}, [%4];" \
        : "=r"(r0), "=r"(r1), "=r"(r2), "=r"(r3) : "r"(a))

#define MMAH(d, a0, a1, a2, a3, b0, b1) \
    asm volatile("mma.sync.aligned.m16n8k16.row.col.f32.f16.f16.f32 " \
        "{%0,%1,%2,%3}, {%4,%5,%6,%7}, {%8,%9}, {%0,%1,%2,%3};" \
        : "+f"((d)[0]), "+f"((d)[1]), "+f"((d)[2]), "+f"((d)[3]) \
        : "r"(a0), "r"(a1), "r"(a2), "r"(a3), "r"(b0), "r"(b1))

__device__ __forceinline__ float warp_sum(float v) {
#pragma unroll
    for (int o = 16; o; o >>= 1) v += __shfl_xor_sync(0xffffffffu, v, o);
    return v;
}

// dot of 8 fp16 (uint4) with 8 fp32 (two float4)
__device__ __forceinline__ float dot8f(uint4 a, float4 w0, float4 w1) {
    const __half2* pa = (const __half2*)&a;
    float2 f0 = __half22float2(pa[0]);
    float2 f1 = __half22float2(pa[1]);
    float2 f2 = __half22float2(pa[2]);
    float2 f3 = __half22float2(pa[3]);
    return f0.x * w0.x + f0.y * w0.y + f1.x * w0.z + f1.y * w0.w +
           f2.x * w1.x + f2.y * w1.y + f3.x * w1.z + f3.y * w1.w;
}

// dot of two float4 pairs
__device__ __forceinline__ float dot8ff(float4 a0, float4 a1, float4 b0, float4 b1) {
    return a0.x * b0.x + a0.y * b0.y + a0.z * b0.z + a0.w * b0.w +
           a1.x * b1.x + a1.y * b1.y + a1.z * b1.z + a1.w * b1.w;
}

// ---------------------------------------------------------------------------
// mma.sync GEMM: C[M,N] = A[M,K] @ B^T[N,K] + bias  (both fp16, fp32 accum)
// CTA tile 128x128, 8 warps (4m x 2n), warp tile 32x64, K-chunk 64,
// 3-stage cp.async pipeline, 2 CTAs/SM (prologue/epilogue overlap).
// SMEM rows stride 144B (conflict-free).
// mode: 0 fp32; 1 fp32+ReLU; 2 fp16+ReLU; 3 fp16;
//       4 score-fused: relu(v+bias) dot ws2 -> partials Cf[row*8 + bn*2 + wn]
// ---------------------------------------------------------------------------
#define STAGES        3
#define ROW_STRIDE    144
#define MAT_BYTES     18432
#define STAGE_BYTES   36864
#define GEMM_SMEM     (STAGES * STAGE_BYTES)   // 110592

__global__ __launch_bounds__(256, 2)
void gemm_mma(const __half* __restrict__ A, const __half* __restrict__ B,
              const float* __restrict__ bias,
              float* __restrict__ Cf, __half* __restrict__ Ch,
              int N, int K, int mode, const float* __restrict__ ws2)
{
    extern __shared__ char smem[];
    const uint32_t sb = smem_u32(smem);
    const int tid  = threadIdx.x;
    const int lane = tid & 31;
    const int wid  = tid >> 5;
    const int wm   = wid & 3;
    const int wn   = wid >> 2;
    const int bn   = blockIdx.x;
    const int bm   = blockIdx.y;
    const int Kb   = K * 2;

    const char* gA = (const char*)(A + (size_t)bm * 128 * K);
    const char* gB = (const char*)(B + (size_t)bn * 128 * K);

    const int lr  = tid >> 1;
    const int lcb = (tid & 1) * 64;
    const size_t   goff = (size_t)lr * Kb + lcb;
    const uint32_t soff = (uint32_t)lr * ROW_STRIDE + lcb;

    float acc[2][8][4];
#pragma unroll
    for (int mi = 0; mi < 2; mi++)
#pragma unroll
        for (int ni = 0; ni < 8; ni++)
#pragma unroll
            for (int r = 0; r < 4; r++) acc[mi][ni][r] = 0.0f;

    const int nch = K >> 6;

#define LOAD_STAGE(stage, kc) do {                                        \
        uint32_t d = sb + (uint32_t)(stage) * STAGE_BYTES + soff;         \
        size_t   g = goff + (size_t)(kc) * 128;                           \
        CP16(d,                   gA + g);                                \
        CP16(d + 16,              gA + g + 16);                           \
        CP16(d + 32,              gA + g + 32);                           \
        CP16(d + 48,              gA + g + 48);                           \
        CP16(d + MAT_BYTES,       gB + g);                                \
        CP16(d + MAT_BYTES + 16,  gB + g + 16);                           \
        CP16(d + MAT_BYTES + 32,  gB + g + 32);                           \
        CP16(d + MAT_BYTES + 48,  gB + g + 48);                           \
    } while (0)

#pragma unroll
    for (int s = 0; s < STAGES - 1; s++) { LOAD_STAGE(s, s); CP_COMMIT(); }

    const uint32_t a_row  = (uint32_t)(wm * 32 + (lane & 15));
    const uint32_t a_coff = (uint32_t)((lane >> 4) * 16);
    const uint32_t b_row  = (uint32_t)(wn * 64 + ((lane >> 4) * 8) + (lane & 7));
    const uint32_t b_coff = (uint32_t)(((lane >> 3) & 1) * 16);

    int cur = 0;               // stage holding chunk i
    int ld  = STAGES - 1;      // stage to load chunk i+STAGES-1 into

#pragma unroll 1
    for (int i = 0; i < nch; i++) {
        CP_WAIT(STAGES - 2);
        __syncthreads();

        int nxt = i + STAGES - 1;
        if (nxt < nch) LOAD_STAGE(ld, nxt);
        CP_COMMIT();

        const uint32_t base = sb + (uint32_t)cur * STAGE_BYTES;

#pragma unroll
        for (int kk = 0; kk < 4; kk++) {
            const uint32_t kb = kk * 32;
            uint32_t ar[2][4], br[8][2];
#pragma unroll
            for (int mi = 0; mi < 2; mi++) {
                uint32_t ad = base + (a_row + mi * 16) * ROW_STRIDE + kb + a_coff;
                LDSM4(ar[mi][0], ar[mi][1], ar[mi][2], ar[mi][3], ad);
            }
#pragma unroll
            for (int p = 0; p < 4; p++) {
                uint32_t bd = base + MAT_BYTES +
                              (b_row + p * 16) * ROW_STRIDE + kb + b_coff;
                uint32_t r0, r1, r2, r3;
                LDSM4(r0, r1, r2, r3, bd);
                br[2*p][0] = r0;   br[2*p][1] = r1;
                br[2*p+1][0] = r2; br[2*p+1][1] = r3;
            }
#pragma unroll
            for (int mi = 0; mi < 2; mi++)
#pragma unroll
                for (int ni = 0; ni < 8; ni++)
                    MMAH(acc[mi][ni], ar[mi][0], ar[mi][1], ar[mi][2], ar[mi][3],
                         br[ni][0], br[ni][1]);
        }
        cur = (cur + 1 == STAGES) ? 0 : cur + 1;
        ld  = (ld  + 1 == STAGES) ? 0 : ld  + 1;
    }
#undef LOAD_STAGE

    // epilogue
    const int row0 = bm * 128 + wm * 32 + (lane >> 2);
    const int col0 = bn * 128 + wn * 64 + (lane & 3) * 2;

#pragma unroll
    for (int mi = 0; mi < 2; mi++) {
        float s0 = 0.f, s1 = 0.f;
#pragma unroll
        for (int ni = 0; ni < 8; ni++) {
            const int r = row0 + mi * 16;
            const int c = col0 + ni * 8;
            const float b0 = __ldg(bias + c);
            const float b1 = __ldg(bias + c + 1);
            float v00 = acc[mi][ni][0] + b0;
            float v01 = acc[mi][ni][1] + b1;
            float v10 = acc[mi][ni][2] + b0;
            float v11 = acc[mi][ni][3] + b1;
            if (mode == 1 || mode == 2 || mode == 4) {
                v00 = fmaxf(v00, 0.0f); v01 = fmaxf(v01, 0.0f);
                v10 = fmaxf(v10, 0.0f); v11 = fmaxf(v11, 0.0f);
            }
            if (mode == 4) {
                const float w0 = __ldg(ws2 + c);
                const float w1 = __ldg(ws2 + c + 1);
                s0 += v00 * w0 + v01 * w1;
                s1 += v10 * w0 + v11 * w1;
            } else if (mode >= 2) {
                __half2 h0 = __floats2half2_rn(v00, v01);
                __half2 h1 = __floats2half2_rn(v10, v11);
                *(__half2*)(Ch + (size_t)r * N + c)       = h0;
                *(__half2*)(Ch + (size_t)(r + 8) * N + c) = h1;
            } else {
                *(float2*)(Cf + (size_t)r * N + c)       = make_float2(v00, v01);
                *(float2*)(Cf + (size_t)(r + 8) * N + c) = make_float2(v10, v11);
            }
        }
        if (mode == 4) {
            s0 += __shfl_xor_sync(0xffffffffu, s0, 1);
            s0 += __shfl_xor_sync(0xffffffffu, s0, 2);
            s1 += __shfl_xor_sync(0xffffffffu, s1, 1);
            s1 += __shfl_xor_sync(0xffffffffu, s1, 2);
            if ((lane & 3) == 0) {
                const int r = row0 + mi * 16;
                Cf[(size_t)r * 8 + bn * 2 + wn]       = s0;
                Cf[(size_t)(r + 8) * 8 + bn * 2 + wn] = s1;
            }
        }
    }
}

// ---------------------------------------------------------------------------
// fp32 -> fp16 convert (elementwise)
// ---------------------------------------------------------------------------
__global__ __launch_bounds__(256)
void cvt_kernel(const float* __restrict__ in, __half* __restrict__ out, size_t n4)
{
    size_t i = (size_t)blockIdx.x * 256 + threadIdx.x;
    if (i >= n4) return;
    float4 v = ((const float4*)in)[i];
    __half2 h0 = __floats2half2_rn(v.x, v.y);
    __half2 h1 = __floats2half2_rn(v.z, v.w);
    uint2 o;
    o.x = *(uint32_t*)&h0;
    o.y = *(uint32_t*)&h1;
    ((uint2*)out)[i] = o;
}

// ---------------------------------------------------------------------------
// weight transpose + fp16 convert: W[K,N] -> Wt[N,K]
// ---------------------------------------------------------------------------
__global__ __launch_bounds__(256)
void wcvt_kernel(const float* __restrict__ W, __half* __restrict__ t,
                 int K, int N)
{
    int idx = blockIdx.x * 256 + threadIdx.x;
    if (idx >= K * N) return;
    int n = idx / K, k = idx - n * K;
    t[idx] = __float2half_rn(W[(size_t)k * N + n]);
}

// ---------------------------------------------------------------------------
// prep: attention bias terms + uv GEMM bias (zeros | bvo)
// ---------------------------------------------------------------------------
__global__ __launch_bounds__(128)
void prep_kernel(const float* __restrict__ wq, const float* __restrict__ wk,
                 const float* __restrict__ bq, const float* __restrict__ bk,
                 const float* __restrict__ bv, const float* __restrict__ wo,
                 const float* __restrict__ bo,
                 float* __restrict__ w_a, float* __restrict__ w_b,
                 float* __restrict__ gamma, float* __restrict__ buv)
{
    int i = blockIdx.x * 128 + threadIdx.x;
    float sa = 0.f, sb = 0.f, so = 0.f;
    for (int o = 0; o < 512; o++) {
        sa += wq[(size_t)i * 512 + o] * bk[o];
        sb += wk[(size_t)i * 512 + o] * bq[o];
        so += bv[o] * wo[(size_t)o * 512 + i];
    }
    w_a[i] = sa;
    w_b[i] = sb;
    buv[i] = 0.f;
    buv[512 + i] = so + bo[i];
    if (blockIdx.x == 0) {
        float gsum = 0.f;
        for (int o = threadIdx.x; o < 512; o += 128) gsum += bq[o] * bk[o];
        gsum = warp_sum(gsum);
        __shared__ float sm[4];
        if ((threadIdx.x & 31) == 0) sm[threadIdx.x >> 5] = gsum;
        __syncthreads();
        if (threadIdx.x == 0) gamma[0] = sm[0] + sm[1] + sm[2] + sm[3];
    }
}

// ---------------------------------------------------------------------------
// Fused attention + residual + LN1 (one warp per sample).
// ---------------------------------------------------------------------------
__global__ __launch_bounds__(256)
void attn_ln_kernel(const __half* __restrict__ uv, const float* __restrict__ x,
                    const float* __restrict__ w_a, const float* __restrict__ w_b,
                    const float* __restrict__ gamma_p,
                    const float* __restrict__ g1, const float* __restrict__ be1,
                    float* __restrict__ hout, __half* __restrict__ hh)
{
    int gw   = (blockIdx.x * 256 + threadIdx.x) >> 5;
    int lane = threadIdx.x & 31;
    if (gw >= B_) return;

    const __half* ub = uv + (size_t)gw * 2048;
    const uint4* u0 = (const uint4*)(ub);
    const uint4* u1 = (const uint4*)(ub + 1024);
    const uint4* v0 = (const uint4*)(ub + 512);
    const uint4* v1 = (const uint4*)(ub + 1536);
    const float4* xb = (const float4*)(x + (size_t)gw * 1024);
    const float4* wa4 = (const float4*)w_a;
    const float4* wb4 = (const float4*)w_b;

    float4 xr0[2][2], xr1[2][2];
#pragma unroll
    for (int r = 0; r < 2; r++) {
        int i = lane + 32 * r;
        xr0[r][0] = xb[2 * i];
        xr0[r][1] = xb[2 * i + 1];
        xr1[r][0] = xb[128 + 2 * i];
        xr1[r][1] = xb[128 + 2 * i + 1];
    }

    float s00 = 0.f, s01 = 0.f, s10 = 0.f, s11 = 0.f;
    float a0s = 0.f, a1s = 0.f, b0s = 0.f, b1s = 0.f;
#pragma unroll
    for (int r = 0; r < 2; r++) {
        int i = lane + 32 * r;
        uint4 uu0 = u0[i], uu1 = u1[i];
        s00 += dot8f(uu0, xr0[r][0], xr0[r][1]);
        s01 += dot8f(uu0, xr1[r][0], xr1[r][1]);
        s10 += dot8f(uu1, xr0[r][0], xr0[r][1]);
        s11 += dot8f(uu1, xr1[r][0], xr1[r][1]);
        float4 wa0 = wa4[2 * i], wa1 = wa4[2 * i + 1];
        float4 wb0 = wb4[2 * i], wb1 = wb4[2 * i + 1];
        a0s += dot8ff(xr0[r][0], xr0[r][1], wa0, wa1);
        a1s += dot8ff(xr1[r][0], xr1[r][1], wa0, wa1);
        b0s += dot8ff(xr0[r][0], xr0[r][1], wb0, wb1);
        b1s += dot8ff(xr1[r][0], xr1[r][1], wb0, wb1);
    }
    s00 = warp_sum(s00); s01 = warp_sum(s01);
    s10 = warp_sum(s10); s11 = warp_sum(s11);
    a0s = warp_sum(a0s); a1s = warp_sum(a1s);
    b0s = warp_sum(b0s); b1s = warp_sum(b1s);

    const float gmm = gamma_p[0];
    s00 += a0s + b0s + gmm;
    s01 += a0s + b1s + gmm;
    s10 += a1s + b0s + gmm;
    s11 += a1s + b1s + gmm;

    const float inv_scale = 1.0f / 22.627416997969522f;
    s00 *= inv_scale; s01 *= inv_scale; s10 *= inv_scale; s11 *= inv_scale;
    s00 = s00 > 0.f ? s00 : 0.2f * s00;
    s01 = s01 > 0.f ? s01 : 0.2f * s01;
    s10 = s10 > 0.f ? s10 : 0.2f * s10;
    s11 = s11 > 0.f ? s11 : 0.2f * s11;

    float m0 = fmaxf(s00, s01), m1 = fmaxf(s10, s11);
    float e00 = expf(s00 - m0), e01 = expf(s01 - m0);
    float e10 = expf(s10 - m1), e11 = expf(s11 - m1);
    float i0 = 1.0f / (e00 + e01), i1 = 1.0f / (e10 + e11);
    float a00 = e00 * i0, a01 = e01 * i0;
    float a10 = e10 * i1, a11 = e11 * i1;

    float sr0[16], sr1[16];
    float sum0 = 0.f, sq0 = 0.f, sum1 = 0.f, sq1 = 0.f;
#pragma unroll
    for (int r = 0; r < 2; r++) {
        int i = lane + 32 * r;
        uint4 xv0 = v0[i], xv1 = v1[i];
        const __half2* p0 = (const __half2*)&xv0;
        const __half2* p1 = (const __half2*)&xv1;
        const float* x0f = (const float*)&xr0[r][0];
        const float* x1f = (const float*)&xr1[r][0];
#pragma unroll
        for (int j = 0; j < 4; j++) {
            float2 f0 = __half22float2(p0[j]);
            float2 f1 = __half22float2(p1[j]);
            float v0a = x0f[2*j]   + a00 * f0.x + a01 * f1.x;
            float v0b = x0f[2*j+1] + a00 * f0.y + a01 * f1.y;
            float v1a = x1f[2*j]   + a10 * f0.x + a11 * f1.x;
            float v1b = x1f[2*j+1] + a10 * f0.y + a11 * f1.y;
            sr0[r*8 + 2*j]   = v0a;  sr0[r*8 + 2*j+1] = v0b;
            sr1[r*8 + 2*j]   = v1a;  sr1[r*8 + 2*j+1] = v1b;
            sum0 += v0a + v0b;  sq0 += v0a * v0a + v0b * v0b;
            sum1 += v1a + v1b;  sq1 += v1a * v1a + v1b * v1b;
        }
    }
    sum0 = warp_sum(sum0); sq0 = warp_sum(sq0);
    sum1 = warp_sum(sum1); sq1 = warp_sum(sq1);
    float mu0 = sum0 * (1.0f / D_);
    float mu1 = sum1 * (1.0f / D_);
    float rs0 = rsqrtf(sq0 * (1.0f / D_) - mu0 * mu0 + 1e-5f);
    float rs1 = rsqrtf(sq1 * (1.0f / D_) - mu1 * mu1 + 1e-5f);

    float4* h4 = (float4*)(hout + (size_t)gw * 1024);
    const float4* g4 = (const float4*)g1;
    const float4* b4 = (const float4*)be1;
    __half* hh0 = hh + (size_t)gw * 1024;

#pragma unroll
    for (int r = 0; r < 2; r++) {
        int i = lane + 32 * r;
        uint4 o0u, o1u;
        __half2* q0o = (__half2*)&o0u;
        __half2* q1o = (__half2*)&o1u;
#pragma unroll
        for (int q = 0; q < 2; q++) {
            float4 G = g4[2 * i + q], Bv = b4[2 * i + q];
            float4 o0, o1;
            o0.x = (sr0[r*8 + 4*q]     - mu0) * rs0 * G.x + Bv.x;
            o0.y = (sr0[r*8 + 4*q + 1] - mu0) * rs0 * G.y + Bv.y;
            o0.z = (sr0[r*8 + 4*q + 2] - mu0) * rs0 * G.z + Bv.z;
            o0.w = (sr0[r*8 + 4*q + 3] - mu0) * rs0 * G.w + Bv.w;
            o1.x = (sr1[r*8 + 4*q]     - mu1) * rs1 * G.x + Bv.x;
            o1.y = (sr1[r*8 + 4*q + 1] - mu1) * rs1 * G.y + Bv.y;
            o1.z = (sr1[r*8 + 4*q + 2] - mu1) * rs1 * G.z + Bv.z;
            o1.w = (sr1[r*8 + 4*q + 3] - mu1) * rs1 * G.w + Bv.w;
            h4[2 * i + q]       = o0;
            h4[128 + 2 * i + q] = o1;
            q0o[2*q]   = __floats2half2_rn(o0.x, o0.y);
            q0o[2*q+1] = __floats2half2_rn(o0.z, o0.w);
            q1o[2*q]   = __floats2half2_rn(o1.x, o1.y);
            q1o[2*q+1] = __floats2half2_rn(o1.z, o1.w);
        }
        ((uint4*)(hh0))[i]       = o0u;
        ((uint4*)(hh0 + 512))[i] = o1u;
    }
}

// ---------------------------------------------------------------------------
// out = LayerNorm(A + P) * g + be ; A fp32, P fp16; fp32 out + fp16 copy
// ---------------------------------------------------------------------------
__global__ __launch_bounds__(128)
void add_ln_kernel(const float* __restrict__ A, const __half* __restrict__ P,
                   const float* __restrict__ g, const float* __restrict__ be,
                   float* __restrict__ out, __half* __restrict__ oh)
{
    size_t row = blockIdx.x;
    int t = threadIdx.x;

    float4 av = ((const float4*)(A + row * D_))[t];
    uint2  pu = ((const uint2*)(P + row * D_))[t];
    __half2 ph0 = *(__half2*)&pu.x;
    __half2 ph1 = *(__half2*)&pu.y;
    float2 p0 = __half22float2(ph0);
    float2 p1 = __half22float2(ph1);
    float4 s;
    s.x = av.x + p0.x; s.y = av.y + p0.y; s.z = av.z + p1.x; s.w = av.w + p1.y;

    float sum = s.x + s.y + s.z + s.w;
    float sq  = s.x * s.x + s.y * s.y + s.z * s.z + s.w * s.w;
    sum = warp_sum(sum);
    sq  = warp_sum(sq);

    __shared__ float sm[8];
    int w = t >> 5;
    if ((t & 31) == 0) { sm[w] = sum; sm[4 + w] = sq; }
    __syncthreads();
    float ts = sm[0] + sm[1] + sm[2] + sm[3];
    float tq = sm[4] + sm[5] + sm[6] + sm[7];

    float mu  = ts * (1.0f / D_);
    float var = tq * (1.0f / D_) - mu * mu;
    float rs  = rsqrtf(var + 1e-5f);

    float4 G  = ((const float4*)g)[t];
    float4 Be = ((const float4*)be)[t];
    float4 o;
    o.x = (s.x - mu) * rs * G.x + Be.x;
    o.y = (s.y - mu) * rs * G.y + Be.y;
    o.z = (s.z - mu) * rs * G.z + Be.z;
    o.w = (s.w - mu) * rs * G.w + Be.w;
    ((float4*)(out + row * D_))[t] = o;

    __half2 h0 = __floats2half2_rn(o.x, o.y);
    __half2 h1 = __floats2half2_rn(o.z, o.w);
    uint2 u;
    u.x = *(uint32_t*)&h0;
    u.y = *(uint32_t*)&h1;
    ((uint2*)(oh + row * D_))[t] = u;
}

// ---------------------------------------------------------------------------
// Final stage: sum score partials, softmax over N=2, pooling, param-free LN
// ---------------------------------------------------------------------------
__global__ __launch_bounds__(256)
void final_kernel(const float* __restrict__ sp, const float* __restrict__ refined,
                  float* __restrict__ fused, float* __restrict__ alpha)
{
    int gw   = (blockIdx.x * 256 + threadIdx.x) >> 5;
    int lane = threadIdx.x & 31;
    if (gw >= B_) return;

    float v = (lane < 16) ? sp[(size_t)gw * 16 + lane] : 0.f;
    v += __shfl_xor_sync(0xffffffffu, v, 1);
    v += __shfl_xor_sync(0xffffffffu, v, 2);
    v += __shfl_xor_sync(0xffffffffu, v, 4);
    float d0 = __shfl_sync(0xffffffffu, v, 0);
    float d1 = __shfl_sync(0xffffffffu, v, 8);

    float m  = fmaxf(d0, d1);
    float e0 = expf(d0 - m), e1 = expf(d1 - m);
    float inv = 1.0f / (e0 + e1);
    float a0 = e0 * inv, a1 = e1 * inv;
    if (lane == 0) {
        alpha[(size_t)gw * 2 + 0] = a0;
        alpha[(size_t)gw * 2 + 1] = a1;
    }

    const float4* f0 = (const float4*)(refined + (size_t)gw * 2 * D_);
    const float4* f1 = f0 + D_ / 4;

    float4 fr[4];
    float sum = 0.f, sq = 0.f;
#pragma unroll
    for (int r = 0; r < 4; r++) {
        int i = lane + 32 * r;
        float4 x0 = f0[i], x1 = f1[i];
        float4 t;
        t.x = a0 * x0.x + a1 * x1.x;  t.y = a0 * x0.y + a1 * x1.y;
        t.z = a0 * x0.z + a1 * x1.z;  t.w = a0 * x0.w + a1 * x1.w;
        fr[r] = t;
        sum += t.x + t.y + t.z + t.w;
        sq  += t.x * t.x + t.y * t.y + t.z * t.z + t.w * t.w;
    }
    sum = warp_sum(sum);
    sq  = warp_sum(sq);
    float mu  = sum * (1.0f / D_);
    float var = sq * (1.0f / D_) - mu * mu;
    float rs  = rsqrtf(var + 1e-5f);

    float4* fo = (float4*)(fused + (size_t)gw * D_);
#pragma unroll
    for (int r = 0; r < 4; r++) {
        int i = lane + 32 * r;
        float4 t = fr[r];
        float4 o;
        o.x = (t.x - mu) * rs;  o.y = (t.y - mu) * rs;
        o.z = (t.z - mu) * rs;  o.w = (t.w - mu) * rs;
        fo[i] = o;
    }
}

// ---------------------------------------------------------------------------
// Launch
// ---------------------------------------------------------------------------
extern "C" void kernel_launch(void* const* d_in, const int* in_sizes, int n_in,
                              void* d_out, int out_size)
{
    const float* x   = (const float*)d_in[0];
    const float* wq  = (const float*)d_in[1];
    const float* bq  = (const float*)d_in[2];
    const float* wk  = (const float*)d_in[3];
    const float* bk  = (const float*)d_in[4];
    const float* wv  = (const float*)d_in[5];
    const float* bv  = (const float*)d_in[6];
    const float* wo  = (const float*)d_in[7];
    const float* bo  = (const float*)d_in[8];
    const float* g1  = (const float*)d_in[9];
    const float* be1 = (const float*)d_in[10];
    const float* wf1 = (const float*)d_in[11];
    const float* bf1 = (const float*)d_in[12];
    const float* wf2 = (const float*)d_in[13];
    const float* bf2 = (const float*)d_in[14];
    const float* g2  = (const float*)d_in[15];
    const float* be2 = (const float*)d_in[16];
    const float* ws1 = (const float*)d_in[17];
    const float* bs1 = (const float*)d_in[18];
    const float* ws2 = (const float*)d_in[19];

    float *h, *sp, *buv, *wa, *wb, *gma;
    __half *uv, *xh, *hh, *rh, *ph, *fh, *wt, *wq16, *wk16, *wv16;
    cudaGetSymbolAddress((void**)&uv, g_uv);
    cudaGetSymbolAddress((void**)&h, g_h);
    cudaGetSymbolAddress((void**)&sp, g_sp);
    cudaGetSymbolAddress((void**)&buv, g_buv);
    cudaGetSymbolAddress((void**)&wa, g_wa);
    cudaGetSymbolAddress((void**)&wb, g_wb);
    cudaGetSymbolAddress((void**)&gma, g_gamma);
    cudaGetSymbolAddress((void**)&xh, g_xh);
    cudaGetSymbolAddress((void**)&hh, g_hh);
    cudaGetSymbolAddress((void**)&rh, g_rh);
    cudaGetSymbolAddress((void**)&ph, g_ph);
    cudaGetSymbolAddress((void**)&fh, g_fh);
    cudaGetSymbolAddress((void**)&wt, g_wt);
    cudaGetSymbolAddress((void**)&wq16, g_wq16);
    cudaGetSymbolAddress((void**)&wk16, g_wk16);
    cudaGetSymbolAddress((void**)&wv16, g_wv16);

    cudaFuncSetAttribute(gemm_mma, cudaFuncAttributeMaxDynamicSharedMemorySize,
                         GEMM_SMEM);

    float* out     = (float*)d_out;
    float* fused   = out;
    float* alpha   = out + (size_t)B_ * D_;
    float* refined = alpha + (size_t)B_ * N_;

    dim3 blk(256);

    // preprocessing
    cvt_kernel<<<(unsigned)(TD_ / 4 / 256), 256>>>(x, xh, TD_ / 4);
    cvt_kernel<<<256, 256>>>(wq, wq16, 262144 / 4);
    cvt_kernel<<<256, 256>>>(wk, wk16, 262144 / 4);
    cvt_kernel<<<256, 256>>>(wv, wv16, 262144 / 4);
    wcvt_kernel<<<1024, 256>>>(wo,  wt + WO_OFF,  512, 512);
    wcvt_kernel<<<2048, 256>>>(wf1, wt + WF1_OFF, 512, 1024);
    wcvt_kernel<<<2048, 256>>>(wf2, wt + WF2_OFF, 1024, 512);
    wcvt_kernel<<<1024, 256>>>(ws1, wt + WS1_OFF, 512, 512);
    prep_kernel<<<4, 128>>>(wq, wk, bq, bk, bv, wo, bo, wa, wb, gma, buv);

    // Mt[j,i] = wk[j,:].wq[i,:]
    gemm_mma<<<dim3(4, 4), blk, GEMM_SMEM>>>(wk16, wq16, buv, nullptr,
                                             wt + WK_OFF, 512, 512, 3, nullptr);
    // Wvo_t[n,k] = wo_t[n,:].wv[k,:]
    gemm_mma<<<dim3(4, 4), blk, GEMM_SMEM>>>(wt + WO_OFF, wv16, buv, nullptr,
                                             wt + WVO_OFF, 512, 512, 3, nullptr);

    // uv = xh @ [Mt | Wvo_t]^T + (0|bvo)  -> fp16 [T, 1024]
    gemm_mma<<<dim3(8, T_ / 128), blk, GEMM_SMEM>>>(xh, wt + WK_OFF, buv,
                                                    nullptr, uv, 1024, 512, 3, nullptr);
    // fused attention + residual + LN1 -> h fp32, hh fp16
    attn_ln_kernel<<<B_ / 8, 256>>>(uv, x, wa, wb, gma, g1, be1, h, hh);
    // FFN
    gemm_mma<<<dim3(8, T_ / 128), blk, GEMM_SMEM>>>(hh, wt + WF1_OFF, bf1,
                                                    nullptr, fh, 1024, 512, 2, nullptr);
    gemm_mma<<<dim3(4, T_ / 128), blk, GEMM_SMEM>>>(fh, wt + WF2_OFF, bf2,
                                                    nullptr, ph, 512, 1024, 3, nullptr);
    add_ln_kernel<<<T_, 128>>>(h, ph, g2, be2, refined, rh);
    // score MLP fused: partials = relu(refined@ws1 + bs1) . ws2
    gemm_mma<<<dim3(4, T_ / 128), blk, GEMM_SMEM>>>(rh, wt + WS1_OFF, bs1,
                                                    sp, nullptr, 512, 512, 4, ws2);
    // softmax + pooling + final LN
    final_kernel<<<B_ / 8, 256>>>(sp, refined, fused, alpha);
}

// round 10
// speedup vs baseline: 5.7886x; 1.0195x over previous
#include <cuda_runtime.h>
#include <cuda_fp16.h>
#include <cstdint>

// ---------------------------------------------------------------------------
// Problem constants
// ---------------------------------------------------------------------------
#define B_   65536
#define N_   2
#define D_   512
#define T_   (B_ * N_)          // 131072 tokens
#define TD_  ((size_t)T_ * D_)  // 67,108,864

// ---------------------------------------------------------------------------
// Scratch (static __device__ arrays)
// ---------------------------------------------------------------------------
__device__ __half g_uv[2 * TD_];   // [T, 1024]: u | v'  (v' = x@Wvo + bvo)
__device__ float  g_sp[(size_t)T_ * 8];  // score partials [T, 8]
__device__ float  g_buv[1024];     // bias for uv GEMM: zeros | bvo
__device__ float  g_wa[512], g_wb[512], g_gamma[1];

__device__ __half g_xh[TD_];
__device__ __half g_hh[TD_];       // h fp16 (residual + FFN input)
__device__ __half g_rh[TD_];
__device__ __half g_ph[TD_];       // fp16 GEMM intermediate (pre-LN2)
__device__ __half g_fh[2 * TD_];
__device__ __half g_wq16[262144], g_wk16[262144], g_wv16[262144]; // row-major fp16

// transposed fp16 weights, [N,K] layout
#define WK_OFF  262144   // Mt lives here; contiguous with WVO for fused uv GEMM
#define WVO_OFF 524288   // Wvo_t lives here
#define WO_OFF  786432   // wo_t (used only to build Wvo_t)
#define WF1_OFF 1048576
#define WF2_OFF 1572864
#define WS1_OFF 2097152
__device__ __half g_wt[2359296];

// ---------------------------------------------------------------------------
// PTX helpers (baseline sm_80+)
// ---------------------------------------------------------------------------
__device__ __forceinline__ uint32_t smem_u32(const void* smem_ptr) {
    uint32_t addr;
    asm("{ .reg .u64 tmp; cvta.to.shared.u64 tmp, %1; cvt.u32.u64 %0, tmp; }"
        : "=r"(addr) : "l"(smem_ptr));
    return addr;
}

#define CP16(dst, src) \
    asm volatile("cp.async.cg.shared.global [%0], [%1], 16;" \
        :: "r"(dst), "l"(src))

#define CP_COMMIT() asm volatile("cp.async.commit_group;" ::: "memory")
#define CP_WAIT(n)  asm volatile("cp.async.wait_group %0;" :: "n"(n) : "memory")

#define LDSM4(r0, r1, r2, r3, a) \
    asm volatile("ldmatrix.sync.aligned.m8n8.x4.shared.b16 {%0,%1,%2,%3}, [%4];" \
        : "=r"(r0), "=r"(r1), "=r"(r2), "=r"(r3) : "r"(a))

#define MMAH(d, a0, a1, a2, a3, b0, b1) \
    asm volatile("mma.sync.aligned.m16n8k16.row.col.f32.f16.f16.f32 " \
        "{%0,%1,%2,%3}, {%4,%5,%6,%7}, {%8,%9}, {%0,%1,%2,%3};" \
        : "+f"((d)[0]), "+f"((d)[1]), "+f"((d)[2]), "+f"((d)[3]) \
        : "r"(a0), "r"(a1), "r"(a2), "r"(a3), "r"(b0), "r"(b1))

__device__ __forceinline__ float warp_sum(float v) {
#pragma unroll
    for (int o = 16; o; o >>= 1) v += __shfl_xor_sync(0xffffffffu, v, o);
    return v;
}

// dot of 8 fp16 (uint4) with 8 fp32 (two float4)
__device__ __forceinline__ float dot8f(uint4 a, float4 w0, float4 w1) {
    const __half2* pa = (const __half2*)&a;
    float2 f0 = __half22float2(pa[0]);
    float2 f1 = __half22float2(pa[1]);
    float2 f2 = __half22float2(pa[2]);
    float2 f3 = __half22float2(pa[3]);
    return f0.x * w0.x + f0.y * w0.y + f1.x * w0.z + f1.y * w0.w +
           f2.x * w1.x + f2.y * w1.y + f3.x * w1.z + f3.y * w1.w;
}

// dot of two float4 pairs
__device__ __forceinline__ float dot8ff(float4 a0, float4 a1, float4 b0, float4 b1) {
    return a0.x * b0.x + a0.y * b0.y + a0.z * b0.z + a0.w * b0.w +
           a1.x * b1.x + a1.y * b1.y + a1.z * b1.z + a1.w * b1.w;
}

// ---------------------------------------------------------------------------
// mma.sync GEMM: C[M,N] = A[M,K] @ B^T[N,K] + bias  (both fp16, fp32 accum)
// CTA tile 128x128, 8 warps (4m x 2n), warp tile 32x64, K-chunk 64,
// 3-stage cp.async pipeline, 2 CTAs/SM (prologue/epilogue overlap).
// SMEM rows stride 144B (conflict-free).
// mode: 0 fp32; 1 fp32+ReLU; 2 fp16+ReLU; 3 fp16;
//       4 score-fused: relu(v+bias) dot ws2 -> partials Cf[row*8 + bn*2 + wn]
// ---------------------------------------------------------------------------
#define STAGES        3
#define ROW_STRIDE    144
#define MAT_BYTES     18432
#define STAGE_BYTES   36864
#define GEMM_SMEM     (STAGES * STAGE_BYTES)   // 110592

__global__ __launch_bounds__(256, 2)
void gemm_mma(const __half* __restrict__ A, const __half* __restrict__ B,
              const float* __restrict__ bias,
              float* __restrict__ Cf, __half* __restrict__ Ch,
              int N, int K, int mode, const float* __restrict__ ws2)
{
    extern __shared__ char smem[];
    const uint32_t sb = smem_u32(smem);
    const int tid  = threadIdx.x;
    const int lane = tid & 31;
    const int wid  = tid >> 5;
    const int wm   = wid & 3;
    const int wn   = wid >> 2;
    const int bn   = blockIdx.x;
    const int bm   = blockIdx.y;
    const int Kb   = K * 2;

    const char* gA = (const char*)(A + (size_t)bm * 128 * K);
    const char* gB = (const char*)(B + (size_t)bn * 128 * K);

    const int lr  = tid >> 1;
    const int lcb = (tid & 1) * 64;
    const size_t   goff = (size_t)lr * Kb + lcb;
    const uint32_t soff = (uint32_t)lr * ROW_STRIDE + lcb;

    float acc[2][8][4];
#pragma unroll
    for (int mi = 0; mi < 2; mi++)
#pragma unroll
        for (int ni = 0; ni < 8; ni++)
#pragma unroll
            for (int r = 0; r < 4; r++) acc[mi][ni][r] = 0.0f;

    const int nch = K >> 6;

#define LOAD_STAGE(stage, kc) do {                                        \
        uint32_t d = sb + (uint32_t)(stage) * STAGE_BYTES + soff;         \
        size_t   g = goff + (size_t)(kc) * 128;                           \
        CP16(d,                   gA + g);                                \
        CP16(d + 16,              gA + g + 16);                           \
        CP16(d + 32,              gA + g + 32);                           \
        CP16(d + 48,              gA + g + 48);                           \
        CP16(d + MAT_BYTES,       gB + g);                                \
        CP16(d + MAT_BYTES + 16,  gB + g + 16);                           \
        CP16(d + MAT_BYTES + 32,  gB + g + 32);                           \
        CP16(d + MAT_BYTES + 48,  gB + g + 48);                           \
    } while (0)

#pragma unroll
    for (int s = 0; s < STAGES - 1; s++) { LOAD_STAGE(s, s); CP_COMMIT(); }

    const uint32_t a_row  = (uint32_t)(wm * 32 + (lane & 15));
    const uint32_t a_coff = (uint32_t)((lane >> 4) * 16);
    const uint32_t b_row  = (uint32_t)(wn * 64 + ((lane >> 4) * 8) + (lane & 7));
    const uint32_t b_coff = (uint32_t)(((lane >> 3) & 1) * 16);

    int cur = 0;
    int ld  = STAGES - 1;

#pragma unroll 1
    for (int i = 0; i < nch; i++) {
        CP_WAIT(STAGES - 2);
        __syncthreads();

        int nxt = i + STAGES - 1;
        if (nxt < nch) LOAD_STAGE(ld, nxt);
        CP_COMMIT();

        const uint32_t base = sb + (uint32_t)cur * STAGE_BYTES;

#pragma unroll
        for (int kk = 0; kk < 4; kk++) {
            const uint32_t kb = kk * 32;
            uint32_t ar[2][4], br[8][2];
#pragma unroll
            for (int mi = 0; mi < 2; mi++) {
                uint32_t ad = base + (a_row + mi * 16) * ROW_STRIDE + kb + a_coff;
                LDSM4(ar[mi][0], ar[mi][1], ar[mi][2], ar[mi][3], ad);
            }
#pragma unroll
            for (int p = 0; p < 4; p++) {
                uint32_t bd = base + MAT_BYTES +
                              (b_row + p * 16) * ROW_STRIDE + kb + b_coff;
                uint32_t r0, r1, r2, r3;
                LDSM4(r0, r1, r2, r3, bd);
                br[2*p][0] = r0;   br[2*p][1] = r1;
                br[2*p+1][0] = r2; br[2*p+1][1] = r3;
            }
#pragma unroll
            for (int mi = 0; mi < 2; mi++)
#pragma unroll
                for (int ni = 0; ni < 8; ni++)
                    MMAH(acc[mi][ni], ar[mi][0], ar[mi][1], ar[mi][2], ar[mi][3],
                         br[ni][0], br[ni][1]);
        }
        cur = (cur + 1 == STAGES) ? 0 : cur + 1;
        ld  = (ld  + 1 == STAGES) ? 0 : ld  + 1;
    }
#undef LOAD_STAGE

    // epilogue
    const int row0 = bm * 128 + wm * 32 + (lane >> 2);
    const int col0 = bn * 128 + wn * 64 + (lane & 3) * 2;

#pragma unroll
    for (int mi = 0; mi < 2; mi++) {
        float s0 = 0.f, s1 = 0.f;
#pragma unroll
        for (int ni = 0; ni < 8; ni++) {
            const int r = row0 + mi * 16;
            const int c = col0 + ni * 8;
            const float b0 = __ldg(bias + c);
            const float b1 = __ldg(bias + c + 1);
            float v00 = acc[mi][ni][0] + b0;
            float v01 = acc[mi][ni][1] + b1;
            float v10 = acc[mi][ni][2] + b0;
            float v11 = acc[mi][ni][3] + b1;
            if (mode == 1 || mode == 2 || mode == 4) {
                v00 = fmaxf(v00, 0.0f); v01 = fmaxf(v01, 0.0f);
                v10 = fmaxf(v10, 0.0f); v11 = fmaxf(v11, 0.0f);
            }
            if (mode == 4) {
                const float w0 = __ldg(ws2 + c);
                const float w1 = __ldg(ws2 + c + 1);
                s0 += v00 * w0 + v01 * w1;
                s1 += v10 * w0 + v11 * w1;
            } else if (mode >= 2) {
                __half2 h0 = __floats2half2_rn(v00, v01);
                __half2 h1 = __floats2half2_rn(v10, v11);
                *(__half2*)(Ch + (size_t)r * N + c)       = h0;
                *(__half2*)(Ch + (size_t)(r + 8) * N + c) = h1;
            } else {
                *(float2*)(Cf + (size_t)r * N + c)       = make_float2(v00, v01);
                *(float2*)(Cf + (size_t)(r + 8) * N + c) = make_float2(v10, v11);
            }
        }
        if (mode == 4) {
            s0 += __shfl_xor_sync(0xffffffffu, s0, 1);
            s0 += __shfl_xor_sync(0xffffffffu, s0, 2);
            s1 += __shfl_xor_sync(0xffffffffu, s1, 1);
            s1 += __shfl_xor_sync(0xffffffffu, s1, 2);
            if ((lane & 3) == 0) {
                const int r = row0 + mi * 16;
                Cf[(size_t)r * 8 + bn * 2 + wn]       = s0;
                Cf[(size_t)(r + 8) * 8 + bn * 2 + wn] = s1;
            }
        }
    }
}

// ---------------------------------------------------------------------------
// fp32 -> fp16 convert (elementwise, for x)
// ---------------------------------------------------------------------------
__global__ __launch_bounds__(256)
void cvt_kernel(const float* __restrict__ in, __half* __restrict__ out, size_t n4)
{
    size_t i = (size_t)blockIdx.x * 256 + threadIdx.x;
    if (i >= n4) return;
    float4 v = ((const float4*)in)[i];
    __half2 h0 = __floats2half2_rn(v.x, v.y);
    __half2 h1 = __floats2half2_rn(v.z, v.w);
    uint2 o;
    o.x = *(uint32_t*)&h0;
    o.y = *(uint32_t*)&h1;
    ((uint2*)out)[i] = o;
}

// ---------------------------------------------------------------------------
// Fused weight prep: straight converts (wq,wk,wv) + transposed converts
// (wo -> WO_OFF, wf1 -> WF1_OFF, wf2 -> WF2_OFF, ws1 -> WS1_OFF).
// Threads [0, 196608): float4 converts. Then scalar transposes.
// ---------------------------------------------------------------------------
__global__ __launch_bounds__(256)
void wprep_kernel(const float* __restrict__ wq, const float* __restrict__ wk,
                  const float* __restrict__ wv, const float* __restrict__ wo,
                  const float* __restrict__ wf1, const float* __restrict__ wf2,
                  const float* __restrict__ ws1,
                  __half* __restrict__ wq16, __half* __restrict__ wk16,
                  __half* __restrict__ wv16, __half* __restrict__ wt)
{
    int idx = blockIdx.x * 256 + threadIdx.x;
    if (idx < 196608) {
        int sec = idx >> 16;            // 0,1,2  (65536 float4 each)
        int i4  = idx & 65535;
        const float* src = sec == 0 ? wq : (sec == 1 ? wk : wv);
        __half* dst      = sec == 0 ? wq16 : (sec == 1 ? wk16 : wv16);
        float4 v = ((const float4*)src)[i4];
        __half2 h0 = __floats2half2_rn(v.x, v.y);
        __half2 h1 = __floats2half2_rn(v.z, v.w);
        uint2 o;
        o.x = *(uint32_t*)&h0;
        o.y = *(uint32_t*)&h1;
        ((uint2*)dst)[i4] = o;
        return;
    }
    int t = idx - 196608;
    if (t < 262144) {                    // wo: K=512, N=512
        int n = t >> 9, k = t & 511;
        wt[WO_OFF + t] = __float2half_rn(wo[(size_t)k * 512 + n]);
        return;
    }
    t -= 262144;
    if (t < 524288) {                    // wf1: K=512, N=1024
        int n = t >> 9, k = t & 511;
        wt[WF1_OFF + t] = __float2half_rn(wf1[(size_t)k * 1024 + n]);
        return;
    }
    t -= 524288;
    if (t < 524288) {                    // wf2: K=1024, N=512
        int n = t >> 10, k = t & 1023;
        wt[WF2_OFF + t] = __float2half_rn(wf2[(size_t)k * 512 + n]);
        return;
    }
    t -= 524288;
    if (t < 262144) {                    // ws1: K=512, N=512
        int n = t >> 9, k = t & 511;
        wt[WS1_OFF + t] = __float2half_rn(ws1[(size_t)k * 512 + n]);
    }
}
#define WPREP_THREADS (196608 + 262144 + 524288 + 524288 + 262144)  // 1769472
#define WPREP_BLOCKS  (WPREP_THREADS / 256)                          // 6912

// ---------------------------------------------------------------------------
// prep: attention bias terms + uv GEMM bias (zeros | bvo)
// ---------------------------------------------------------------------------
__global__ __launch_bounds__(128)
void prep_kernel(const float* __restrict__ wq, const float* __restrict__ wk,
                 const float* __restrict__ bq, const float* __restrict__ bk,
                 const float* __restrict__ bv, const float* __restrict__ wo,
                 const float* __restrict__ bo,
                 float* __restrict__ w_a, float* __restrict__ w_b,
                 float* __restrict__ gamma, float* __restrict__ buv)
{
    int i = blockIdx.x * 128 + threadIdx.x;
    float sa = 0.f, sb = 0.f, so = 0.f;
    for (int o = 0; o < 512; o++) {
        sa += wq[(size_t)i * 512 + o] * bk[o];
        sb += wk[(size_t)i * 512 + o] * bq[o];
        so += bv[o] * wo[(size_t)o * 512 + i];
    }
    w_a[i] = sa;
    w_b[i] = sb;
    buv[i] = 0.f;
    buv[512 + i] = so + bo[i];
    if (blockIdx.x == 0) {
        float gsum = 0.f;
        for (int o = threadIdx.x; o < 512; o += 128) gsum += bq[o] * bk[o];
        gsum = warp_sum(gsum);
        __shared__ float sm[4];
        if ((threadIdx.x & 31) == 0) sm[threadIdx.x >> 5] = gsum;
        __syncthreads();
        if (threadIdx.x == 0) gamma[0] = sm[0] + sm[1] + sm[2] + sm[3];
    }
}

// ---------------------------------------------------------------------------
// Fused attention + residual + LN1 (one warp per sample).
// Writes ONLY hh fp16 (h is consumed downstream in fp16 everywhere).
// ---------------------------------------------------------------------------
__global__ __launch_bounds__(256)
void attn_ln_kernel(const __half* __restrict__ uv, const float* __restrict__ x,
                    const float* __restrict__ w_a, const float* __restrict__ w_b,
                    const float* __restrict__ gamma_p,
                    const float* __restrict__ g1, const float* __restrict__ be1,
                    __half* __restrict__ hh)
{
    int gw   = (blockIdx.x * 256 + threadIdx.x) >> 5;
    int lane = threadIdx.x & 31;
    if (gw >= B_) return;

    const __half* ub = uv + (size_t)gw * 2048;
    const uint4* u0 = (const uint4*)(ub);
    const uint4* u1 = (const uint4*)(ub + 1024);
    const uint4* v0 = (const uint4*)(ub + 512);
    const uint4* v1 = (const uint4*)(ub + 1536);
    const float4* xb = (const float4*)(x + (size_t)gw * 1024);
    const float4* wa4 = (const float4*)w_a;
    const float4* wb4 = (const float4*)w_b;

    float4 xr0[2][2], xr1[2][2];
#pragma unroll
    for (int r = 0; r < 2; r++) {
        int i = lane + 32 * r;
        xr0[r][0] = xb[2 * i];
        xr0[r][1] = xb[2 * i + 1];
        xr1[r][0] = xb[128 + 2 * i];
        xr1[r][1] = xb[128 + 2 * i + 1];
    }

    float s00 = 0.f, s01 = 0.f, s10 = 0.f, s11 = 0.f;
    float a0s = 0.f, a1s = 0.f, b0s = 0.f, b1s = 0.f;
#pragma unroll
    for (int r = 0; r < 2; r++) {
        int i = lane + 32 * r;
        uint4 uu0 = u0[i], uu1 = u1[i];
        s00 += dot8f(uu0, xr0[r][0], xr0[r][1]);
        s01 += dot8f(uu0, xr1[r][0], xr1[r][1]);
        s10 += dot8f(uu1, xr0[r][0], xr0[r][1]);
        s11 += dot8f(uu1, xr1[r][0], xr1[r][1]);
        float4 wa0 = wa4[2 * i], wa1 = wa4[2 * i + 1];
        float4 wb0 = wb4[2 * i], wb1 = wb4[2 * i + 1];
        a0s += dot8ff(xr0[r][0], xr0[r][1], wa0, wa1);
        a1s += dot8ff(xr1[r][0], xr1[r][1], wa0, wa1);
        b0s += dot8ff(xr0[r][0], xr0[r][1], wb0, wb1);
        b1s += dot8ff(xr1[r][0], xr1[r][1], wb0, wb1);
    }
    s00 = warp_sum(s00); s01 = warp_sum(s01);
    s10 = warp_sum(s10); s11 = warp_sum(s11);
    a0s = warp_sum(a0s); a1s = warp_sum(a1s);
    b0s = warp_sum(b0s); b1s = warp_sum(b1s);

    const float gmm = gamma_p[0];
    s00 += a0s + b0s + gmm;
    s01 += a0s + b1s + gmm;
    s10 += a1s + b0s + gmm;
    s11 += a1s + b1s + gmm;

    const float inv_scale = 1.0f / 22.627416997969522f;
    s00 *= inv_scale; s01 *= inv_scale; s10 *= inv_scale; s11 *= inv_scale;
    s00 = s00 > 0.f ? s00 : 0.2f * s00;
    s01 = s01 > 0.f ? s01 : 0.2f * s01;
    s10 = s10 > 0.f ? s10 : 0.2f * s10;
    s11 = s11 > 0.f ? s11 : 0.2f * s11;

    float m0 = fmaxf(s00, s01), m1 = fmaxf(s10, s11);
    float e00 = expf(s00 - m0), e01 = expf(s01 - m0);
    float e10 = expf(s10 - m1), e11 = expf(s11 - m1);
    float i0 = 1.0f / (e00 + e01), i1 = 1.0f / (e10 + e11);
    float a00 = e00 * i0, a01 = e01 * i0;
    float a10 = e10 * i1, a11 = e11 * i1;

    float sr0[16], sr1[16];
    float sum0 = 0.f, sq0 = 0.f, sum1 = 0.f, sq1 = 0.f;
#pragma unroll
    for (int r = 0; r < 2; r++) {
        int i = lane + 32 * r;
        uint4 xv0 = v0[i], xv1 = v1[i];
        const __half2* p0 = (const __half2*)&xv0;
        const __half2* p1 = (const __half2*)&xv1;
        const float* x0f = (const float*)&xr0[r][0];
        const float* x1f = (const float*)&xr1[r][0];
#pragma unroll
        for (int j = 0; j < 4; j++) {
            float2 f0 = __half22float2(p0[j]);
            float2 f1 = __half22float2(p1[j]);
            float v0a = x0f[2*j]   + a00 * f0.x + a01 * f1.x;
            float v0b = x0f[2*j+1] + a00 * f0.y + a01 * f1.y;
            float v1a = x1f[2*j]   + a10 * f0.x + a11 * f1.x;
            float v1b = x1f[2*j+1] + a10 * f0.y + a11 * f1.y;
            sr0[r*8 + 2*j]   = v0a;  sr0[r*8 + 2*j+1] = v0b;
            sr1[r*8 + 2*j]   = v1a;  sr1[r*8 + 2*j+1] = v1b;
            sum0 += v0a + v0b;  sq0 += v0a * v0a + v0b * v0b;
            sum1 += v1a + v1b;  sq1 += v1a * v1a + v1b * v1b;
        }
    }
    sum0 = warp_sum(sum0); sq0 = warp_sum(sq0);
    sum1 = warp_sum(sum1); sq1 = warp_sum(sq1);
    float mu0 = sum0 * (1.0f / D_);
    float mu1 = sum1 * (1.0f / D_);
    float rs0 = rsqrtf(sq0 * (1.0f / D_) - mu0 * mu0 + 1e-5f);
    float rs1 = rsqrtf(sq1 * (1.0f / D_) - mu1 * mu1 + 1e-5f);

    const float4* g4 = (const float4*)g1;
    const float4* b4 = (const float4*)be1;
    __half* hh0 = hh + (size_t)gw * 1024;

#pragma unroll
    for (int r = 0; r < 2; r++) {
        int i = lane + 32 * r;
        uint4 o0u, o1u;
        __half2* q0o = (__half2*)&o0u;
        __half2* q1o = (__half2*)&o1u;
#pragma unroll
        for (int q = 0; q < 2; q++) {
            float4 G = g4[2 * i + q], Bv = b4[2 * i + q];
            float o0x = (sr0[r*8 + 4*q]     - mu0) * rs0 * G.x + Bv.x;
            float o0y = (sr0[r*8 + 4*q + 1] - mu0) * rs0 * G.y + Bv.y;
            float o0z = (sr0[r*8 + 4*q + 2] - mu0) * rs0 * G.z + Bv.z;
            float o0w = (sr0[r*8 + 4*q + 3] - mu0) * rs0 * G.w + Bv.w;
            float o1x = (sr1[r*8 + 4*q]     - mu1) * rs1 * G.x + Bv.x;
            float o1y = (sr1[r*8 + 4*q + 1] - mu1) * rs1 * G.y + Bv.y;
            float o1z = (sr1[r*8 + 4*q + 2] - mu1) * rs1 * G.z + Bv.z;
            float o1w = (sr1[r*8 + 4*q + 3] - mu1) * rs1 * G.w + Bv.w;
            q0o[2*q]   = __floats2half2_rn(o0x, o0y);
            q0o[2*q+1] = __floats2half2_rn(o0z, o0w);
            q1o[2*q]   = __floats2half2_rn(o1x, o1y);
            q1o[2*q+1] = __floats2half2_rn(o1z, o1w);
        }
        ((uint4*)(hh0))[i]       = o0u;
        ((uint4*)(hh0 + 512))[i] = o1u;
    }
}

// ---------------------------------------------------------------------------
// out = LayerNorm(A + P) * g + be ; A fp16, P fp16; fp32 out + fp16 copy
// ---------------------------------------------------------------------------
__global__ __launch_bounds__(128)
void add_ln_kernel(const __half* __restrict__ A, const __half* __restrict__ P,
                   const float* __restrict__ g, const float* __restrict__ be,
                   float* __restrict__ out, __half* __restrict__ oh)
{
    size_t row = blockIdx.x;
    int t = threadIdx.x;

    uint2 au = ((const uint2*)(A + row * D_))[t];
    uint2 pu = ((const uint2*)(P + row * D_))[t];
    float2 a0 = __half22float2(*(__half2*)&au.x);
    float2 a1 = __half22float2(*(__half2*)&au.y);
    float2 p0 = __half22float2(*(__half2*)&pu.x);
    float2 p1 = __half22float2(*(__half2*)&pu.y);
    float4 s;
    s.x = a0.x + p0.x; s.y = a0.y + p0.y; s.z = a1.x + p1.x; s.w = a1.y + p1.y;

    float sum = s.x + s.y + s.z + s.w;
    float sq  = s.x * s.x + s.y * s.y + s.z * s.z + s.w * s.w;
    sum = warp_sum(sum);
    sq  = warp_sum(sq);

    __shared__ float sm[8];
    int w = t >> 5;
    if ((t & 31) == 0) { sm[w] = sum; sm[4 + w] = sq; }
    __syncthreads();
    float ts = sm[0] + sm[1] + sm[2] + sm[3];
    float tq = sm[4] + sm[5] + sm[6] + sm[7];

    float mu  = ts * (1.0f / D_);
    float var = tq * (1.0f / D_) - mu * mu;
    float rs  = rsqrtf(var + 1e-5f);

    float4 G  = ((const float4*)g)[t];
    float4 Be = ((const float4*)be)[t];
    float4 o;
    o.x = (s.x - mu) * rs * G.x + Be.x;
    o.y = (s.y - mu) * rs * G.y + Be.y;
    o.z = (s.z - mu) * rs * G.z + Be.z;
    o.w = (s.w - mu) * rs * G.w + Be.w;
    ((float4*)(out + row * D_))[t] = o;

    __half2 h0 = __floats2half2_rn(o.x, o.y);
    __half2 h1 = __floats2half2_rn(o.z, o.w);
    uint2 u;
    u.x = *(uint32_t*)&h0;
    u.y = *(uint32_t*)&h1;
    ((uint2*)(oh + row * D_))[t] = u;
}

// ---------------------------------------------------------------------------
// Final stage: sum score partials, softmax over N=2, pooling, param-free LN
// ---------------------------------------------------------------------------
__global__ __launch_bounds__(256)
void final_kernel(const float* __restrict__ sp, const float* __restrict__ refined,
                  float* __restrict__ fused, float* __restrict__ alpha)
{
    int gw   = (blockIdx.x * 256 + threadIdx.x) >> 5;
    int lane = threadIdx.x & 31;
    if (gw >= B_) return;

    float v = (lane < 16) ? sp[(size_t)gw * 16 + lane] : 0.f;
    v += __shfl_xor_sync(0xffffffffu, v, 1);
    v += __shfl_xor_sync(0xffffffffu, v, 2);
    v += __shfl_xor_sync(0xffffffffu, v, 4);
    float d0 = __shfl_sync(0xffffffffu, v, 0);
    float d1 = __shfl_sync(0xffffffffu, v, 8);

    float m  = fmaxf(d0, d1);
    float e0 = expf(d0 - m), e1 = expf(d1 - m);
    float inv = 1.0f / (e0 + e1);
    float a0 = e0 * inv, a1 = e1 * inv;
    if (lane == 0) {
        alpha[(size_t)gw * 2 + 0] = a0;
        alpha[(size_t)gw * 2 + 1] = a1;
    }

    const float4* f0 = (const float4*)(refined + (size_t)gw * 2 * D_);
    const float4* f1 = f0 + D_ / 4;

    float4 fr[4];
    float sum = 0.f, sq = 0.f;
#pragma unroll
    for (int r = 0; r < 4; r++) {
        int i = lane + 32 * r;
        float4 x0 = f0[i], x1 = f1[i];
        float4 t;
        t.x = a0 * x0.x + a1 * x1.x;  t.y = a0 * x0.y + a1 * x1.y;
        t.z = a0 * x0.z + a1 * x1.z;  t.w = a0 * x0.w + a1 * x1.w;
        fr[r] = t;
        sum += t.x + t.y + t.z + t.w;
        sq  += t.x * t.x + t.y * t.y + t.z * t.z + t.w * t.w;
    }
    sum = warp_sum(sum);
    sq  = warp_sum(sq);
    float mu  = sum * (1.0f / D_);
    float var = sq * (1.0f / D_) - mu * mu;
    float rs  = rsqrtf(var + 1e-5f);

    float4* fo = (float4*)(fused + (size_t)gw * D_);
#pragma unroll
    for (int r = 0; r < 4; r++) {
        int i = lane + 32 * r;
        float4 t = fr[r];
        float4 o;
        o.x = (t.x - mu) * rs;  o.y = (t.y - mu) * rs;
        o.z = (t.z - mu) * rs;  o.w = (t.w - mu) * rs;
        fo[i] = o;
    }
}

// ---------------------------------------------------------------------------
// Launch
// ---------------------------------------------------------------------------
extern "C" void kernel_launch(void* const* d_in, const int* in_sizes, int n_in,
                              void* d_out, int out_size)
{
    const float* x   = (const float*)d_in[0];
    const float* wq  = (const float*)d_in[1];
    const float* bq  = (const float*)d_in[2];
    const float* wk  = (const float*)d_in[3];
    const float* bk  = (const float*)d_in[4];
    const float* wv  = (const float*)d_in[5];
    const float* bv  = (const float*)d_in[6];
    const float* wo  = (const float*)d_in[7];
    const float* bo  = (const float*)d_in[8];
    const float* g1  = (const float*)d_in[9];
    const float* be1 = (const float*)d_in[10];
    const float* wf1 = (const float*)d_in[11];
    const float* bf1 = (const float*)d_in[12];
    const float* wf2 = (const float*)d_in[13];
    const float* bf2 = (const float*)d_in[14];
    const float* g2  = (const float*)d_in[15];
    const float* be2 = (const float*)d_in[16];
    const float* ws1 = (const float*)d_in[17];
    const float* bs1 = (const float*)d_in[18];
    const float* ws2 = (const float*)d_in[19];

    float *sp, *buv, *wa, *wb, *gma;
    __half *uv, *xh, *hh, *rh, *ph, *fh, *wt, *wq16, *wk16, *wv16;
    cudaGetSymbolAddress((void**)&uv, g_uv);
    cudaGetSymbolAddress((void**)&sp, g_sp);
    cudaGetSymbolAddress((void**)&buv, g_buv);
    cudaGetSymbolAddress((void**)&wa, g_wa);
    cudaGetSymbolAddress((void**)&wb, g_wb);
    cudaGetSymbolAddress((void**)&gma, g_gamma);
    cudaGetSymbolAddress((void**)&xh, g_xh);
    cudaGetSymbolAddress((void**)&hh, g_hh);
    cudaGetSymbolAddress((void**)&rh, g_rh);
    cudaGetSymbolAddress((void**)&ph, g_ph);
    cudaGetSymbolAddress((void**)&fh, g_fh);
    cudaGetSymbolAddress((void**)&wt, g_wt);
    cudaGetSymbolAddress((void**)&wq16, g_wq16);
    cudaGetSymbolAddress((void**)&wk16, g_wk16);
    cudaGetSymbolAddress((void**)&wv16, g_wv16);

    cudaFuncSetAttribute(gemm_mma, cudaFuncAttributeMaxDynamicSharedMemorySize,
                         GEMM_SMEM);

    float* out     = (float*)d_out;
    float* fused   = out;
    float* alpha   = out + (size_t)B_ * D_;
    float* refined = alpha + (size_t)B_ * N_;

    dim3 blk(256);

    // preprocessing
    cvt_kernel<<<(unsigned)(TD_ / 4 / 256), 256>>>(x, xh, TD_ / 4);
    wprep_kernel<<<WPREP_BLOCKS, 256>>>(wq, wk, wv, wo, wf1, wf2, ws1,
                                        wq16, wk16, wv16, wt);
    prep_kernel<<<4, 128>>>(wq, wk, bq, bk, bv, wo, bo, wa, wb, gma, buv);

    // Mt[j,i] = wk[j,:].wq[i,:]
    gemm_mma<<<dim3(4, 4), blk, GEMM_SMEM>>>(wk16, wq16, buv, nullptr,
                                             wt + WK_OFF, 512, 512, 3, nullptr);
    // Wvo_t[n,k] = wo_t[n,:].wv[k,:]
    gemm_mma<<<dim3(4, 4), blk, GEMM_SMEM>>>(wt + WO_OFF, wv16, buv, nullptr,
                                             wt + WVO_OFF, 512, 512, 3, nullptr);

    // uv = xh @ [Mt | Wvo_t]^T + (0|bvo)  -> fp16 [T, 1024]
    gemm_mma<<<dim3(8, T_ / 128), blk, GEMM_SMEM>>>(xh, wt + WK_OFF, buv,
                                                    nullptr, uv, 1024, 512, 3, nullptr);
    // fused attention + residual + LN1 -> hh fp16
    attn_ln_kernel<<<B_ / 8, 256>>>(uv, x, wa, wb, gma, g1, be1, hh);
    // FFN
    gemm_mma<<<dim3(8, T_ / 128), blk, GEMM_SMEM>>>(hh, wt + WF1_OFF, bf1,
                                                    nullptr, fh, 1024, 512, 2, nullptr);
    gemm_mma<<<dim3(4, T_ / 128), blk, GEMM_SMEM>>>(fh, wt + WF2_OFF, bf2,
                                                    nullptr, ph, 512, 1024, 3, nullptr);
    add_ln_kernel<<<T_, 128>>>(hh, ph, g2, be2, refined, rh);
    // score MLP fused: partials = relu(refined@ws1 + bs1) . ws2
    gemm_mma<<<dim3(4, T_ / 128), blk, GEMM_SMEM>>>(rh, wt + WS1_OFF, bs1,
                                                    sp, nullptr, 512, 512, 4, ws2);
    // softmax + pooling + final LN
    final_kernel<<<B_ / 8, 256>>>(sp, refined, fused, alpha);
}